// round 6
// baseline (speedup 1.0000x reference)
#include <cuda_runtime.h>
#include <cuda_bf16.h>
#include <math.h>

#define B_   2
#define N_   4096
#define C_   256
#define NC_  150
#define T_   4
#define HID_ 1024
#define R_   16384   /* T_*N_ */

typedef long long ll;

/* ---------------- scratch (device globals) ------------------------------- */
__device__ float g_xf  [B_*T_*N_*C_];
__device__ float g_clt [B_*NC_*R_];      /* (B,nc,R) k-major */
__device__ float g_s1  [B_*R_];
__device__ float g_s2  [B_*R_];
__device__ float g_soft[B_*T_*NC_*N_];
__device__ float g_cen [B_*T_*NC_*C_];
__device__ float g_cin [B_*NC_*C_];
__device__ float g_k   [B_*NC_*C_];
__device__ float g_v   [B_*NC_*C_];
__device__ float g_q   [B_*N_*C_];
__device__ float g_attn[B_*N_*C_];
__device__ float g_tmp [B_*N_*C_];
__device__ float g_out1[B_*N_*C_];
__device__ float g_h1  [B_*N_*HID_];
__device__ float g_hg  [B_*N_*HID_];

__device__ __forceinline__ float blockSum256(float v, float* sh) {
    #pragma unroll
    for (int o = 16; o; o >>= 1) v += __shfl_xor_sync(0xffffffffu, v, o);
    if ((threadIdx.x & 31) == 0) sh[threadIdx.x >> 5] = v;
    __syncthreads();
    float r = sh[0]+sh[1]+sh[2]+sh[3]+sh[4]+sh[5]+sh[6]+sh[7];
    __syncthreads();
    return r;
}

__global__ void zero_kernel(float* p, int n) {
    int i = blockIdx.x * 256 + threadIdx.x;
    if (i < n) p[i] = 0.f;
}

/* ---------------- xf = concat(mem, x), float4 ----------------------------- */
__global__ void copy_xf_kernel(const float4* __restrict__ x,
                               const float4* __restrict__ mem,
                               float4* __restrict__ xf) {
    ll i = (ll)blockIdx.x * 256 + threadIdx.x;
    int b  = (int)(i >> 20);
    int rem = (int)(i & 1048575);
    int tt = rem >> 18;
    int rc = rem & 262143;
    float4 v;
    if (tt < 3) v = mem[((ll)(b*3 + tt) << 18) + rc];
    else        v = x[((ll)b << 18) + rc];
    xf[i] = v;
}

/* ---------------- split-bf16 tensor-core GEMM -----------------------------
 * C = alpha*(A·W^T + bias). A:(M,K) fp32 row-major, W:(N,K) fp32 row-major.
 * Double-bf16 decomposition: acc += Ah·Wh + Ah·Wl + Al·Wh  (fp32 accum).
 * BM=128, BN=64, 256 threads = 8 warps (4 m-warps x 2 n-warps), 32x32 warp
 * tiles, mma.sync.m16n8k16. Requires K%16==0, lda%4==0, ldw%4==0.         */
__global__ void gemm_mma(int M, int N, int K,
                         const float* __restrict__ A, int lda, ll bsA,
                         const float* __restrict__ W, int ldw,
                         float* __restrict__ Cp, ll crs, ll ccs, ll bsC,
                         const float* __restrict__ bias, float alpha) {
    constexpr int BM = 128, BN = 64, PAD = 24;
    __shared__ __nv_bfloat16 Ah[BM][PAD], Al[BM][PAD];
    __shared__ __nv_bfloat16 Bh[BN][PAD], Bl[BN][PAD];
    int bt = blockIdx.z;
    A  += (ll)bt * bsA;
    Cp += (ll)bt * bsC;
    int m0 = blockIdx.x * BM, n0 = blockIdx.y * BN;
    int tid = threadIdx.x;
    int wid = tid >> 5, lane = tid & 31;
    int wm = wid >> 1, wn = wid & 1;
    int lq = lane >> 2, lr = lane & 3;       /* groupID, threadID-in-group */

    float acc[2][4][4];
    #pragma unroll
    for (int im = 0; im < 2; im++)
        #pragma unroll
        for (int jn = 0; jn < 4; jn++)
            #pragma unroll
            for (int c = 0; c < 4; c++) acc[im][jn][c] = 0.f;

    for (int k0 = 0; k0 < K; k0 += 16) {
        /* A tile: BM rows x 16 k; 512 float4 slots, 2 per thread */
        #pragma unroll
        for (int s = tid; s < BM * 4; s += 256) {
            int row = s >> 2, q = s & 3;
            int m = m0 + row;
            float4 v = make_float4(0.f, 0.f, 0.f, 0.f);
            if (m < M) v = *(const float4*)&A[(ll)m * lda + k0 + q * 4];
            float vv[4] = {v.x, v.y, v.z, v.w};
            #pragma unroll
            for (int u = 0; u < 4; u++) {
                __nv_bfloat16 h = __float2bfloat16(vv[u]);
                Ah[row][q * 4 + u] = h;
                Al[row][q * 4 + u] = __float2bfloat16(vv[u] - __bfloat162float(h));
            }
        }
        /* W tile: BN rows x 16 k; 256 slots, 1 per thread */
        {
            int s = tid;
            int row = s >> 2, q = s & 3;
            int n = n0 + row;
            float4 v = make_float4(0.f, 0.f, 0.f, 0.f);
            if (n < N) v = *(const float4*)&W[(ll)n * ldw + k0 + q * 4];
            float vv[4] = {v.x, v.y, v.z, v.w};
            #pragma unroll
            for (int u = 0; u < 4; u++) {
                __nv_bfloat16 h = __float2bfloat16(vv[u]);
                Bh[row][q * 4 + u] = h;
                Bl[row][q * 4 + u] = __float2bfloat16(vv[u] - __bfloat162float(h));
            }
        }
        __syncthreads();

        unsigned ah[2][4], al[2][4], bh[4][2], bl[4][2];
        #pragma unroll
        for (int im = 0; im < 2; im++) {
            int r = wm * 32 + im * 16 + lq;
            int c = lr * 2;
            ah[im][0] = *(const unsigned*)&Ah[r    ][c    ];
            ah[im][1] = *(const unsigned*)&Ah[r + 8][c    ];
            ah[im][2] = *(const unsigned*)&Ah[r    ][c + 8];
            ah[im][3] = *(const unsigned*)&Ah[r + 8][c + 8];
            al[im][0] = *(const unsigned*)&Al[r    ][c    ];
            al[im][1] = *(const unsigned*)&Al[r + 8][c    ];
            al[im][2] = *(const unsigned*)&Al[r    ][c + 8];
            al[im][3] = *(const unsigned*)&Al[r + 8][c + 8];
        }
        #pragma unroll
        for (int jn = 0; jn < 4; jn++) {
            int n = wn * 32 + jn * 8 + lq;
            int c = lr * 2;
            bh[jn][0] = *(const unsigned*)&Bh[n][c    ];
            bh[jn][1] = *(const unsigned*)&Bh[n][c + 8];
            bl[jn][0] = *(const unsigned*)&Bl[n][c    ];
            bl[jn][1] = *(const unsigned*)&Bl[n][c + 8];
        }
        #pragma unroll
        for (int im = 0; im < 2; im++)
            #pragma unroll
            for (int jn = 0; jn < 4; jn++) {
                float* cc = acc[im][jn];
                asm volatile(
                    "mma.sync.aligned.m16n8k16.row.col.f32.bf16.bf16.f32 "
                    "{%0,%1,%2,%3}, {%4,%5,%6,%7}, {%8,%9}, {%0,%1,%2,%3};"
                    : "+f"(cc[0]), "+f"(cc[1]), "+f"(cc[2]), "+f"(cc[3])
                    : "r"(ah[im][0]), "r"(ah[im][1]), "r"(ah[im][2]), "r"(ah[im][3]),
                      "r"(bh[jn][0]), "r"(bh[jn][1]));
                asm volatile(
                    "mma.sync.aligned.m16n8k16.row.col.f32.bf16.bf16.f32 "
                    "{%0,%1,%2,%3}, {%4,%5,%6,%7}, {%8,%9}, {%0,%1,%2,%3};"
                    : "+f"(cc[0]), "+f"(cc[1]), "+f"(cc[2]), "+f"(cc[3])
                    : "r"(ah[im][0]), "r"(ah[im][1]), "r"(ah[im][2]), "r"(ah[im][3]),
                      "r"(bl[jn][0]), "r"(bl[jn][1]));
                asm volatile(
                    "mma.sync.aligned.m16n8k16.row.col.f32.bf16.bf16.f32 "
                    "{%0,%1,%2,%3}, {%4,%5,%6,%7}, {%8,%9}, {%0,%1,%2,%3};"
                    : "+f"(cc[0]), "+f"(cc[1]), "+f"(cc[2]), "+f"(cc[3])
                    : "r"(al[im][0]), "r"(al[im][1]), "r"(al[im][2]), "r"(al[im][3]),
                      "r"(bh[jn][0]), "r"(bh[jn][1]));
            }
        __syncthreads();
    }

    /* epilogue */
    #pragma unroll
    for (int im = 0; im < 2; im++) {
        int mb = m0 + wm * 32 + im * 16 + lq;
        #pragma unroll
        for (int jn = 0; jn < 4; jn++) {
            int nb = n0 + wn * 32 + jn * 8 + lr * 2;
            float b0 = 0.f, b1 = 0.f;
            if (bias) {
                if (nb     < N) b0 = bias[nb];
                if (nb + 1 < N) b1 = bias[nb + 1];
            }
            float* cc = acc[im][jn];
            if (mb < M) {
                if (nb     < N) Cp[(ll)mb * crs + (ll)(nb    ) * ccs] = (cc[0] + b0) * alpha;
                if (nb + 1 < N) Cp[(ll)mb * crs + (ll)(nb + 1) * ccs] = (cc[1] + b1) * alpha;
            }
            if (mb + 8 < M) {
                if (nb     < N) Cp[(ll)(mb + 8) * crs + (ll)(nb    ) * ccs] = (cc[2] + b0) * alpha;
                if (nb + 1 < N) Cp[(ll)(mb + 8) * crs + (ll)(nb + 1) * ccs] = (cc[3] + b1) * alpha;
            }
        }
    }
}

/* ---------------- scalar SGEMM (TRW=1 path, used for cen) ----------------- */
template<int BM, int BN, int TM, int TN>
__global__ void gemm_t(int M, int N, int K,
                       const float* __restrict__ A, int lda, ll bsA,
                       const float* __restrict__ W, int ldw, ll bsW,
                       float* __restrict__ Cp, ll crs, ll ccs, ll bsC,
                       float alpha, int ksplit) {
    constexpr int BK = 8;
    constexpr int TX = BN / TN, TY = BM / TM, NT = TX * TY;
    __shared__ __align__(16) float As[BK][BM + 4];
    __shared__ __align__(16) float Ws[BK][BN + 4];
    int zz = blockIdx.z, bt = zz / ksplit, ks = zz - bt * ksplit;
    A  += (ll)bt * bsA;  W += (ll)bt * bsW;  Cp += (ll)bt * bsC;
    int Kc = K / ksplit;
    int kbeg = ks * Kc, kend = kbeg + Kc;
    int m0 = blockIdx.x * BM, n0 = blockIdx.y * BN;
    int tid = threadIdx.x, tx = tid % TX, ty = tid / TX;
    float acc[TM][TN];
    #pragma unroll
    for (int i = 0; i < TM; i++)
        #pragma unroll
        for (int j = 0; j < TN; j++) acc[i][j] = 0.f;

    for (int k0 = kbeg; k0 < kend; k0 += BK) {
        for (int i4 = tid; i4 < BM * (BK/4); i4 += NT) {
            int q = i4 % (BK/4), mm = i4 / (BK/4);
            int m = m0 + mm, k = k0 + q*4;
            float4 v = make_float4(0.f,0.f,0.f,0.f);
            if (m < M) v = *(const float4*)&A[(ll)m * lda + k];
            As[q*4+0][mm] = v.x; As[q*4+1][mm] = v.y;
            As[q*4+2][mm] = v.z; As[q*4+3][mm] = v.w;
        }
        for (int i4 = tid; i4 < (BN/4) * BK; i4 += NT) {
            int q = i4 % (BN/4), kk = i4 / (BN/4);
            int n = n0 + q*4, k = k0 + kk;
            float4 v = make_float4(0.f,0.f,0.f,0.f);
            if (n + 3 < N) v = *(const float4*)&W[(ll)k * ldw + n];
            else {
                v.x = (n   < N) ? W[(ll)k*ldw + n  ] : 0.f;
                v.y = (n+1 < N) ? W[(ll)k*ldw + n+1] : 0.f;
                v.z = (n+2 < N) ? W[(ll)k*ldw + n+2] : 0.f;
                v.w = (n+3 < N) ? W[(ll)k*ldw + n+3] : 0.f;
            }
            *(float4*)&Ws[kk][q*4] = v;
        }
        __syncthreads();
        #pragma unroll
        for (int kk = 0; kk < BK; kk++) {
            float a[TM], w[TN];
            #pragma unroll
            for (int i = 0; i < TM/4; i++)
                *(float4*)&a[i*4] = *(const float4*)&As[kk][ty*TM + i*4];
            #pragma unroll
            for (int j = 0; j < TN/4; j++)
                *(float4*)&w[j*4] = *(const float4*)&Ws[kk][tx*TN + j*4];
            #pragma unroll
            for (int i = 0; i < TM; i++)
                #pragma unroll
                for (int j = 0; j < TN; j++) acc[i][j] += a[i] * w[j];
        }
        __syncthreads();
    }
    #pragma unroll
    for (int i = 0; i < TM; i++) {
        int m = m0 + ty*TM + i;
        if (m >= M) continue;
        #pragma unroll
        for (int j = 0; j < TN; j++) {
            int n = n0 + tx*TN + j;
            if (n >= N) continue;
            float v = acc[i][j] * alpha;
            float* dst = Cp + (ll)m * crs + (ll)n * ccs;
            if (ksplit == 1) *dst = v;
            else atomicAdd(dst, v);
        }
    }
}

/* ---------------- cosine scales per (b,r) --------------------------------- */
__global__ void scales_kernel(const float* __restrict__ z, const float* __restrict__ clt,
                              const float* __restrict__ p1, const float* __restrict__ p2,
                              float* __restrict__ s1o, float* __restrict__ s2o) {
    __shared__ float p1s[NC_], p2s[NC_], pn[2];
    int b = blockIdx.y;
    int r = blockIdx.x * 128 + threadIdx.x;
    int tid = threadIdx.x;
    for (int i = tid; i < NC_; i += 128) { p1s[i] = p1[i]; p2s[i] = p2[i]; }
    if (tid < 2) {
        const float* p = tid ? p2 : p1;
        float s = 0.f;
        for (int k = 0; k < NC_; k++) s += p[k]*p[k];
        pn[tid] = 1.0f / fmaxf(sqrtf(s), 1e-12f);
    }
    __syncthreads();
    const float* zb = z   + (ll)b * NC_ * R_ + r;
    const float* cb = clt + (ll)b * NC_ * R_ + r;
    float zz = 0.f, zp = 0.f, cc = 0.f, cp = 0.f;
    #pragma unroll 2
    for (int j = 0; j < NC_; j++) {
        float zv = zb[(ll)j * R_];
        float cv = cb[(ll)j * R_];
        zz += zv*zv; zp += zv*p1s[j];
        cc += cv*cv; cp += cv*p2s[j];
    }
    float s1 = zp * pn[0] / fmaxf(sqrtf(zz), 1e-12f);
    float s2 = cp * pn[1] / fmaxf(sqrtf(cc), 1e-12f);
    s1o[(ll)b*R_ + r] = fminf(fmaxf(s1, 0.f), 1.f);
    s2o[(ll)b*R_ + r] = fminf(fmaxf(s2, 0.f), 1.f);
}

/* ---------------- cxz = 0.5*(t1^T@(z*s1) + t2^T@(cl*s2)) ------------------
 * round-4 proven: 64x64 tile, TM=TN=4, 256 threads.                        */
__global__ void cxz_gemm(const float* __restrict__ z, const float* __restrict__ clt,
                         const float* __restrict__ t1, const float* __restrict__ t2,
                         const float* __restrict__ s1, const float* __restrict__ s2,
                         float* __restrict__ out) {
    constexpr int BK = 8;
    __shared__ __align__(16) float As[BK][68];
    __shared__ __align__(16) float Ws[BK][68];
    __shared__ float s1s[64], s2s[64];
    int b = blockIdx.z;
    int m0 = blockIdx.x * 64, n0 = blockIdx.y * 64;
    int tid = threadIdx.x, tx = tid % 16, ty = tid / 16;
    const float* zb = z   + (ll)b * NC_ * R_;
    const float* cb = clt + (ll)b * NC_ * R_;
    if (tid < 64) {
        s1s[tid] = s1[(ll)b * R_ + n0 + tid];
        s2s[tid] = s2[(ll)b * R_ + n0 + tid];
    }
    __syncthreads();
    float acc[4][4];
    #pragma unroll
    for (int i = 0; i < 4; i++)
        #pragma unroll
        for (int j = 0; j < 4; j++) acc[i][j] = 0.f;

    for (int k0 = 0; k0 < 2*NC_; k0 += BK) {
        for (int i = tid; i < 64 * BK; i += 256) {
            int mm = i % 64, kk = i / 64;
            int j = k0 + kk, m = m0 + mm;
            float v = 0.f;
            if (m < NC_) {
                if (j < NC_)        v = t1[j*NC_ + m];
                else if (j < 2*NC_) v = t2[(j-NC_)*NC_ + m];
            }
            As[kk][mm] = v;
        }
        for (int i = tid; i < 16 * BK; i += 256) {
            int q = i % 16, kk = i / 16;
            int j = k0 + kk, r = n0 + q*4;
            float4 v = make_float4(0.f,0.f,0.f,0.f);
            if (j < NC_) {
                v = *(const float4*)&zb[(ll)j * R_ + r];
                v.x *= s1s[q*4]; v.y *= s1s[q*4+1]; v.z *= s1s[q*4+2]; v.w *= s1s[q*4+3];
            } else if (j < 2*NC_) {
                v = *(const float4*)&cb[(ll)(j-NC_) * R_ + r];
                v.x *= s2s[q*4]; v.y *= s2s[q*4+1]; v.z *= s2s[q*4+2]; v.w *= s2s[q*4+3];
            }
            *(float4*)&Ws[kk][q*4] = v;
        }
        __syncthreads();
        #pragma unroll
        for (int kk = 0; kk < BK; kk++) {
            float a[4], w[4];
            *(float4*)a = *(const float4*)&As[kk][ty*4];
            *(float4*)w = *(const float4*)&Ws[kk][tx*4];
            #pragma unroll
            for (int i = 0; i < 4; i++)
                #pragma unroll
                for (int j = 0; j < 4; j++) acc[i][j] += a[i] * w[j];
        }
        __syncthreads();
    }
    #pragma unroll
    for (int i = 0; i < 4; i++) {
        int m = m0 + ty*4 + i;
        if (m >= NC_) continue;
        #pragma unroll
        for (int j = 0; j < 4; j++) {
            int r = n0 + tx*4 + j;
            out[((ll)(b*NC_ + m)) * R_ + r] = 0.5f * acc[i][j];
        }
    }
}

/* ---------------- softmax + raw copy -------------------------------------- */
__global__ void softmax_rows2(const float* __restrict__ cxz,
                              float* __restrict__ asn, float* __restrict__ soft) {
    int row = blockIdx.x;
    int b = row / 600; int rem = row - b * 600;
    int t = rem / NC_; int k = rem - t * NC_;
    const float* s = cxz + ((ll)(b * NC_ + k)) * R_ + (ll)t * N_;
    ll drow = ((ll)((b * T_ + t) * NC_ + k)) * N_;
    __shared__ float sh[8];
    int tid = threadIdx.x;
    float mx = -1e30f;
    for (int i = tid; i < N_; i += 256) mx = fmaxf(mx, s[i]);
    #pragma unroll
    for (int o = 16; o; o >>= 1) mx = fmaxf(mx, __shfl_xor_sync(0xffffffffu, mx, o));
    if ((tid & 31) == 0) sh[tid >> 5] = mx;
    __syncthreads();
    mx = fmaxf(fmaxf(fmaxf(sh[0],sh[1]),fmaxf(sh[2],sh[3])),
               fmaxf(fmaxf(sh[4],sh[5]),fmaxf(sh[6],sh[7])));
    __syncthreads();
    float sum = 0.f;
    for (int i = tid; i < N_; i += 256) sum += expf(s[i] - mx);
    sum = blockSum256(sum, sh);
    float inv = 1.0f / sum;
    for (int i = tid; i < N_; i += 256) {
        float v = s[i];
        asn[drow + i]  = v;
        soft[drow + i] = expf(v - mx) * inv;
    }
}

/* ---------------- gate + LayerNorm --------------------------------------- */
__global__ void gate_ln_kernel(const float* __restrict__ cen,
                               const float* __restrict__ nw, const float* __restrict__ nb,
                               const float* __restrict__ salpha, const float* __restrict__ sbeta,
                               float* __restrict__ cin_out) {
    int k = blockIdx.x, b = blockIdx.y, c = threadIdx.x;
    __shared__ float sh[8];
    float pv[4];
    #pragma unroll
    for (int t = 0; t < 4; t++)
        pv[t] = cen[(((ll)b*4 + t) * NC_ + k) * C_ + c];
    float last = pv[3];
    float ll2 = blockSum256(last*last, sh);
    float cin = last;
    float alpha = salpha[0], beta = sbeta[0];
    for (int t = 0; t < 3; t++) {
        float dt = blockSum256(last * pv[t], sh);
        float pp = blockSum256(pv[t] * pv[t], sh);
        float denom = fmaxf(sqrtf(ll2) * sqrtf(pp), 1e-8f);
        float gate = 1.0f / (1.0f + expf(-(beta + alpha * (dt / denom))));
        cin += gate * pv[t];
    }
    float m  = blockSum256(cin, sh) * (1.0f / C_);
    float dv = cin - m;
    float var = blockSum256(dv*dv, sh) * (1.0f / C_);
    cin_out[((ll)b*NC_ + k) * C_ + c] = dv * rsqrtf(var + 1e-5f) * nw[c] + nb[c];
}

/* ---------------- K/V projections ---------------------------------------- */
__global__ void kv_kernel(const float* __restrict__ cin,
                          const float* __restrict__ kw, const float* __restrict__ kb,
                          const float* __restrict__ vw, const float* __restrict__ vb,
                          float* __restrict__ ko, float* __restrict__ vo) {
    int row = blockIdx.x, c = threadIdx.x;
    __shared__ float ci[C_];
    ci[c] = cin[(ll)row * C_ + c];
    __syncthreads();
    float ka = kb[c], va = vb[c];
    const float* kwr = kw + (ll)c * C_;
    const float* vwr = vw + (ll)c * C_;
    #pragma unroll 4
    for (int j = 0; j < C_; j++) {
        float cv = ci[j];
        ka += cv * kwr[j];
        va += cv * vwr[j];
    }
    ko[(ll)row * C_ + c] = ka;
    vo[(ll)row * C_ + c] = va;
}

/* ---------------- fused attention (8 queries/block) ----------------------- */
__global__ void attn_kernel(const float* __restrict__ q, const float* __restrict__ ks,
                            const float* __restrict__ vs, float* __restrict__ o) {
    const int b = blockIdx.y;
    const int n0 = blockIdx.x * 8;
    __shared__ float qs[8][C_];
    __shared__ float P[8][8][152];
    int tid = threadIdx.x;
    for (int i = tid; i < 8*C_; i += 256)
        qs[i >> 8][i & 255] = q[((ll)b*N_ + n0 + (i >> 8)) * C_ + (i & 255)];
    __syncthreads();
    int h = tid >> 5, lane = tid & 31;
    float lg[8][5];
    #pragma unroll
    for (int g = 0; g < 8; g++)
        #pragma unroll
        for (int s = 0; s < 5; s++) lg[g][s] = -1e30f;
    #pragma unroll
    for (int s = 0; s < 5; s++) {
        int idx = lane + s*32;
        if (idx < NC_) {
            const float4* kp = reinterpret_cast<const float4*>(ks + ((ll)b*NC_ + idx)*C_ + h*32);
            float4 kk[8];
            #pragma unroll
            for (int u = 0; u < 8; u++) kk[u] = kp[u];
            #pragma unroll
            for (int g = 0; g < 8; g++) {
                const float* qb = &qs[g][h*32];
                float d = 0.f;
                #pragma unroll
                for (int u = 0; u < 8; u++)
                    d += kk[u].x*qb[u*4] + kk[u].y*qb[u*4+1] + kk[u].z*qb[u*4+2] + kk[u].w*qb[u*4+3];
                lg[g][s] = d;
            }
        }
    }
    float invg[8];
    #pragma unroll
    for (int g = 0; g < 8; g++) {
        float mx = -1e30f;
        #pragma unroll
        for (int s = 0; s < 5; s++) mx = fmaxf(mx, lg[g][s]);
        #pragma unroll
        for (int o2 = 16; o2; o2 >>= 1) mx = fmaxf(mx, __shfl_xor_sync(0xffffffffu, mx, o2));
        float sum = 0.f;
        #pragma unroll
        for (int s = 0; s < 5; s++) {
            int idx = lane + s*32;
            if (idx < NC_) {
                float e = expf(lg[g][s] - mx);
                P[h][g][idx] = e;
                sum += e;
            }
        }
        #pragma unroll
        for (int o2 = 16; o2; o2 >>= 1) sum += __shfl_xor_sync(0xffffffffu, sum, o2);
        invg[g] = 1.0f / sum;
    }
    __syncwarp();
    float og[8] = {0.f,0.f,0.f,0.f,0.f,0.f,0.f,0.f};
    for (int j = 0; j < NC_; j++) {
        float vv = vs[((ll)b*NC_ + j) * C_ + h*32 + lane];
        #pragma unroll
        for (int g = 0; g < 8; g++) og[g] += P[h][g][j] * vv;
    }
    #pragma unroll
    for (int g = 0; g < 8; g++)
        o[((ll)b*N_ + n0 + g) * C_ + h*32 + lane] = og[g] * invg[g];
}

/* ---------------- smem-tiled depthwise 3x3 conv + GELU -------------------- */
__global__ void conv_gelu2(const float* __restrict__ h,
                           const float* __restrict__ dww, const float* __restrict__ dwb,
                           float* __restrict__ out) {
    __shared__ float patch[10][10][64];
    int ch0 = blockIdx.x * 64;
    int tileid = blockIdx.y;
    int y0 = (tileid >> 3) * 8, x0 = (tileid & 7) * 8;
    int b = blockIdx.z;
    int tid = threadIdx.x;
    for (int i = tid; i < 6400; i += 256) {
        int c = i & 63, sp = i >> 6;
        int py = sp / 10, px = sp % 10;
        int yy = y0 + py - 1, xx = x0 + px - 1;
        float v = 0.f;
        if (yy >= 0 && yy < 64 && xx >= 0 && xx < 64)
            v = h[(((ll)b*N_) + (yy*64 + xx)) * HID_ + ch0 + c];
        patch[py][px][c] = v;
    }
    __syncthreads();
    int c = tid & 63, sub = tid >> 6;
    float w[9];
    #pragma unroll
    for (int i = 0; i < 9; i++) w[i] = dww[(ch0 + c)*9 + i];
    float bv = dwb[ch0 + c];
    for (int oy = sub; oy < 8; oy += 4) {
        #pragma unroll
        for (int ox = 0; ox < 8; ox++) {
            float a = bv;
            #pragma unroll
            for (int dy = 0; dy < 3; dy++)
                #pragma unroll
                for (int dx = 0; dx < 3; dx++)
                    a += patch[oy+dy][ox+dx][c] * w[dy*3+dx];
            float g = 0.5f * a * (1.0f + erff(a * 0.7071067811865475f));
            out[(((ll)b*N_) + ((y0+oy)*64 + x0+ox)) * HID_ + ch0 + c] = g;
        }
    }
}

/* ---------------- residual + LayerNorm ------------------------------------ */
__global__ void add_ln_kernel(const float* __restrict__ res, const float* __restrict__ val,
                              const float* __restrict__ nw, const float* __restrict__ nb,
                              float* __restrict__ dst) {
    ll row = blockIdx.x;
    int c = threadIdx.x;
    __shared__ float sh[8];
    float v = val[row * C_ + c];
    float m = blockSum256(v, sh) * (1.0f / C_);
    float d = v - m;
    float var = blockSum256(d*d, sh) * (1.0f / C_);
    dst[row * C_ + c] = res[row * C_ + c] + d * rsqrtf(var + 1e-5f) * nw[c] + nb[c];
}

/* ---------------- host launch --------------------------------------------- */
static float* symaddr(const void* sym) {
    void* p = nullptr;
    cudaGetSymbolAddress(&p, sym);
    return (float*)p;
}

extern "C" void kernel_launch(void* const* d_in, const int* in_sizes, int n_in,
                              void* d_out, int out_size) {
    const float* x    = (const float*)d_in[0];
    const float* z    = (const float*)d_in[1];
    const float* mem  = (const float*)d_in[2];
    const float* cw   = (const float*)d_in[3];
    const float* p1   = (const float*)d_in[4];
    const float* t1   = (const float*)d_in[5];
    const float* p2   = (const float*)d_in[6];
    const float* t2   = (const float*)d_in[7];
    const float* sal  = (const float*)d_in[8];
    const float* sbe  = (const float*)d_in[9];
    const float* qw   = (const float*)d_in[10];
    const float* qb   = (const float*)d_in[11];
    const float* kw   = (const float*)d_in[12];
    const float* kb   = (const float*)d_in[13];
    const float* vw   = (const float*)d_in[14];
    const float* vb   = (const float*)d_in[15];
    const float* pw   = (const float*)d_in[16];
    const float* pb   = (const float*)d_in[17];
    const float* nw   = (const float*)d_in[18];
    const float* nb   = (const float*)d_in[19];
    const float* f1w  = (const float*)d_in[20];
    const float* f1b  = (const float*)d_in[21];
    const float* dww  = (const float*)d_in[22];
    const float* dwb  = (const float*)d_in[23];
    const float* f2w  = (const float*)d_in[24];
    const float* f2b  = (const float*)d_in[25];

    float* out_main = (float*)d_out;
    float* out_cxz  = out_main + (ll)B_*N_*C_;
    float* out_asn  = out_cxz  + (ll)B_*NC_*R_;

    float* xf   = symaddr(g_xf);
    float* clt  = symaddr(g_clt);
    float* s1   = symaddr(g_s1);
    float* s2   = symaddr(g_s2);
    float* soft = symaddr(g_soft);
    float* cen  = symaddr(g_cen);
    float* cin  = symaddr(g_cin);
    float* ksc  = symaddr(g_k);
    float* vsc  = symaddr(g_v);
    float* qsc  = symaddr(g_q);
    float* atn  = symaddr(g_attn);
    float* tmp  = symaddr(g_tmp);
    float* out1 = symaddr(g_out1);
    float* h1   = symaddr(g_h1);
    float* hg   = symaddr(g_hg);

    /* 1. xf = concat(mem, x) */
    copy_xf_kernel<<<8192, 256>>>((const float4*)x, (const float4*)mem, (float4*)xf);

    /* 2. clt[b,k,r] = xf[b,r,:]·cw[k,:]  (tensor-core, transposed store) */
    gemm_mma<<<dim3(R_/128, 3, B_), 256>>>(
        R_, NC_, C_, xf, C_, (ll)R_*C_, cw, C_,
        clt, 1, R_, (ll)NC_*R_, nullptr, 1.0f);

    /* 3. cosine scales */
    scales_kernel<<<dim3(R_/128, B_), 128>>>(z, clt, p1, p2, s1, s2);

    /* 4. cluster_x_z */
    cxz_gemm<<<dim3(3, R_/64, B_), 256>>>(z, clt, t1, t2, s1, s2, out_cxz);

    /* 5. softmax + assigned copy */
    softmax_rows2<<<B_*T_*NC_, 256>>>(out_cxz, out_asn, soft);

    /* 6. cen = soft @ xf  (split-K=8, atomic, scalar) */
    zero_kernel<<<(B_*T_*NC_*C_ + 255)/256, 256>>>(cen, B_*T_*NC_*C_);
    gemm_t<64,64,4,4><<<dim3(3, 4, B_*T_*8), 256>>>(
        NC_, C_, N_, soft, N_, (ll)NC_*N_, xf, C_, (ll)N_*C_,
        cen, C_, 1, (ll)NC_*C_, 1.0f, 8);

    /* 7. gate + LN */
    gate_ln_kernel<<<dim3(NC_, B_), 256>>>(cen, nw, nb, sal, sbe, cin);

    /* 8. k,v */
    kv_kernel<<<B_*NC_, 256>>>(cin, kw, kb, vw, vb, ksc, vsc);

    /* 9. q (tensor-core) */
    gemm_mma<<<dim3(64, 4, 1), 256>>>(
        B_*N_, C_, C_, x, C_, 0, qw, C_,
        qsc, C_, 1, 0, qb, 0.17677669529663687f);

    /* 10. attention */
    attn_kernel<<<dim3(N_/8, B_), 256>>>(qsc, ksc, vsc, atn);

    /* 11. proj (tensor-core) */
    gemm_mma<<<dim3(64, 4, 1), 256>>>(
        B_*N_, C_, C_, atn, C_, 0, pw, C_,
        tmp, C_, 1, 0, pb, 1.0f);

    /* 12. out1 = x + LN(proj) */
    add_ln_kernel<<<B_*N_, 256>>>(x, tmp, nw, nb, out1);

    /* 13. fc1 (tensor-core) */
    gemm_mma<<<dim3(64, 16, 1), 256>>>(
        B_*N_, HID_, C_, out1, C_, 0, f1w, C_,
        h1, HID_, 1, 0, f1b, 1.0f);

    /* 14. depthwise conv + GELU (smem-tiled) */
    conv_gelu2<<<dim3(HID_/64, 64, B_), 256>>>(h1, dww, dwb, hg);

    /* 15. fc2 (tensor-core) */
    gemm_mma<<<dim3(64, 4, 1), 256>>>(
        B_*N_, C_, HID_, hg, HID_, 0, f2w, HID_,
        tmp, C_, 1, 0, f2b, 1.0f);

    /* 16. out = out1 + LN(fc2) */
    add_ln_kernel<<<B_*N_, 256>>>(out1, tmp, nw, nb, out_main);
}

// round 9
// speedup vs baseline: 1.5498x; 1.5498x over previous
#include <cuda_runtime.h>
#include <cuda_bf16.h>
#include <math.h>

#define B_   2
#define N_   4096
#define C_   256
#define NC_  150
#define T_   4
#define HID_ 1024
#define R_   16384   /* T_*N_ */

typedef long long ll;
typedef __nv_bfloat16 bf16;

/* ---------------- scratch (device globals) ------------------------------- */
__device__ float g_xf  [B_*T_*N_*C_];
__device__ float g_clt [B_*NC_*R_];
__device__ float g_s1  [B_*R_];
__device__ float g_s2  [B_*R_];
__device__ float g_soft[B_*T_*NC_*N_];
__device__ float g_cen [B_*T_*NC_*C_];
__device__ float g_cin [B_*NC_*C_];
__device__ float g_k   [B_*NC_*C_];
__device__ float g_v   [B_*NC_*C_];
__device__ float g_q   [B_*N_*C_];
__device__ float g_tmp [B_*N_*C_];
__device__ float g_out1[B_*N_*C_];
__device__ float g_h1  [B_*N_*HID_];

/* bf16 hi/lo operand buffers — MUST be 16B aligned (float4-read in GEMM) */
__device__ __align__(16) bf16 g_xf_h [B_*T_*N_*C_];
__device__ __align__(16) bf16 g_xf_l [B_*T_*N_*C_];
__device__ __align__(16) bf16 g_x_h  [B_*N_*C_];
__device__ __align__(16) bf16 g_x_l  [B_*N_*C_];
__device__ __align__(16) bf16 g_atn_h[B_*N_*C_];
__device__ __align__(16) bf16 g_atn_l[B_*N_*C_];
__device__ __align__(16) bf16 g_o1_h [B_*N_*C_];
__device__ __align__(16) bf16 g_o1_l [B_*N_*C_];
__device__ __align__(16) bf16 g_hg_h [B_*N_*HID_];
__device__ __align__(16) bf16 g_hg_l [B_*N_*HID_];
__device__ __align__(16) bf16 g_cw_h [NC_*C_];
__device__ __align__(16) bf16 g_cw_l [NC_*C_];
__device__ __align__(16) bf16 g_qw_h [C_*C_];
__device__ __align__(16) bf16 g_qw_l [C_*C_];
__device__ __align__(16) bf16 g_pw_h [C_*C_];
__device__ __align__(16) bf16 g_pw_l [C_*C_];
__device__ __align__(16) bf16 g_f1_h [HID_*C_];
__device__ __align__(16) bf16 g_f1_l [HID_*C_];
__device__ __align__(16) bf16 g_f2_h [C_*HID_];
__device__ __align__(16) bf16 g_f2_l [C_*HID_];

__device__ __forceinline__ float blockSum256(float v, float* sh) {
    #pragma unroll
    for (int o = 16; o; o >>= 1) v += __shfl_xor_sync(0xffffffffu, v, o);
    if ((threadIdx.x & 31) == 0) sh[threadIdx.x >> 5] = v;
    __syncthreads();
    float r = sh[0]+sh[1]+sh[2]+sh[3]+sh[4]+sh[5]+sh[6]+sh[7];
    __syncthreads();
    return r;
}

__device__ __forceinline__ void split_store(float v, bf16* h, bf16* l, ll idx) {
    bf16 hh = __float2bfloat16(v);
    h[idx] = hh;
    l[idx] = __float2bfloat16(v - __bfloat162float(hh));
}

__global__ void zero_kernel(float* p, int n) {
    int i = blockIdx.x * 256 + threadIdx.x;
    if (i < n) p[i] = 0.f;
}

/* ---------------- fp32 -> bf16 hi/lo split -------------------------------- */
__global__ void cvt_split(const float4* __restrict__ src,
                          bf16* __restrict__ h, bf16* __restrict__ l, int n4) {
    int i = blockIdx.x * 256 + threadIdx.x;
    if (i >= n4) return;
    float4 v = src[i];
    float vv[4] = {v.x, v.y, v.z, v.w};
    #pragma unroll
    for (int u = 0; u < 4; u++) split_store(vv[u], h, l, (ll)i*4 + u);
}

/* ---------------- xf = concat(mem, x) + bf16 split ------------------------- */
__global__ void copy_xf_kernel(const float4* __restrict__ x,
                               const float4* __restrict__ mem,
                               float4* __restrict__ xf,
                               bf16* __restrict__ xh, bf16* __restrict__ xl) {
    ll i = (ll)blockIdx.x * 256 + threadIdx.x;
    int b  = (int)(i >> 20);
    int rem = (int)(i & 1048575);
    int tt = rem >> 18;
    int rc = rem & 262143;
    float4 v;
    if (tt < 3) v = mem[((ll)(b*3 + tt) << 18) + rc];
    else        v = x[((ll)b << 18) + rc];
    xf[i] = v;
    float vv[4] = {v.x, v.y, v.z, v.w};
    #pragma unroll
    for (int u = 0; u < 4; u++) split_store(vv[u], xh, xl, i*4 + u);
}

/* ---------------- pre-split bf16 tensor-core GEMM -------------------------
 * C = alpha*(A·W^T + bias), fp32-accurate via Ah·Wh + Ah·Wl + Al·Wh.
 * BM=128 BN=64 BK=32, 256 thr, 8 warps (4m x 2n), mma.m16n8k16.
 * Requires K%32==0, M%128==0.                                             */
__global__ void gemm_mma2(int M, int N, int K,
                          const bf16* __restrict__ Ah_, const bf16* __restrict__ Al_,
                          int lda, ll bsA,
                          const bf16* __restrict__ Wh_, const bf16* __restrict__ Wl_,
                          int ldw,
                          float* __restrict__ Cp, ll crs, ll ccs, ll bsC,
                          const float* __restrict__ bias, float alpha) {
    constexpr int BM = 128, BN = 64, BK = 32, PAD = 40; /* row stride 40 bf16 = 80B */
    __shared__ __align__(16) bf16 Ah[BM * PAD], Al[BM * PAD];
    __shared__ __align__(16) bf16 Bh[BN * PAD], Bl[BN * PAD];
    int bt = blockIdx.z;
    Ah_ += (ll)bt * bsA;  Al_ += (ll)bt * bsA;
    Cp  += (ll)bt * bsC;
    int m0 = blockIdx.x * BM, n0 = blockIdx.y * BN;
    int tid = threadIdx.x;
    int wid = tid >> 5, lane = tid & 31;
    int wm = wid >> 1, wn = wid & 1;
    int lq = lane >> 2, lr = lane & 3;

    float acc[2][4][4];
    #pragma unroll
    for (int im = 0; im < 2; im++)
        #pragma unroll
        for (int jn = 0; jn < 4; jn++)
            #pragma unroll
            for (int c = 0; c < 4; c++) acc[im][jn][c] = 0.f;

    for (int k0 = 0; k0 < K; k0 += BK) {
        /* A tiles: 128 rows x 32 bf16 = 4 float4-slots/row; 2 slots/thread */
        #pragma unroll
        for (int s = tid; s < BM * 4; s += 256) {
            int row = s >> 2;
            int q = s & 3;
            ll g = (ll)(m0 + row) * lda + k0 + q * 8;
            *(float4*)&Ah[row * PAD + q * 8] = *(const float4*)&Ah_[g];
            *(float4*)&Al[row * PAD + q * 8] = *(const float4*)&Al_[g];
        }
        /* B tiles: 64 rows x 32 bf16; 1 slot/thread */
        {
            int row = tid >> 2, q = tid & 3;
            int n = n0 + row;
            float4 vh = make_float4(0.f,0.f,0.f,0.f), vl = vh;
            if (n < N) {
                ll g = (ll)n * ldw + k0 + q * 8;
                vh = *(const float4*)&Wh_[g];
                vl = *(const float4*)&Wl_[g];
            }
            *(float4*)&Bh[row * PAD + q * 8] = vh;
            *(float4*)&Bl[row * PAD + q * 8] = vl;
        }
        __syncthreads();

        #pragma unroll
        for (int kc = 0; kc < 2; kc++) {
            int cb = kc * 16 + lr * 2;
            unsigned ah[2][4], al[2][4], bh[4][2], bl[4][2];
            #pragma unroll
            for (int im = 0; im < 2; im++) {
                int r = wm * 32 + im * 16 + lq;
                ah[im][0] = *(const unsigned*)&Ah[ r      * PAD + cb    ];
                ah[im][1] = *(const unsigned*)&Ah[(r + 8) * PAD + cb    ];
                ah[im][2] = *(const unsigned*)&Ah[ r      * PAD + cb + 8];
                ah[im][3] = *(const unsigned*)&Ah[(r + 8) * PAD + cb + 8];
                al[im][0] = *(const unsigned*)&Al[ r      * PAD + cb    ];
                al[im][1] = *(const unsigned*)&Al[(r + 8) * PAD + cb    ];
                al[im][2] = *(const unsigned*)&Al[ r      * PAD + cb + 8];
                al[im][3] = *(const unsigned*)&Al[(r + 8) * PAD + cb + 8];
            }
            #pragma unroll
            for (int jn = 0; jn < 4; jn++) {
                int n = wn * 32 + jn * 8 + lq;
                bh[jn][0] = *(const unsigned*)&Bh[n * PAD + cb    ];
                bh[jn][1] = *(const unsigned*)&Bh[n * PAD + cb + 8];
                bl[jn][0] = *(const unsigned*)&Bl[n * PAD + cb    ];
                bl[jn][1] = *(const unsigned*)&Bl[n * PAD + cb + 8];
            }
            #pragma unroll
            for (int im = 0; im < 2; im++)
                #pragma unroll
                for (int jn = 0; jn < 4; jn++) {
                    float* cc = acc[im][jn];
                    asm volatile(
                        "mma.sync.aligned.m16n8k16.row.col.f32.bf16.bf16.f32 "
                        "{%0,%1,%2,%3}, {%4,%5,%6,%7}, {%8,%9}, {%0,%1,%2,%3};"
                        : "+f"(cc[0]), "+f"(cc[1]), "+f"(cc[2]), "+f"(cc[3])
                        : "r"(ah[im][0]), "r"(ah[im][1]), "r"(ah[im][2]), "r"(ah[im][3]),
                          "r"(bh[jn][0]), "r"(bh[jn][1]));
                    asm volatile(
                        "mma.sync.aligned.m16n8k16.row.col.f32.bf16.bf16.f32 "
                        "{%0,%1,%2,%3}, {%4,%5,%6,%7}, {%8,%9}, {%0,%1,%2,%3};"
                        : "+f"(cc[0]), "+f"(cc[1]), "+f"(cc[2]), "+f"(cc[3])
                        : "r"(ah[im][0]), "r"(ah[im][1]), "r"(ah[im][2]), "r"(ah[im][3]),
                          "r"(bl[jn][0]), "r"(bl[jn][1]));
                    asm volatile(
                        "mma.sync.aligned.m16n8k16.row.col.f32.bf16.bf16.f32 "
                        "{%0,%1,%2,%3}, {%4,%5,%6,%7}, {%8,%9}, {%0,%1,%2,%3};"
                        : "+f"(cc[0]), "+f"(cc[1]), "+f"(cc[2]), "+f"(cc[3])
                        : "r"(al[im][0]), "r"(al[im][1]), "r"(al[im][2]), "r"(al[im][3]),
                          "r"(bh[jn][0]), "r"(bh[jn][1]));
                }
        }
        __syncthreads();
    }

    #pragma unroll
    for (int im = 0; im < 2; im++) {
        int mb = m0 + wm * 32 + im * 16 + lq;
        #pragma unroll
        for (int jn = 0; jn < 4; jn++) {
            int nb = n0 + wn * 32 + jn * 8 + lr * 2;
            float b0 = 0.f, b1 = 0.f;
            if (bias) {
                if (nb     < N) b0 = bias[nb];
                if (nb + 1 < N) b1 = bias[nb + 1];
            }
            float* cc = acc[im][jn];
            if (nb < N) {
                Cp[(ll)mb * crs + (ll)nb * ccs]       = (cc[0] + b0) * alpha;
                Cp[(ll)(mb + 8) * crs + (ll)nb * ccs] = (cc[2] + b0) * alpha;
            }
            if (nb + 1 < N) {
                Cp[(ll)mb * crs + (ll)(nb + 1) * ccs]       = (cc[1] + b1) * alpha;
                Cp[(ll)(mb + 8) * crs + (ll)(nb + 1) * ccs] = (cc[3] + b1) * alpha;
            }
        }
    }
}

/* ---------------- scalar SGEMM (TRW=1, used for cen) ----------------------- */
template<int BM, int BN, int TM, int TN>
__global__ void gemm_t(int M, int N, int K,
                       const float* __restrict__ A, int lda, ll bsA,
                       const float* __restrict__ W, int ldw, ll bsW,
                       float* __restrict__ Cp, ll crs, ll ccs, ll bsC,
                       float alpha, int ksplit) {
    constexpr int BK = 8;
    constexpr int TX = BN / TN, TY = BM / TM, NT = TX * TY;
    __shared__ __align__(16) float As[BK][BM + 4];
    __shared__ __align__(16) float Ws[BK][BN + 4];
    int zz = blockIdx.z, bt = zz / ksplit, ks = zz - bt * ksplit;
    A  += (ll)bt * bsA;  W += (ll)bt * bsW;  Cp += (ll)bt * bsC;
    int Kc = K / ksplit;
    int kbeg = ks * Kc, kend = kbeg + Kc;
    int m0 = blockIdx.x * BM, n0 = blockIdx.y * BN;
    int tid = threadIdx.x, tx = tid % TX, ty = tid / TX;
    float acc[TM][TN];
    #pragma unroll
    for (int i = 0; i < TM; i++)
        #pragma unroll
        for (int j = 0; j < TN; j++) acc[i][j] = 0.f;

    for (int k0 = kbeg; k0 < kend; k0 += BK) {
        for (int i4 = tid; i4 < BM * (BK/4); i4 += NT) {
            int q = i4 % (BK/4), mm = i4 / (BK/4);
            int m = m0 + mm, k = k0 + q*4;
            float4 v = make_float4(0.f,0.f,0.f,0.f);
            if (m < M) v = *(const float4*)&A[(ll)m * lda + k];
            As[q*4+0][mm] = v.x; As[q*4+1][mm] = v.y;
            As[q*4+2][mm] = v.z; As[q*4+3][mm] = v.w;
        }
        for (int i4 = tid; i4 < (BN/4) * BK; i4 += NT) {
            int q = i4 % (BN/4), kk = i4 / (BN/4);
            int n = n0 + q*4, k = k0 + kk;
            float4 v = make_float4(0.f,0.f,0.f,0.f);
            if (n + 3 < N) v = *(const float4*)&W[(ll)k * ldw + n];
            else {
                v.x = (n   < N) ? W[(ll)k*ldw + n  ] : 0.f;
                v.y = (n+1 < N) ? W[(ll)k*ldw + n+1] : 0.f;
                v.z = (n+2 < N) ? W[(ll)k*ldw + n+2] : 0.f;
                v.w = (n+3 < N) ? W[(ll)k*ldw + n+3] : 0.f;
            }
            *(float4*)&Ws[kk][q*4] = v;
        }
        __syncthreads();
        #pragma unroll
        for (int kk = 0; kk < BK; kk++) {
            float a[TM], w[TN];
            #pragma unroll
            for (int i = 0; i < TM/4; i++)
                *(float4*)&a[i*4] = *(const float4*)&As[kk][ty*TM + i*4];
            #pragma unroll
            for (int j = 0; j < TN/4; j++)
                *(float4*)&w[j*4] = *(const float4*)&Ws[kk][tx*TN + j*4];
            #pragma unroll
            for (int i = 0; i < TM; i++)
                #pragma unroll
                for (int j = 0; j < TN; j++) acc[i][j] += a[i] * w[j];
        }
        __syncthreads();
    }
    #pragma unroll
    for (int i = 0; i < TM; i++) {
        int m = m0 + ty*TM + i;
        if (m >= M) continue;
        #pragma unroll
        for (int j = 0; j < TN; j++) {
            int n = n0 + tx*TN + j;
            if (n >= N) continue;
            float v = acc[i][j] * alpha;
            float* dst = Cp + (ll)m * crs + (ll)n * ccs;
            if (ksplit == 1) *dst = v;
            else atomicAdd(dst, v);
        }
    }
}

/* ---------------- cosine scales per (b,r) --------------------------------- */
__global__ void scales_kernel(const float* __restrict__ z, const float* __restrict__ clt,
                              const float* __restrict__ p1, const float* __restrict__ p2,
                              float* __restrict__ s1o, float* __restrict__ s2o) {
    __shared__ float p1s[NC_], p2s[NC_], pn[2];
    int b = blockIdx.y;
    int r = blockIdx.x * 128 + threadIdx.x;
    int tid = threadIdx.x;
    for (int i = tid; i < NC_; i += 128) { p1s[i] = p1[i]; p2s[i] = p2[i]; }
    if (tid < 2) {
        const float* p = tid ? p2 : p1;
        float s = 0.f;
        for (int k = 0; k < NC_; k++) s += p[k]*p[k];
        pn[tid] = 1.0f / fmaxf(sqrtf(s), 1e-12f);
    }
    __syncthreads();
    const float* zb = z   + (ll)b * NC_ * R_ + r;
    const float* cb = clt + (ll)b * NC_ * R_ + r;
    float zz = 0.f, zp = 0.f, cc = 0.f, cp = 0.f;
    #pragma unroll 2
    for (int j = 0; j < NC_; j++) {
        float zv = zb[(ll)j * R_];
        float cv = cb[(ll)j * R_];
        zz += zv*zv; zp += zv*p1s[j];
        cc += cv*cv; cp += cv*p2s[j];
    }
    float s1 = zp * pn[0] / fmaxf(sqrtf(zz), 1e-12f);
    float s2 = cp * pn[1] / fmaxf(sqrtf(cc), 1e-12f);
    s1o[(ll)b*R_ + r] = fminf(fmaxf(s1, 0.f), 1.f);
    s2o[(ll)b*R_ + r] = fminf(fmaxf(s2, 0.f), 1.f);
}

/* ---------------- cxz = 0.5*(t1^T@(z*s1) + t2^T@(cl*s2)) ------------------ */
__global__ void cxz_gemm(const float* __restrict__ z, const float* __restrict__ clt,
                         const float* __restrict__ t1, const float* __restrict__ t2,
                         const float* __restrict__ s1, const float* __restrict__ s2,
                         float* __restrict__ out) {
    constexpr int BK = 8;
    __shared__ __align__(16) float As[BK][68];
    __shared__ __align__(16) float Ws[BK][68];
    __shared__ float s1s[64], s2s[64];
    int b = blockIdx.z;
    int m0 = blockIdx.x * 64, n0 = blockIdx.y * 64;
    int tid = threadIdx.x, tx = tid % 16, ty = tid / 16;
    const float* zb = z   + (ll)b * NC_ * R_;
    const float* cb = clt + (ll)b * NC_ * R_;
    if (tid < 64) {
        s1s[tid] = s1[(ll)b * R_ + n0 + tid];
        s2s[tid] = s2[(ll)b * R_ + n0 + tid];
    }
    __syncthreads();
    float acc[4][4];
    #pragma unroll
    for (int i = 0; i < 4; i++)
        #pragma unroll
        for (int j = 0; j < 4; j++) acc[i][j] = 0.f;

    for (int k0 = 0; k0 < 2*NC_; k0 += BK) {
        for (int i = tid; i < 64 * BK; i += 256) {
            int mm = i % 64, kk = i / 64;
            int j = k0 + kk, m = m0 + mm;
            float v = 0.f;
            if (m < NC_) {
                if (j < NC_)        v = t1[j*NC_ + m];
                else if (j < 2*NC_) v = t2[(j-NC_)*NC_ + m];
            }
            As[kk][mm] = v;
        }
        for (int i = tid; i < 16 * BK; i += 256) {
            int q = i % 16, kk = i / 16;
            int j = k0 + kk, r = n0 + q*4;
            float4 v = make_float4(0.f,0.f,0.f,0.f);
            if (j < NC_) {
                v = *(const float4*)&zb[(ll)j * R_ + r];
                v.x *= s1s[q*4]; v.y *= s1s[q*4+1]; v.z *= s1s[q*4+2]; v.w *= s1s[q*4+3];
            } else if (j < 2*NC_) {
                v = *(const float4*)&cb[(ll)(j-NC_) * R_ + r];
                v.x *= s2s[q*4]; v.y *= s2s[q*4+1]; v.z *= s2s[q*4+2]; v.w *= s2s[q*4+3];
            }
            *(float4*)&Ws[kk][q*4] = v;
        }
        __syncthreads();
        #pragma unroll
        for (int kk = 0; kk < BK; kk++) {
            float a[4], w[4];
            *(float4*)a = *(const float4*)&As[kk][ty*4];
            *(float4*)w = *(const float4*)&Ws[kk][tx*4];
            #pragma unroll
            for (int i = 0; i < 4; i++)
                #pragma unroll
                for (int j = 0; j < 4; j++) acc[i][j] += a[i] * w[j];
        }
        __syncthreads();
    }
    #pragma unroll
    for (int i = 0; i < 4; i++) {
        int m = m0 + ty*4 + i;
        if (m >= NC_) continue;
        #pragma unroll
        for (int j = 0; j < 4; j++) {
            int r = n0 + tx*4 + j;
            out[((ll)(b*NC_ + m)) * R_ + r] = 0.5f * acc[i][j];
        }
    }
}

/* ---------------- softmax + raw copy -------------------------------------- */
__global__ void softmax_rows2(const float* __restrict__ cxz,
                              float* __restrict__ asn, float* __restrict__ soft) {
    int row = blockIdx.x;
    int b = row / 600; int rem = row - b * 600;
    int t = rem / NC_; int k = rem - t * NC_;
    const float* s = cxz + ((ll)(b * NC_ + k)) * R_ + (ll)t * N_;
    ll drow = ((ll)((b * T_ + t) * NC_ + k)) * N_;
    __shared__ float sh[8];
    int tid = threadIdx.x;
    float mx = -1e30f;
    for (int i = tid; i < N_; i += 256) mx = fmaxf(mx, s[i]);
    #pragma unroll
    for (int o = 16; o; o >>= 1) mx = fmaxf(mx, __shfl_xor_sync(0xffffffffu, mx, o));
    if ((tid & 31) == 0) sh[tid >> 5] = mx;
    __syncthreads();
    mx = fmaxf(fmaxf(fmaxf(sh[0],sh[1]),fmaxf(sh[2],sh[3])),
               fmaxf(fmaxf(sh[4],sh[5]),fmaxf(sh[6],sh[7])));
    __syncthreads();
    float sum = 0.f;
    for (int i = tid; i < N_; i += 256) sum += expf(s[i] - mx);
    sum = blockSum256(sum, sh);
    float inv = 1.0f / sum;
    for (int i = tid; i < N_; i += 256) {
        float v = s[i];
        asn[drow + i]  = v;
        soft[drow + i] = expf(v - mx) * inv;
    }
}

/* ---------------- gate + LayerNorm --------------------------------------- */
__global__ void gate_ln_kernel(const float* __restrict__ cen,
                               const float* __restrict__ nw, const float* __restrict__ nb,
                               const float* __restrict__ salpha, const float* __restrict__ sbeta,
                               float* __restrict__ cin_out) {
    int k = blockIdx.x, b = blockIdx.y, c = threadIdx.x;
    __shared__ float sh[8];
    float pv[4];
    #pragma unroll
    for (int t = 0; t < 4; t++)
        pv[t] = cen[(((ll)b*4 + t) * NC_ + k) * C_ + c];
    float last = pv[3];
    float ll2 = blockSum256(last*last, sh);
    float cin = last;
    float alpha = salpha[0], beta = sbeta[0];
    for (int t = 0; t < 3; t++) {
        float dt = blockSum256(last * pv[t], sh);
        float pp = blockSum256(pv[t] * pv[t], sh);
        float denom = fmaxf(sqrtf(ll2) * sqrtf(pp), 1e-8f);
        float gate = 1.0f / (1.0f + expf(-(beta + alpha * (dt / denom))));
        cin += gate * pv[t];
    }
    float m  = blockSum256(cin, sh) * (1.0f / C_);
    float dv = cin - m;
    float var = blockSum256(dv*dv, sh) * (1.0f / C_);
    cin_out[((ll)b*NC_ + k) * C_ + c] = dv * rsqrtf(var + 1e-5f) * nw[c] + nb[c];
}

/* ---------------- K/V projections ---------------------------------------- */
__global__ void kv_kernel(const float* __restrict__ cin,
                          const float* __restrict__ kw, const float* __restrict__ kb,
                          const float* __restrict__ vw, const float* __restrict__ vb,
                          float* __restrict__ ko, float* __restrict__ vo) {
    int row = blockIdx.x, c = threadIdx.x;
    __shared__ float ci[C_];
    ci[c] = cin[(ll)row * C_ + c];
    __syncthreads();
    float ka = kb[c], va = vb[c];
    const float* kwr = kw + (ll)c * C_;
    const float* vwr = vw + (ll)c * C_;
    #pragma unroll 4
    for (int j = 0; j < C_; j++) {
        float cv = ci[j];
        ka += cv * kwr[j];
        va += cv * vwr[j];
    }
    ko[(ll)row * C_ + c] = ka;
    vo[(ll)row * C_ + c] = va;
}

/* ---------------- fused attention -> bf16 hi/lo output -------------------- */
__global__ void attn_kernel(const float* __restrict__ q, const float* __restrict__ ks,
                            const float* __restrict__ vs,
                            bf16* __restrict__ oh, bf16* __restrict__ ol) {
    const int b = blockIdx.y;
    const int n0 = blockIdx.x * 8;
    __shared__ float qs[8][C_];
    __shared__ float P[8][8][152];
    int tid = threadIdx.x;
    for (int i = tid; i < 8*C_; i += 256)
        qs[i >> 8][i & 255] = q[((ll)b*N_ + n0 + (i >> 8)) * C_ + (i & 255)];
    __syncthreads();
    int h = tid >> 5, lane = tid & 31;
    float lg[8][5];
    #pragma unroll
    for (int g = 0; g < 8; g++)
        #pragma unroll
        for (int s = 0; s < 5; s++) lg[g][s] = -1e30f;
    #pragma unroll
    for (int s = 0; s < 5; s++) {
        int idx = lane + s*32;
        if (idx < NC_) {
            const float4* kp = reinterpret_cast<const float4*>(ks + ((ll)b*NC_ + idx)*C_ + h*32);
            float4 kk[8];
            #pragma unroll
            for (int u = 0; u < 8; u++) kk[u] = kp[u];
            #pragma unroll
            for (int g = 0; g < 8; g++) {
                const float* qb = &qs[g][h*32];
                float d = 0.f;
                #pragma unroll
                for (int u = 0; u < 8; u++)
                    d += kk[u].x*qb[u*4] + kk[u].y*qb[u*4+1] + kk[u].z*qb[u*4+2] + kk[u].w*qb[u*4+3];
                lg[g][s] = d;
            }
        }
    }
    float invg[8];
    #pragma unroll
    for (int g = 0; g < 8; g++) {
        float mx = -1e30f;
        #pragma unroll
        for (int s = 0; s < 5; s++) mx = fmaxf(mx, lg[g][s]);
        #pragma unroll
        for (int o2 = 16; o2; o2 >>= 1) mx = fmaxf(mx, __shfl_xor_sync(0xffffffffu, mx, o2));
        float sum = 0.f;
        #pragma unroll
        for (int s = 0; s < 5; s++) {
            int idx = lane + s*32;
            if (idx < NC_) {
                float e = expf(lg[g][s] - mx);
                P[h][g][idx] = e;
                sum += e;
            }
        }
        #pragma unroll
        for (int o2 = 16; o2; o2 >>= 1) sum += __shfl_xor_sync(0xffffffffu, sum, o2);
        invg[g] = 1.0f / sum;
    }
    __syncwarp();
    float og[8] = {0.f,0.f,0.f,0.f,0.f,0.f,0.f,0.f};
    for (int j = 0; j < NC_; j++) {
        float vv = vs[((ll)b*NC_ + j) * C_ + h*32 + lane];
        #pragma unroll
        for (int g = 0; g < 8; g++) og[g] += P[h][g][j] * vv;
    }
    #pragma unroll
    for (int g = 0; g < 8; g++) {
        float v = og[g] * invg[g];
        split_store(v, oh, ol, ((ll)b*N_ + n0 + g) * C_ + h*32 + lane);
    }
}

/* ---------------- depthwise 3x3 conv + GELU -> bf16 hi/lo ----------------- */
__global__ void conv_gelu2(const float* __restrict__ h,
                           const float* __restrict__ dww, const float* __restrict__ dwb,
                           bf16* __restrict__ oh, bf16* __restrict__ ol) {
    __shared__ float patch[10][10][64];
    int ch0 = blockIdx.x * 64;
    int tileid = blockIdx.y;
    int y0 = (tileid >> 3) * 8, x0 = (tileid & 7) * 8;
    int b = blockIdx.z;
    int tid = threadIdx.x;
    for (int i = tid; i < 6400; i += 256) {
        int c = i & 63, sp = i >> 6;
        int py = sp / 10, px = sp % 10;
        int yy = y0 + py - 1, xx = x0 + px - 1;
        float v = 0.f;
        if (yy >= 0 && yy < 64 && xx >= 0 && xx < 64)
            v = h[(((ll)b*N_) + (yy*64 + xx)) * HID_ + ch0 + c];
        patch[py][px][c] = v;
    }
    __syncthreads();
    int c = tid & 63, sub = tid >> 6;
    float w[9];
    #pragma unroll
    for (int i = 0; i < 9; i++) w[i] = dww[(ch0 + c)*9 + i];
    float bv = dwb[ch0 + c];
    for (int oy = sub; oy < 8; oy += 4) {
        #pragma unroll
        for (int ox = 0; ox < 8; ox++) {
            float a = bv;
            #pragma unroll
            for (int dy = 0; dy < 3; dy++)
                #pragma unroll
                for (int dx = 0; dx < 3; dx++)
                    a += patch[oy+dy][ox+dx][c] * w[dy*3+dx];
            float g = 0.5f * a * (1.0f + erff(a * 0.7071067811865475f));
            split_store(g, oh, ol, (((ll)b*N_) + ((y0+oy)*64 + x0+ox)) * HID_ + ch0 + c);
        }
    }
}

/* ---------------- residual + LayerNorm (optional bf16 dual-write) ---------- */
__global__ void add_ln_kernel(const float* __restrict__ res, const float* __restrict__ val,
                              const float* __restrict__ nw, const float* __restrict__ nb,
                              float* __restrict__ dst,
                              bf16* __restrict__ dh, bf16* __restrict__ dl) {
    ll row = blockIdx.x;
    int c = threadIdx.x;
    __shared__ float sh[8];
    float v = val[row * C_ + c];
    float m = blockSum256(v, sh) * (1.0f / C_);
    float d = v - m;
    float var = blockSum256(d*d, sh) * (1.0f / C_);
    float r = res[row * C_ + c] + d * rsqrtf(var + 1e-5f) * nw[c] + nb[c];
    dst[row * C_ + c] = r;
    if (dh) split_store(r, dh, dl, row * C_ + c);
}

/* ---------------- host launch --------------------------------------------- */
static float* symaddr(const void* sym) {
    void* p = nullptr;
    cudaGetSymbolAddress(&p, sym);
    return (float*)p;
}
static bf16* symaddrb(const void* sym) {
    void* p = nullptr;
    cudaGetSymbolAddress(&p, sym);
    return (bf16*)p;
}

extern "C" void kernel_launch(void* const* d_in, const int* in_sizes, int n_in,
                              void* d_out, int out_size) {
    const float* x    = (const float*)d_in[0];
    const float* z    = (const float*)d_in[1];
    const float* mem  = (const float*)d_in[2];
    const float* cw   = (const float*)d_in[3];
    const float* p1   = (const float*)d_in[4];
    const float* t1   = (const float*)d_in[5];
    const float* p2   = (const float*)d_in[6];
    const float* t2   = (const float*)d_in[7];
    const float* sal  = (const float*)d_in[8];
    const float* sbe  = (const float*)d_in[9];
    const float* qw   = (const float*)d_in[10];
    const float* qb   = (const float*)d_in[11];
    const float* kw   = (const float*)d_in[12];
    const float* kb   = (const float*)d_in[13];
    const float* vw   = (const float*)d_in[14];
    const float* vb   = (const float*)d_in[15];
    const float* pw   = (const float*)d_in[16];
    const float* pb   = (const float*)d_in[17];
    const float* nw   = (const float*)d_in[18];
    const float* nb   = (const float*)d_in[19];
    const float* f1w  = (const float*)d_in[20];
    const float* f1b  = (const float*)d_in[21];
    const float* dww  = (const float*)d_in[22];
    const float* dwb  = (const float*)d_in[23];
    const float* f2w  = (const float*)d_in[24];
    const float* f2b  = (const float*)d_in[25];

    float* out_main = (float*)d_out;
    float* out_cxz  = out_main + (ll)B_*N_*C_;
    float* out_asn  = out_cxz  + (ll)B_*NC_*R_;

    float* xf   = symaddr(g_xf);
    float* clt  = symaddr(g_clt);
    float* s1   = symaddr(g_s1);
    float* s2   = symaddr(g_s2);
    float* soft = symaddr(g_soft);
    float* cen  = symaddr(g_cen);
    float* cin  = symaddr(g_cin);
    float* ksc  = symaddr(g_k);
    float* vsc  = symaddr(g_v);
    float* qsc  = symaddr(g_q);
    float* tmp  = symaddr(g_tmp);
    float* out1 = symaddr(g_out1);
    float* h1   = symaddr(g_h1);

    bf16 *xf_h = symaddrb(g_xf_h), *xf_l = symaddrb(g_xf_l);
    bf16 *x_h  = symaddrb(g_x_h),  *x_l  = symaddrb(g_x_l);
    bf16 *at_h = symaddrb(g_atn_h),*at_l = symaddrb(g_atn_l);
    bf16 *o1_h = symaddrb(g_o1_h), *o1_l = symaddrb(g_o1_l);
    bf16 *hg_h = symaddrb(g_hg_h), *hg_l = symaddrb(g_hg_l);
    bf16 *cw_h = symaddrb(g_cw_h), *cw_l = symaddrb(g_cw_l);
    bf16 *qw_h = symaddrb(g_qw_h), *qw_l = symaddrb(g_qw_l);
    bf16 *pw_h = symaddrb(g_pw_h), *pw_l = symaddrb(g_pw_l);
    bf16 *f1_h = symaddrb(g_f1_h), *f1_l = symaddrb(g_f1_l);
    bf16 *f2_h = symaddrb(g_f2_h), *f2_l = symaddrb(g_f2_l);

    /* 0. weight + x conversions */
    cvt_split<<<(NC_*C_/4 + 255)/256, 256>>>((const float4*)cw, cw_h, cw_l, NC_*C_/4);
    cvt_split<<<(C_*C_/4 + 255)/256, 256>>>((const float4*)qw, qw_h, qw_l, C_*C_/4);
    cvt_split<<<(C_*C_/4 + 255)/256, 256>>>((const float4*)pw, pw_h, pw_l, C_*C_/4);
    cvt_split<<<(HID_*C_/4 + 255)/256, 256>>>((const float4*)f1w, f1_h, f1_l, HID_*C_/4);
    cvt_split<<<(HID_*C_/4 + 255)/256, 256>>>((const float4*)f2w, f2_h, f2_l, HID_*C_/4);
    cvt_split<<<(B_*N_*C_/4 + 255)/256, 256>>>((const float4*)x, x_h, x_l, B_*N_*C_/4);

    /* 1. xf = concat(mem, x) + bf16 split */
    copy_xf_kernel<<<8192, 256>>>((const float4*)x, (const float4*)mem,
                                  (float4*)xf, xf_h, xf_l);

    /* 2. clt (tensor-core, transposed store) */
    gemm_mma2<<<dim3(R_/128, 3, B_), 256>>>(
        R_, NC_, C_, xf_h, xf_l, C_, (ll)R_*C_, cw_h, cw_l, C_,
        clt, 1, R_, (ll)NC_*R_, nullptr, 1.0f);

    /* 3. cosine scales */
    scales_kernel<<<dim3(R_/128, B_), 128>>>(z, clt, p1, p2, s1, s2);

    /* 4. cluster_x_z */
    cxz_gemm<<<dim3(3, R_/64, B_), 256>>>(z, clt, t1, t2, s1, s2, out_cxz);

    /* 5. softmax + assigned copy */
    softmax_rows2<<<B_*T_*NC_, 256>>>(out_cxz, out_asn, soft);

    /* 6. cen = soft @ xf  (split-K=8, scalar) */
    zero_kernel<<<(B_*T_*NC_*C_ + 255)/256, 256>>>(cen, B_*T_*NC_*C_);
    gemm_t<64,64,4,4><<<dim3(3, 4, B_*T_*8), 256>>>(
        NC_, C_, N_, soft, N_, (ll)NC_*N_, xf, C_, (ll)N_*C_,
        cen, C_, 1, (ll)NC_*C_, 1.0f, 8);

    /* 7. gate + LN */
    gate_ln_kernel<<<dim3(NC_, B_), 256>>>(cen, nw, nb, sal, sbe, cin);

    /* 8. k,v */
    kv_kernel<<<B_*NC_, 256>>>(cin, kw, kb, vw, vb, ksc, vsc);

    /* 9. q (tensor-core) */
    gemm_mma2<<<dim3(64, 4, 1), 256>>>(
        B_*N_, C_, C_, x_h, x_l, C_, 0, qw_h, qw_l, C_,
        qsc, C_, 1, 0, qb, 0.17677669529663687f);

    /* 10. attention -> bf16 */
    attn_kernel<<<dim3(N_/8, B_), 256>>>(qsc, ksc, vsc, at_h, at_l);

    /* 11. proj (tensor-core) */
    gemm_mma2<<<dim3(64, 4, 1), 256>>>(
        B_*N_, C_, C_, at_h, at_l, C_, 0, pw_h, pw_l, C_,
        tmp, C_, 1, 0, pb, 1.0f);

    /* 12. out1 = x + LN(proj), dual-write */
    add_ln_kernel<<<B_*N_, 256>>>(x, tmp, nw, nb, out1, o1_h, o1_l);

    /* 13. fc1 (tensor-core) */
    gemm_mma2<<<dim3(64, 16, 1), 256>>>(
        B_*N_, HID_, C_, o1_h, o1_l, C_, 0, f1_h, f1_l, C_,
        h1, HID_, 1, 0, f1b, 1.0f);

    /* 14. depthwise conv + GELU -> bf16 */
    conv_gelu2<<<dim3(HID_/64, 64, B_), 256>>>(h1, dww, dwb, hg_h, hg_l);

    /* 15. fc2 (tensor-core, K=1024) */
    gemm_mma2<<<dim3(64, 4, 1), 256>>>(
        B_*N_, C_, HID_, hg_h, hg_l, HID_, 0, f2_h, f2_l, HID_,
        tmp, C_, 1, 0, f2b, 1.0f);

    /* 16. out = out1 + LN(fc2) */
    add_ln_kernel<<<B_*N_, 256>>>(out1, tmp, nw, nb, out_main, nullptr, nullptr);
}

// round 10
// speedup vs baseline: 1.6567x; 1.0690x over previous
#include <cuda_runtime.h>
#include <cuda_bf16.h>
#include <math.h>

#define B_   2
#define N_   4096
#define C_   256
#define NC_  150
#define T_   4
#define HID_ 1024
#define R_   16384   /* T_*N_ */
#define KS_  320     /* padded 2*NC_ for cxz MMA */

typedef long long ll;
typedef __nv_bfloat16 bf16;

/* ---------------- scratch (device globals) ------------------------------- */
__device__ float g_xf  [B_*T_*N_*C_];
__device__ float g_clt [B_*NC_*R_];
__device__ float g_s1  [B_*R_];
__device__ float g_s2  [B_*R_];
__device__ float g_cen [B_*T_*NC_*C_];
__device__ float g_cin [B_*NC_*C_];
__device__ float g_k   [B_*NC_*C_];
__device__ float g_v   [B_*NC_*C_];
__device__ float g_q   [B_*N_*C_];
__device__ float g_tmp [B_*N_*C_];
__device__ float g_out1[B_*N_*C_];
__device__ float g_h1  [B_*N_*HID_];

/* bf16 hi/lo operand buffers — 16B aligned (float4-read in GEMM) */
__device__ __align__(16) bf16 g_xf_h [B_*T_*N_*C_];
__device__ __align__(16) bf16 g_xf_l [B_*T_*N_*C_];
__device__ __align__(16) bf16 g_xfT_h[B_*T_*C_*N_];
__device__ __align__(16) bf16 g_xfT_l[B_*T_*C_*N_];
__device__ __align__(16) bf16 g_S_h  [B_*R_*KS_];
__device__ __align__(16) bf16 g_S_l  [B_*R_*KS_];
__device__ __align__(16) bf16 g_tc_h [NC_*KS_];
__device__ __align__(16) bf16 g_tc_l [NC_*KS_];
__device__ __align__(16) bf16 g_sf_h [B_*T_*NC_*N_];
__device__ __align__(16) bf16 g_sf_l [B_*T_*NC_*N_];
__device__ __align__(16) bf16 g_x_h  [B_*N_*C_];
__device__ __align__(16) bf16 g_x_l  [B_*N_*C_];
__device__ __align__(16) bf16 g_atn_h[B_*N_*C_];
__device__ __align__(16) bf16 g_atn_l[B_*N_*C_];
__device__ __align__(16) bf16 g_o1_h [B_*N_*C_];
__device__ __align__(16) bf16 g_o1_l [B_*N_*C_];
__device__ __align__(16) bf16 g_hg_h [B_*N_*HID_];
__device__ __align__(16) bf16 g_hg_l [B_*N_*HID_];
__device__ __align__(16) bf16 g_cw_h [NC_*C_];
__device__ __align__(16) bf16 g_cw_l [NC_*C_];
__device__ __align__(16) bf16 g_qw_h [C_*C_];
__device__ __align__(16) bf16 g_qw_l [C_*C_];
__device__ __align__(16) bf16 g_pw_h [C_*C_];
__device__ __align__(16) bf16 g_pw_l [C_*C_];
__device__ __align__(16) bf16 g_f1_h [HID_*C_];
__device__ __align__(16) bf16 g_f1_l [HID_*C_];
__device__ __align__(16) bf16 g_f2_h [C_*HID_];
__device__ __align__(16) bf16 g_f2_l [C_*HID_];

__device__ __forceinline__ float blockSum256(float v, float* sh) {
    #pragma unroll
    for (int o = 16; o; o >>= 1) v += __shfl_xor_sync(0xffffffffu, v, o);
    if ((threadIdx.x & 31) == 0) sh[threadIdx.x >> 5] = v;
    __syncthreads();
    float r = sh[0]+sh[1]+sh[2]+sh[3]+sh[4]+sh[5]+sh[6]+sh[7];
    __syncthreads();
    return r;
}

__device__ __forceinline__ void split_store(float v, bf16* h, bf16* l, ll idx) {
    bf16 hh = __float2bfloat16(v);
    h[idx] = hh;
    l[idx] = __float2bfloat16(v - __bfloat162float(hh));
}
__device__ __forceinline__ void split_pair(float v, bf16& h, bf16& l) {
    h = __float2bfloat16(v);
    l = __float2bfloat16(v - __bfloat162float(h));
}

__global__ void zero_kernel(float* p, int n) {
    int i = blockIdx.x * 256 + threadIdx.x;
    if (i < n) p[i] = 0.f;
}

/* ---------------- fp32 -> bf16 hi/lo split -------------------------------- */
__global__ void cvt_split(const float4* __restrict__ src,
                          bf16* __restrict__ h, bf16* __restrict__ l, int n4) {
    int i = blockIdx.x * 256 + threadIdx.x;
    if (i >= n4) return;
    float4 v = src[i];
    float vv[4] = {v.x, v.y, v.z, v.w};
    #pragma unroll
    for (int u = 0; u < 4; u++) split_store(vv[u], h, l, (ll)i*4 + u);
}

/* ---------------- tcat hi/lo: tc[kp][j], j<150:t1, j<300:t2, else 0 ------- */
__global__ void build_tcat(const float* __restrict__ t1, const float* __restrict__ t2,
                           bf16* __restrict__ th, bf16* __restrict__ tl) {
    int idx = blockIdx.x * 256 + threadIdx.x;
    if (idx >= NC_ * KS_) return;
    int kp = idx / KS_, j = idx % KS_;
    float v = 0.f;
    if (j < NC_)        v = t1[j * NC_ + kp];
    else if (j < 2*NC_) v = t2[(j - NC_) * NC_ + kp];
    split_store(v, th, tl, idx);
}

/* ---------------- xf = concat(mem, x) + bf16 split ------------------------- */
__global__ void copy_xf_kernel(const float4* __restrict__ x,
                               const float4* __restrict__ mem,
                               float4* __restrict__ xf,
                               bf16* __restrict__ xh, bf16* __restrict__ xl) {
    ll i = (ll)blockIdx.x * 256 + threadIdx.x;
    int b  = (int)(i >> 20);
    int rem = (int)(i & 1048575);
    int tt = rem >> 18;
    int rc = rem & 262143;
    float4 v;
    if (tt < 3) v = mem[((ll)(b*3 + tt) << 18) + rc];
    else        v = x[((ll)b << 18) + rc];
    xf[i] = v;
    float vv[4] = {v.x, v.y, v.z, v.w};
    #pragma unroll
    for (int u = 0; u < 4; u++) split_store(vv[u], xh, xl, i*4 + u);
}

/* ---------------- xfT hi/lo: xfT[bt][c][n] (smem transpose) ---------------- */
__global__ void build_xfT(const float* __restrict__ xf,
                          bf16* __restrict__ oh, bf16* __restrict__ olo) {
    __shared__ float tile[32][65];
    int bt = blockIdx.z;
    int n0 = blockIdx.x * 64, c0 = blockIdx.y * 32;
    int tid = threadIdx.x;
    for (int i = tid; i < 32 * 64; i += 256) {
        int cl = i & 31, nl = i >> 5;
        tile[cl][nl] = xf[((ll)bt * N_ + n0 + nl) * C_ + c0 + cl];
    }
    __syncthreads();
    int cl = tid >> 3, nseg = (tid & 7) * 8;
    __align__(16) bf16 hb[8], lb[8];
    #pragma unroll
    for (int u = 0; u < 8; u++) split_pair(tile[cl][nseg + u], hb[u], lb[u]);
    ll off = ((ll)bt * C_ + c0 + cl) * N_ + n0 + nseg;
    *(uint4*)&oh [off] = *(const uint4*)hb;
    *(uint4*)&olo[off] = *(const uint4*)lb;
}

/* ---------------- S hi/lo: S[b][r][j] = scaled z/clt (smem transpose) ------ */
__global__ void build_S(const float* __restrict__ z, const float* __restrict__ clt,
                        const float* __restrict__ s1, const float* __restrict__ s2,
                        bf16* __restrict__ sh_, bf16* __restrict__ sl_) {
    __shared__ float tile[32][65];
    __shared__ float s1s[64], s2s[64];
    int b = blockIdx.y;
    int r0 = blockIdx.x * 64;
    int tid = threadIdx.x;
    if (tid < 64) {
        s1s[tid] = s1[(ll)b * R_ + r0 + tid];
        s2s[tid] = s2[(ll)b * R_ + r0 + tid];
    }
    __syncthreads();
    for (int jc = 0; jc < KS_ / 32; jc++) {
        int j0 = jc * 32;
        for (int i = tid; i < 32 * 64; i += 256) {
            int rl = i & 63, jl = i >> 6;
            int j = j0 + jl;
            float v = 0.f;
            if (j < NC_)        v = z  [((ll)b * NC_ + j)        * R_ + r0 + rl] * s1s[rl];
            else if (j < 2*NC_) v = clt[((ll)b * NC_ + (j-NC_))  * R_ + r0 + rl] * s2s[rl];
            tile[jl][rl] = v;
        }
        __syncthreads();
        int rl = tid >> 2, jseg = (tid & 3) * 8;
        __align__(16) bf16 hb[8], lb[8];
        #pragma unroll
        for (int u = 0; u < 8; u++) split_pair(tile[jseg + u][rl], hb[u], lb[u]);
        ll off = ((ll)b * R_ + r0 + rl) * KS_ + j0 + jseg;
        *(uint4*)&sh_[off] = *(const uint4*)hb;
        *(uint4*)&sl_[off] = *(const uint4*)lb;
        __syncthreads();
    }
}

/* ---------------- pre-split bf16 tensor-core GEMM -------------------------
 * C = alpha*(A·W^T + bias), fp32-accurate via Ah·Wh + Ah·Wl + Al·Wh.
 * BM=128 BN=64 BK=32, 256 thr, 8 warps (4m x 2n), mma.m16n8k16.
 * M-guarded; optional split-K (atomicAdd). (K/ksplit)%32==0.              */
__global__ void gemm_mma2(int M, int N, int K,
                          const bf16* __restrict__ Ah_, const bf16* __restrict__ Al_,
                          int lda, ll bsA,
                          const bf16* __restrict__ Wh_, const bf16* __restrict__ Wl_,
                          int ldw, ll bsW,
                          float* __restrict__ Cp, ll crs, ll ccs, ll bsC,
                          const float* __restrict__ bias, float alpha, int ksplit) {
    constexpr int BM = 128, BN = 64, BK = 32, PAD = 40;
    __shared__ __align__(16) bf16 Ah[BM * PAD], Al[BM * PAD];
    __shared__ __align__(16) bf16 Bh[BN * PAD], Bl[BN * PAD];
    int zz = blockIdx.z, bt = zz / ksplit, ks = zz - bt * ksplit;
    Ah_ += (ll)bt * bsA;  Al_ += (ll)bt * bsA;
    Wh_ += (ll)bt * bsW;  Wl_ += (ll)bt * bsW;
    Cp  += (ll)bt * bsC;
    int Kc = K / ksplit;
    int kbeg = ks * Kc, kend = kbeg + Kc;
    int m0 = blockIdx.x * BM, n0 = blockIdx.y * BN;
    int tid = threadIdx.x;
    int wid = tid >> 5, lane = tid & 31;
    int wm = wid >> 1, wn = wid & 1;
    int lq = lane >> 2, lr = lane & 3;

    float acc[2][4][4];
    #pragma unroll
    for (int im = 0; im < 2; im++)
        #pragma unroll
        for (int jn = 0; jn < 4; jn++)
            #pragma unroll
            for (int c = 0; c < 4; c++) acc[im][jn][c] = 0.f;

    for (int k0 = kbeg; k0 < kend; k0 += BK) {
        #pragma unroll
        for (int s = tid; s < BM * 4; s += 256) {
            int row = s >> 2;
            int q = s & 3;
            int m = m0 + row;
            float4 vh = make_float4(0.f,0.f,0.f,0.f), vl = vh;
            if (m < M) {
                ll g = (ll)m * lda + k0 + q * 8;
                vh = *(const float4*)&Ah_[g];
                vl = *(const float4*)&Al_[g];
            }
            *(float4*)&Ah[row * PAD + q * 8] = vh;
            *(float4*)&Al[row * PAD + q * 8] = vl;
        }
        {
            int row = tid >> 2, q = tid & 3;
            int n = n0 + row;
            float4 vh = make_float4(0.f,0.f,0.f,0.f), vl = vh;
            if (n < N) {
                ll g = (ll)n * ldw + k0 + q * 8;
                vh = *(const float4*)&Wh_[g];
                vl = *(const float4*)&Wl_[g];
            }
            *(float4*)&Bh[row * PAD + q * 8] = vh;
            *(float4*)&Bl[row * PAD + q * 8] = vl;
        }
        __syncthreads();

        #pragma unroll
        for (int kc = 0; kc < 2; kc++) {
            int cb = kc * 16 + lr * 2;
            unsigned ah[2][4], al[2][4], bh[4][2], bl[4][2];
            #pragma unroll
            for (int im = 0; im < 2; im++) {
                int r = wm * 32 + im * 16 + lq;
                ah[im][0] = *(const unsigned*)&Ah[ r      * PAD + cb    ];
                ah[im][1] = *(const unsigned*)&Ah[(r + 8) * PAD + cb    ];
                ah[im][2] = *(const unsigned*)&Ah[ r      * PAD + cb + 8];
                ah[im][3] = *(const unsigned*)&Ah[(r + 8) * PAD + cb + 8];
                al[im][0] = *(const unsigned*)&Al[ r      * PAD + cb    ];
                al[im][1] = *(const unsigned*)&Al[(r + 8) * PAD + cb    ];
                al[im][2] = *(const unsigned*)&Al[ r      * PAD + cb + 8];
                al[im][3] = *(const unsigned*)&Al[(r + 8) * PAD + cb + 8];
            }
            #pragma unroll
            for (int jn = 0; jn < 4; jn++) {
                int n = wn * 32 + jn * 8 + lq;
                bh[jn][0] = *(const unsigned*)&Bh[n * PAD + cb    ];
                bh[jn][1] = *(const unsigned*)&Bh[n * PAD + cb + 8];
                bl[jn][0] = *(const unsigned*)&Bl[n * PAD + cb    ];
                bl[jn][1] = *(const unsigned*)&Bl[n * PAD + cb + 8];
            }
            #pragma unroll
            for (int im = 0; im < 2; im++)
                #pragma unroll
                for (int jn = 0; jn < 4; jn++) {
                    float* cc = acc[im][jn];
                    asm volatile(
                        "mma.sync.aligned.m16n8k16.row.col.f32.bf16.bf16.f32 "
                        "{%0,%1,%2,%3}, {%4,%5,%6,%7}, {%8,%9}, {%0,%1,%2,%3};"
                        : "+f"(cc[0]), "+f"(cc[1]), "+f"(cc[2]), "+f"(cc[3])
                        : "r"(ah[im][0]), "r"(ah[im][1]), "r"(ah[im][2]), "r"(ah[im][3]),
                          "r"(bh[jn][0]), "r"(bh[jn][1]));
                    asm volatile(
                        "mma.sync.aligned.m16n8k16.row.col.f32.bf16.bf16.f32 "
                        "{%0,%1,%2,%3}, {%4,%5,%6,%7}, {%8,%9}, {%0,%1,%2,%3};"
                        : "+f"(cc[0]), "+f"(cc[1]), "+f"(cc[2]), "+f"(cc[3])
                        : "r"(ah[im][0]), "r"(ah[im][1]), "r"(ah[im][2]), "r"(ah[im][3]),
                          "r"(bl[jn][0]), "r"(bl[jn][1]));
                    asm volatile(
                        "mma.sync.aligned.m16n8k16.row.col.f32.bf16.bf16.f32 "
                        "{%0,%1,%2,%3}, {%4,%5,%6,%7}, {%8,%9}, {%0,%1,%2,%3};"
                        : "+f"(cc[0]), "+f"(cc[1]), "+f"(cc[2]), "+f"(cc[3])
                        : "r"(al[im][0]), "r"(al[im][1]), "r"(al[im][2]), "r"(al[im][3]),
                          "r"(bh[jn][0]), "r"(bh[jn][1]));
                }
        }
        __syncthreads();
    }

    #pragma unroll
    for (int im = 0; im < 2; im++) {
        int mb = m0 + wm * 32 + im * 16 + lq;
        #pragma unroll
        for (int jn = 0; jn < 4; jn++) {
            int nb = n0 + wn * 32 + jn * 8 + lr * 2;
            float b0 = 0.f, b1 = 0.f;
            if (bias && ks == 0) {
                if (nb     < N) b0 = bias[nb];
                if (nb + 1 < N) b1 = bias[nb + 1];
            }
            float* cc = acc[im][jn];
            #pragma unroll
            for (int half = 0; half < 2; half++) {
                int m = mb + half * 8;
                if (m >= M) continue;
                if (nb < N) {
                    float r = (cc[half*2] + b0) * alpha;
                    float* p = Cp + (ll)m * crs + (ll)nb * ccs;
                    if (ksplit == 1) *p = r; else atomicAdd(p, r);
                }
                if (nb + 1 < N) {
                    float r = (cc[half*2 + 1] + b1) * alpha;
                    float* p = Cp + (ll)m * crs + (ll)(nb + 1) * ccs;
                    if (ksplit == 1) *p = r; else atomicAdd(p, r);
                }
            }
        }
    }
}

/* ---------------- cosine scales per (b,r) --------------------------------- */
__global__ void scales_kernel(const float* __restrict__ z, const float* __restrict__ clt,
                              const float* __restrict__ p1, const float* __restrict__ p2,
                              float* __restrict__ s1o, float* __restrict__ s2o) {
    __shared__ float p1s[NC_], p2s[NC_], pn[2];
    int b = blockIdx.y;
    int r = blockIdx.x * 128 + threadIdx.x;
    int tid = threadIdx.x;
    for (int i = tid; i < NC_; i += 128) { p1s[i] = p1[i]; p2s[i] = p2[i]; }
    if (tid < 2) {
        const float* p = tid ? p2 : p1;
        float s = 0.f;
        for (int k = 0; k < NC_; k++) s += p[k]*p[k];
        pn[tid] = 1.0f / fmaxf(sqrtf(s), 1e-12f);
    }
    __syncthreads();
    const float* zb = z   + (ll)b * NC_ * R_ + r;
    const float* cb = clt + (ll)b * NC_ * R_ + r;
    float zz = 0.f, zp = 0.f, cc = 0.f, cp = 0.f;
    #pragma unroll 2
    for (int j = 0; j < NC_; j++) {
        float zv = zb[(ll)j * R_];
        float cv = cb[(ll)j * R_];
        zz += zv*zv; zp += zv*p1s[j];
        cc += cv*cv; cp += cv*p2s[j];
    }
    float s1 = zp * pn[0] / fmaxf(sqrtf(zz), 1e-12f);
    float s2 = cp * pn[1] / fmaxf(sqrtf(cc), 1e-12f);
    s1o[(ll)b*R_ + r] = fminf(fmaxf(s1, 0.f), 1.f);
    s2o[(ll)b*R_ + r] = fminf(fmaxf(s2, 0.f), 1.f);
}

/* ---------------- softmax: asn copy + soft bf16 hi/lo --------------------- */
__global__ void softmax_rows2(const float* __restrict__ cxz,
                              float* __restrict__ asn,
                              bf16* __restrict__ sfh, bf16* __restrict__ sfl) {
    int row = blockIdx.x;
    int b = row / 600; int rem = row - b * 600;
    int t = rem / NC_; int k = rem - t * NC_;
    const float* s = cxz + ((ll)(b * NC_ + k)) * R_ + (ll)t * N_;
    ll drow = ((ll)((b * T_ + t) * NC_ + k)) * N_;
    __shared__ float sh[8];
    int tid = threadIdx.x;
    float mx = -1e30f;
    for (int i = tid; i < N_; i += 256) mx = fmaxf(mx, s[i]);
    #pragma unroll
    for (int o = 16; o; o >>= 1) mx = fmaxf(mx, __shfl_xor_sync(0xffffffffu, mx, o));
    if ((tid & 31) == 0) sh[tid >> 5] = mx;
    __syncthreads();
    mx = fmaxf(fmaxf(fmaxf(sh[0],sh[1]),fmaxf(sh[2],sh[3])),
               fmaxf(fmaxf(sh[4],sh[5]),fmaxf(sh[6],sh[7])));
    __syncthreads();
    float sum = 0.f;
    for (int i = tid; i < N_; i += 256) sum += expf(s[i] - mx);
    sum = blockSum256(sum, sh);
    float inv = 1.0f / sum;
    for (int i = tid; i < N_; i += 256) {
        float v = s[i];
        asn[drow + i] = v;
        split_store(expf(v - mx) * inv, sfh, sfl, drow + i);
    }
}

/* ---------------- gate + LayerNorm --------------------------------------- */
__global__ void gate_ln_kernel(const float* __restrict__ cen,
                               const float* __restrict__ nw, const float* __restrict__ nb,
                               const float* __restrict__ salpha, const float* __restrict__ sbeta,
                               float* __restrict__ cin_out) {
    int k = blockIdx.x, b = blockIdx.y, c = threadIdx.x;
    __shared__ float sh[8];
    float pv[4];
    #pragma unroll
    for (int t = 0; t < 4; t++)
        pv[t] = cen[(((ll)b*4 + t) * NC_ + k) * C_ + c];
    float last = pv[3];
    float ll2 = blockSum256(last*last, sh);
    float cin = last;
    float alpha = salpha[0], beta = sbeta[0];
    for (int t = 0; t < 3; t++) {
        float dt = blockSum256(last * pv[t], sh);
        float pp = blockSum256(pv[t] * pv[t], sh);
        float denom = fmaxf(sqrtf(ll2) * sqrtf(pp), 1e-8f);
        float gate = 1.0f / (1.0f + expf(-(beta + alpha * (dt / denom))));
        cin += gate * pv[t];
    }
    float m  = blockSum256(cin, sh) * (1.0f / C_);
    float dv = cin - m;
    float var = blockSum256(dv*dv, sh) * (1.0f / C_);
    cin_out[((ll)b*NC_ + k) * C_ + c] = dv * rsqrtf(var + 1e-5f) * nw[c] + nb[c];
}

/* ---------------- K/V projections ---------------------------------------- */
__global__ void kv_kernel(const float* __restrict__ cin,
                          const float* __restrict__ kw, const float* __restrict__ kb,
                          const float* __restrict__ vw, const float* __restrict__ vb,
                          float* __restrict__ ko, float* __restrict__ vo) {
    int row = blockIdx.x, c = threadIdx.x;
    __shared__ float ci[C_];
    ci[c] = cin[(ll)row * C_ + c];
    __syncthreads();
    float ka = kb[c], va = vb[c];
    const float* kwr = kw + (ll)c * C_;
    const float* vwr = vw + (ll)c * C_;
    #pragma unroll 4
    for (int j = 0; j < C_; j++) {
        float cv = ci[j];
        ka += cv * kwr[j];
        va += cv * vwr[j];
    }
    ko[(ll)row * C_ + c] = ka;
    vo[(ll)row * C_ + c] = va;
}

/* ---------------- fused attention -> bf16 hi/lo output -------------------- */
__global__ void attn_kernel(const float* __restrict__ q, const float* __restrict__ ks,
                            const float* __restrict__ vs,
                            bf16* __restrict__ oh, bf16* __restrict__ ol) {
    const int b = blockIdx.y;
    const int n0 = blockIdx.x * 8;
    __shared__ float qs[8][C_];
    __shared__ float P[8][8][152];
    int tid = threadIdx.x;
    for (int i = tid; i < 8*C_; i += 256)
        qs[i >> 8][i & 255] = q[((ll)b*N_ + n0 + (i >> 8)) * C_ + (i & 255)];
    __syncthreads();
    int h = tid >> 5, lane = tid & 31;
    float lg[8][5];
    #pragma unroll
    for (int g = 0; g < 8; g++)
        #pragma unroll
        for (int s = 0; s < 5; s++) lg[g][s] = -1e30f;
    #pragma unroll
    for (int s = 0; s < 5; s++) {
        int idx = lane + s*32;
        if (idx < NC_) {
            const float4* kp = reinterpret_cast<const float4*>(ks + ((ll)b*NC_ + idx)*C_ + h*32);
            float4 kk[8];
            #pragma unroll
            for (int u = 0; u < 8; u++) kk[u] = kp[u];
            #pragma unroll
            for (int g = 0; g < 8; g++) {
                const float* qb = &qs[g][h*32];
                float d = 0.f;
                #pragma unroll
                for (int u = 0; u < 8; u++)
                    d += kk[u].x*qb[u*4] + kk[u].y*qb[u*4+1] + kk[u].z*qb[u*4+2] + kk[u].w*qb[u*4+3];
                lg[g][s] = d;
            }
        }
    }
    float invg[8];
    #pragma unroll
    for (int g = 0; g < 8; g++) {
        float mx = -1e30f;
        #pragma unroll
        for (int s = 0; s < 5; s++) mx = fmaxf(mx, lg[g][s]);
        #pragma unroll
        for (int o2 = 16; o2; o2 >>= 1) mx = fmaxf(mx, __shfl_xor_sync(0xffffffffu, mx, o2));
        float sum = 0.f;
        #pragma unroll
        for (int s = 0; s < 5; s++) {
            int idx = lane + s*32;
            if (idx < NC_) {
                float e = expf(lg[g][s] - mx);
                P[h][g][idx] = e;
                sum += e;
            }
        }
        #pragma unroll
        for (int o2 = 16; o2; o2 >>= 1) sum += __shfl_xor_sync(0xffffffffu, sum, o2);
        invg[g] = 1.0f / sum;
    }
    __syncwarp();
    float og[8] = {0.f,0.f,0.f,0.f,0.f,0.f,0.f,0.f};
    for (int j = 0; j < NC_; j++) {
        float vv = vs[((ll)b*NC_ + j) * C_ + h*32 + lane];
        #pragma unroll
        for (int g = 0; g < 8; g++) og[g] += P[h][g][j] * vv;
    }
    #pragma unroll
    for (int g = 0; g < 8; g++) {
        float v = og[g] * invg[g];
        split_store(v, oh, ol, ((ll)b*N_ + n0 + g) * C_ + h*32 + lane);
    }
}

/* ---------------- depthwise 3x3 conv + GELU -> bf16 hi/lo ----------------- */
__global__ void conv_gelu2(const float* __restrict__ h,
                           const float* __restrict__ dww, const float* __restrict__ dwb,
                           bf16* __restrict__ oh, bf16* __restrict__ ol) {
    __shared__ float patch[10][10][64];
    int ch0 = blockIdx.x * 64;
    int tileid = blockIdx.y;
    int y0 = (tileid >> 3) * 8, x0 = (tileid & 7) * 8;
    int b = blockIdx.z;
    int tid = threadIdx.x;
    for (int i = tid; i < 6400; i += 256) {
        int c = i & 63, sp = i >> 6;
        int py = sp / 10, px = sp % 10;
        int yy = y0 + py - 1, xx = x0 + px - 1;
        float v = 0.f;
        if (yy >= 0 && yy < 64 && xx >= 0 && xx < 64)
            v = h[(((ll)b*N_) + (yy*64 + xx)) * HID_ + ch0 + c];
        patch[py][px][c] = v;
    }
    __syncthreads();
    int c = tid & 63, sub = tid >> 6;
    float w[9];
    #pragma unroll
    for (int i = 0; i < 9; i++) w[i] = dww[(ch0 + c)*9 + i];
    float bv = dwb[ch0 + c];
    for (int oy = sub; oy < 8; oy += 4) {
        #pragma unroll
        for (int ox = 0; ox < 8; ox++) {
            float a = bv;
            #pragma unroll
            for (int dy = 0; dy < 3; dy++)
                #pragma unroll
                for (int dx = 0; dx < 3; dx++)
                    a += patch[oy+dy][ox+dx][c] * w[dy*3+dx];
            float g = 0.5f * a * (1.0f + erff(a * 0.7071067811865475f));
            split_store(g, oh, ol, (((ll)b*N_) + ((y0+oy)*64 + x0+ox)) * HID_ + ch0 + c);
        }
    }
}

/* ---------------- residual + LayerNorm (optional bf16 dual-write) ---------- */
__global__ void add_ln_kernel(const float* __restrict__ res, const float* __restrict__ val,
                              const float* __restrict__ nw, const float* __restrict__ nb,
                              float* __restrict__ dst,
                              bf16* __restrict__ dh, bf16* __restrict__ dl) {
    ll row = blockIdx.x;
    int c = threadIdx.x;
    __shared__ float sh[8];
    float v = val[row * C_ + c];
    float m = blockSum256(v, sh) * (1.0f / C_);
    float d = v - m;
    float var = blockSum256(d*d, sh) * (1.0f / C_);
    float r = res[row * C_ + c] + d * rsqrtf(var + 1e-5f) * nw[c] + nb[c];
    dst[row * C_ + c] = r;
    if (dh) split_store(r, dh, dl, row * C_ + c);
}

/* ---------------- host launch --------------------------------------------- */
static float* symaddr(const void* sym) {
    void* p = nullptr;
    cudaGetSymbolAddress(&p, sym);
    return (float*)p;
}
static bf16* symaddrb(const void* sym) {
    void* p = nullptr;
    cudaGetSymbolAddress(&p, sym);
    return (bf16*)p;
}

extern "C" void kernel_launch(void* const* d_in, const int* in_sizes, int n_in,
                              void* d_out, int out_size) {
    const float* x    = (const float*)d_in[0];
    const float* z    = (const float*)d_in[1];
    const float* mem  = (const float*)d_in[2];
    const float* cw   = (const float*)d_in[3];
    const float* p1   = (const float*)d_in[4];
    const float* t1   = (const float*)d_in[5];
    const float* p2   = (const float*)d_in[6];
    const float* t2   = (const float*)d_in[7];
    const float* sal  = (const float*)d_in[8];
    const float* sbe  = (const float*)d_in[9];
    const float* qw   = (const float*)d_in[10];
    const float* qb   = (const float*)d_in[11];
    const float* kw   = (const float*)d_in[12];
    const float* kb   = (const float*)d_in[13];
    const float* vw   = (const float*)d_in[14];
    const float* vb   = (const float*)d_in[15];
    const float* pw   = (const float*)d_in[16];
    const float* pb   = (const float*)d_in[17];
    const float* nw   = (const float*)d_in[18];
    const float* nb   = (const float*)d_in[19];
    const float* f1w  = (const float*)d_in[20];
    const float* f1b  = (const float*)d_in[21];
    const float* dww  = (const float*)d_in[22];
    const float* dwb  = (const float*)d_in[23];
    const float* f2w  = (const float*)d_in[24];
    const float* f2b  = (const float*)d_in[25];

    float* out_main = (float*)d_out;
    float* out_cxz  = out_main + (ll)B_*N_*C_;
    float* out_asn  = out_cxz  + (ll)B_*NC_*R_;

    float* xf   = symaddr(g_xf);
    float* clt  = symaddr(g_clt);
    float* s1   = symaddr(g_s1);
    float* s2   = symaddr(g_s2);
    float* cen  = symaddr(g_cen);
    float* cin  = symaddr(g_cin);
    float* ksc  = symaddr(g_k);
    float* vsc  = symaddr(g_v);
    float* qsc  = symaddr(g_q);
    float* tmp  = symaddr(g_tmp);
    float* out1 = symaddr(g_out1);
    float* h1   = symaddr(g_h1);

    bf16 *xf_h = symaddrb(g_xf_h), *xf_l = symaddrb(g_xf_l);
    bf16 *xT_h = symaddrb(g_xfT_h),*xT_l = symaddrb(g_xfT_l);
    bf16 *S_h  = symaddrb(g_S_h),  *S_l  = symaddrb(g_S_l);
    bf16 *tc_h = symaddrb(g_tc_h), *tc_l = symaddrb(g_tc_l);
    bf16 *sf_h = symaddrb(g_sf_h), *sf_l = symaddrb(g_sf_l);
    bf16 *x_h  = symaddrb(g_x_h),  *x_l  = symaddrb(g_x_l);
    bf16 *at_h = symaddrb(g_atn_h),*at_l = symaddrb(g_atn_l);
    bf16 *o1_h = symaddrb(g_o1_h), *o1_l = symaddrb(g_o1_l);
    bf16 *hg_h = symaddrb(g_hg_h), *hg_l = symaddrb(g_hg_l);
    bf16 *cw_h = symaddrb(g_cw_h), *cw_l = symaddrb(g_cw_l);
    bf16 *qw_h = symaddrb(g_qw_h), *qw_l = symaddrb(g_qw_l);
    bf16 *pw_h = symaddrb(g_pw_h), *pw_l = symaddrb(g_pw_l);
    bf16 *f1_h = symaddrb(g_f1_h), *f1_l = symaddrb(g_f1_l);
    bf16 *f2_h = symaddrb(g_f2_h), *f2_l = symaddrb(g_f2_l);

    /* 0. weight + x conversions, tcat */
    cvt_split<<<(NC_*C_/4 + 255)/256, 256>>>((const float4*)cw, cw_h, cw_l, NC_*C_/4);
    cvt_split<<<(C_*C_/4 + 255)/256, 256>>>((const float4*)qw, qw_h, qw_l, C_*C_/4);
    cvt_split<<<(C_*C_/4 + 255)/256, 256>>>((const float4*)pw, pw_h, pw_l, C_*C_/4);
    cvt_split<<<(HID_*C_/4 + 255)/256, 256>>>((const float4*)f1w, f1_h, f1_l, HID_*C_/4);
    cvt_split<<<(HID_*C_/4 + 255)/256, 256>>>((const float4*)f2w, f2_h, f2_l, HID_*C_/4);
    cvt_split<<<(B_*N_*C_/4 + 255)/256, 256>>>((const float4*)x, x_h, x_l, B_*N_*C_/4);
    build_tcat<<<(NC_*KS_ + 255)/256, 256>>>(t1, t2, tc_h, tc_l);

    /* 1. xf = concat(mem, x) + bf16 split; xfT for cen */
    copy_xf_kernel<<<8192, 256>>>((const float4*)x, (const float4*)mem,
                                  (float4*)xf, xf_h, xf_l);
    build_xfT<<<dim3(N_/64, C_/32, B_*T_), 256>>>(xf, xT_h, xT_l);

    /* 2. clt (MMA, transposed store) */
    gemm_mma2<<<dim3(R_/128, 3, B_), 256>>>(
        R_, NC_, C_, xf_h, xf_l, C_, (ll)R_*C_, cw_h, cw_l, C_, 0,
        clt, 1, R_, (ll)NC_*R_, nullptr, 1.0f, 1);

    /* 3. cosine scales + scaled/split S */
    scales_kernel<<<dim3(R_/128, B_), 128>>>(z, clt, p1, p2, s1, s2);
    build_S<<<dim3(R_/64, B_), 256>>>(z, clt, s1, s2, S_h, S_l);

    /* 4. cluster_x_z (MMA: M=R, N=150, K=320, transposed store) */
    gemm_mma2<<<dim3(R_/128, 3, B_), 256>>>(
        R_, NC_, KS_, S_h, S_l, KS_, (ll)R_*KS_, tc_h, tc_l, KS_, 0,
        out_cxz, 1, R_, (ll)NC_*R_, nullptr, 0.5f, 1);

    /* 5. softmax: asn copy + soft bf16 */
    softmax_rows2<<<B_*T_*NC_, 256>>>(out_cxz, out_asn, sf_h, sf_l);

    /* 6. cen = soft @ xf (MMA, split-K=8 atomic, M=150 guarded) */
    zero_kernel<<<(B_*T_*NC_*C_ + 255)/256, 256>>>(cen, B_*T_*NC_*C_);
    gemm_mma2<<<dim3(2, 4, B_*T_*8), 256>>>(
        NC_, C_, N_, sf_h, sf_l, N_, (ll)NC_*N_, xT_h, xT_l, N_, (ll)C_*N_,
        cen, C_, 1, (ll)NC_*C_, nullptr, 1.0f, 8);

    /* 7. gate + LN */
    gate_ln_kernel<<<dim3(NC_, B_), 256>>>(cen, nw, nb, sal, sbe, cin);

    /* 8. k,v */
    kv_kernel<<<B_*NC_, 256>>>(cin, kw, kb, vw, vb, ksc, vsc);

    /* 9. q (MMA) */
    gemm_mma2<<<dim3(64, 4, 1), 256>>>(
        B_*N_, C_, C_, x_h, x_l, C_, 0, qw_h, qw_l, C_, 0,
        qsc, C_, 1, 0, qb, 0.17677669529663687f, 1);

    /* 10. attention -> bf16 */
    attn_kernel<<<dim3(N_/8, B_), 256>>>(qsc, ksc, vsc, at_h, at_l);

    /* 11. proj (MMA) */
    gemm_mma2<<<dim3(64, 4, 1), 256>>>(
        B_*N_, C_, C_, at_h, at_l, C_, 0, pw_h, pw_l, C_, 0,
        tmp, C_, 1, 0, pb, 1.0f, 1);

    /* 12. out1 = x + LN(proj), dual-write */
    add_ln_kernel<<<B_*N_, 256>>>(x, tmp, nw, nb, out1, o1_h, o1_l);

    /* 13. fc1 (MMA) */
    gemm_mma2<<<dim3(64, 16, 1), 256>>>(
        B_*N_, HID_, C_, o1_h, o1_l, C_, 0, f1_h, f1_l, C_, 0,
        h1, HID_, 1, 0, f1b, 1.0f, 1);

    /* 14. depthwise conv + GELU -> bf16 */
    conv_gelu2<<<dim3(HID_/64, 64, B_), 256>>>(h1, dww, dwb, hg_h, hg_l);

    /* 15. fc2 (MMA, K=1024) */
    gemm_mma2<<<dim3(64, 4, 1), 256>>>(
        B_*N_, C_, HID_, hg_h, hg_l, HID_, 0, f2_h, f2_l, HID_, 0,
        tmp, C_, 1, 0, f2b, 1.0f, 1);

    /* 16. out = out1 + LN(fc2) */
    add_ln_kernel<<<B_*N_, 256>>>(out1, tmp, nw, nb, out_main, nullptr, nullptr);
}

// round 11
// speedup vs baseline: 1.8641x; 1.1252x over previous
#include <cuda_runtime.h>
#include <cuda_bf16.h>
#include <math.h>

#define B_   2
#define N_   4096
#define C_   256
#define NC_  150
#define T_   4
#define HID_ 1024
#define R_   16384   /* T_*N_ */
#define KS_  320     /* padded 2*NC_ for cxz MMA */

typedef long long ll;
typedef __nv_bfloat16 bf16;

/* ---------------- scratch (device globals) ------------------------------- */
__device__ float g_xf  [B_*T_*N_*C_];
__device__ float g_clt [B_*NC_*R_];
__device__ float g_s1  [B_*R_];
__device__ float g_s2  [B_*R_];
__device__ float g_cen [B_*T_*NC_*C_];
__device__ float g_cin [B_*NC_*C_];
__device__ float g_k   [B_*NC_*C_];
__device__ float g_v   [B_*NC_*C_];
__device__ float g_q   [B_*N_*C_];
__device__ float g_tmp [B_*N_*C_];
__device__ float g_out1[B_*N_*C_];
__device__ float g_h1  [B_*N_*HID_];

/* bf16 hi/lo operand buffers — 16B aligned (float4 / cp.async reads) */
__device__ __align__(16) bf16 g_xf_h [B_*T_*N_*C_];
__device__ __align__(16) bf16 g_xf_l [B_*T_*N_*C_];
__device__ __align__(16) bf16 g_xfT_h[B_*T_*C_*N_];
__device__ __align__(16) bf16 g_xfT_l[B_*T_*C_*N_];
__device__ __align__(16) bf16 g_S_h  [B_*R_*KS_];
__device__ __align__(16) bf16 g_S_l  [B_*R_*KS_];
__device__ __align__(16) bf16 g_tc_h [NC_*KS_];
__device__ __align__(16) bf16 g_tc_l [NC_*KS_];
__device__ __align__(16) bf16 g_sf_h [B_*T_*NC_*N_];
__device__ __align__(16) bf16 g_sf_l [B_*T_*NC_*N_];
__device__ __align__(16) bf16 g_x_h  [B_*N_*C_];
__device__ __align__(16) bf16 g_x_l  [B_*N_*C_];
__device__ __align__(16) bf16 g_atn_h[B_*N_*C_];
__device__ __align__(16) bf16 g_atn_l[B_*N_*C_];
__device__ __align__(16) bf16 g_o1_h [B_*N_*C_];
__device__ __align__(16) bf16 g_o1_l [B_*N_*C_];
__device__ __align__(16) bf16 g_hg_h [B_*N_*HID_];
__device__ __align__(16) bf16 g_hg_l [B_*N_*HID_];
__device__ __align__(16) bf16 g_cw_h [NC_*C_];
__device__ __align__(16) bf16 g_cw_l [NC_*C_];
__device__ __align__(16) bf16 g_qw_h [C_*C_];
__device__ __align__(16) bf16 g_qw_l [C_*C_];
__device__ __align__(16) bf16 g_pw_h [C_*C_];
__device__ __align__(16) bf16 g_pw_l [C_*C_];
__device__ __align__(16) bf16 g_f1_h [HID_*C_];
__device__ __align__(16) bf16 g_f1_l [HID_*C_];
__device__ __align__(16) bf16 g_f2_h [C_*HID_];
__device__ __align__(16) bf16 g_f2_l [C_*HID_];

__device__ __forceinline__ float blockSum256(float v, float* sh) {
    #pragma unroll
    for (int o = 16; o; o >>= 1) v += __shfl_xor_sync(0xffffffffu, v, o);
    if ((threadIdx.x & 31) == 0) sh[threadIdx.x >> 5] = v;
    __syncthreads();
    float r = sh[0]+sh[1]+sh[2]+sh[3]+sh[4]+sh[5]+sh[6]+sh[7];
    __syncthreads();
    return r;
}

__device__ __forceinline__ void split_store(float v, bf16* h, bf16* l, ll idx) {
    bf16 hh = __float2bfloat16(v);
    h[idx] = hh;
    l[idx] = __float2bfloat16(v - __bfloat162float(hh));
}
__device__ __forceinline__ void split_pair(float v, bf16& h, bf16& l) {
    h = __float2bfloat16(v);
    l = __float2bfloat16(v - __bfloat162float(h));
}

/* ---------------- cp.async helpers ---------------------------------------- */
__device__ __forceinline__ void cp16(unsigned dst, const void* src, bool pred) {
    int sz = pred ? 16 : 0;
    asm volatile("cp.async.ca.shared.global [%0], [%1], 16, %2;"
                 :: "r"(dst), "l"(src), "r"(sz));
}
__device__ __forceinline__ void cp_commit() {
    asm volatile("cp.async.commit_group;");
}
__device__ __forceinline__ void cp_wait0() {
    asm volatile("cp.async.wait_group 0;");
}

__global__ void zero_kernel(float* p, int n) {
    int i = blockIdx.x * 256 + threadIdx.x;
    if (i < n) p[i] = 0.f;
}

/* ---------------- fused fp32 -> bf16 hi/lo split (6 segments) -------------- */
struct CvtJob { const float4* s; bf16* h; bf16* l; int n4; };
__global__ void cvt_multi(CvtJob j0, CvtJob j1, CvtJob j2,
                          CvtJob j3, CvtJob j4, CvtJob j5) {
    CvtJob j;
    switch (blockIdx.y) {
        case 0: j = j0; break;
        case 1: j = j1; break;
        case 2: j = j2; break;
        case 3: j = j3; break;
        case 4: j = j4; break;
        default: j = j5; break;
    }
    int i = blockIdx.x * 256 + threadIdx.x;
    if (i >= j.n4) return;
    float4 v = j.s[i];
    float vv[4] = {v.x, v.y, v.z, v.w};
    #pragma unroll
    for (int u = 0; u < 4; u++) split_store(vv[u], j.h, j.l, (ll)i*4 + u);
}

/* ---------------- tcat hi/lo ----------------------------------------------- */
__global__ void build_tcat(const float* __restrict__ t1, const float* __restrict__ t2,
                           bf16* __restrict__ th, bf16* __restrict__ tl) {
    int idx = blockIdx.x * 256 + threadIdx.x;
    if (idx >= NC_ * KS_) return;
    int kp = idx / KS_, j = idx % KS_;
    float v = 0.f;
    if (j < NC_)        v = t1[j * NC_ + kp];
    else if (j < 2*NC_) v = t2[(j - NC_) * NC_ + kp];
    split_store(v, th, tl, idx);
}

/* ---------------- xf = concat(mem, x) + bf16 split ------------------------- */
__global__ void copy_xf_kernel(const float4* __restrict__ x,
                               const float4* __restrict__ mem,
                               float4* __restrict__ xf,
                               bf16* __restrict__ xh, bf16* __restrict__ xl) {
    ll i = (ll)blockIdx.x * 256 + threadIdx.x;
    int b  = (int)(i >> 20);
    int rem = (int)(i & 1048575);
    int tt = rem >> 18;
    int rc = rem & 262143;
    float4 v;
    if (tt < 3) v = mem[((ll)(b*3 + tt) << 18) + rc];
    else        v = x[((ll)b << 18) + rc];
    xf[i] = v;
    float vv[4] = {v.x, v.y, v.z, v.w};
    #pragma unroll
    for (int u = 0; u < 4; u++) split_store(vv[u], xh, xl, i*4 + u);
}

/* ---------------- xfT hi/lo: xfT[bt][c][n] (smem transpose) ---------------- */
__global__ void build_xfT(const float* __restrict__ xf,
                          bf16* __restrict__ oh, bf16* __restrict__ olo) {
    __shared__ float tile[32][65];
    int bt = blockIdx.z;
    int n0 = blockIdx.x * 64, c0 = blockIdx.y * 32;
    int tid = threadIdx.x;
    for (int i = tid; i < 32 * 64; i += 256) {
        int cl = i & 31, nl = i >> 5;
        tile[cl][nl] = xf[((ll)bt * N_ + n0 + nl) * C_ + c0 + cl];
    }
    __syncthreads();
    int cl = tid >> 3, nseg = (tid & 7) * 8;
    __align__(16) bf16 hb[8], lb[8];
    #pragma unroll
    for (int u = 0; u < 8; u++) split_pair(tile[cl][nseg + u], hb[u], lb[u]);
    ll off = ((ll)bt * C_ + c0 + cl) * N_ + n0 + nseg;
    *(uint4*)&oh [off] = *(const uint4*)hb;
    *(uint4*)&olo[off] = *(const uint4*)lb;
}

/* ---------------- S hi/lo: S[b][r][j] = scaled z/clt (smem transpose) ------ */
__global__ void build_S(const float* __restrict__ z, const float* __restrict__ clt,
                        const float* __restrict__ s1, const float* __restrict__ s2,
                        bf16* __restrict__ sh_, bf16* __restrict__ sl_) {
    __shared__ float tile[32][65];
    __shared__ float s1s[64], s2s[64];
    int b = blockIdx.y;
    int r0 = blockIdx.x * 64;
    int tid = threadIdx.x;
    if (tid < 64) {
        s1s[tid] = s1[(ll)b * R_ + r0 + tid];
        s2s[tid] = s2[(ll)b * R_ + r0 + tid];
    }
    __syncthreads();
    for (int jc = 0; jc < KS_ / 32; jc++) {
        int j0 = jc * 32;
        for (int i = tid; i < 32 * 64; i += 256) {
            int rl = i & 63, jl = i >> 6;
            int j = j0 + jl;
            float v = 0.f;
            if (j < NC_)        v = z  [((ll)b * NC_ + j)        * R_ + r0 + rl] * s1s[rl];
            else if (j < 2*NC_) v = clt[((ll)b * NC_ + (j-NC_))  * R_ + r0 + rl] * s2s[rl];
            tile[jl][rl] = v;
        }
        __syncthreads();
        int rl = tid >> 2, jseg = (tid & 3) * 8;
        __align__(16) bf16 hb[8], lb[8];
        #pragma unroll
        for (int u = 0; u < 8; u++) split_pair(tile[jseg + u][rl], hb[u], lb[u]);
        ll off = ((ll)b * R_ + r0 + rl) * KS_ + j0 + jseg;
        *(uint4*)&sh_[off] = *(const uint4*)hb;
        *(uint4*)&sl_[off] = *(const uint4*)lb;
        __syncthreads();
    }
}

/* ---------------- pipelined pre-split bf16 tensor-core GEMM ----------------
 * C = alpha*(A·W^T + bias), fp32-accurate via Ah·Wh + Ah·Wl + Al·Wh.
 * BM=128 BN=64 BK=32, 256 thr, 2-stage cp.async double buffering.
 * M-guarded; optional split-K (atomicAdd). (K/ksplit)%32==0.              */
__global__ void gemm_mma2(int M, int N, int K,
                          const bf16* __restrict__ Ah_, const bf16* __restrict__ Al_,
                          int lda, ll bsA,
                          const bf16* __restrict__ Wh_, const bf16* __restrict__ Wl_,
                          int ldw, ll bsW,
                          float* __restrict__ Cp, ll crs, ll ccs, ll bsC,
                          const float* __restrict__ bias, float alpha, int ksplit) {
    constexpr int BM = 128, BN = 64, BK = 32, PAD = 40;
    constexpr int ASZ = BM * PAD, BSZ = BN * PAD;
    __shared__ __align__(16) bf16 Ah[2*ASZ], Al[2*ASZ];
    __shared__ __align__(16) bf16 Bh[2*BSZ], Bl[2*BSZ];
    int zz = blockIdx.z, bt = zz / ksplit, ks = zz - bt * ksplit;
    Ah_ += (ll)bt * bsA;  Al_ += (ll)bt * bsA;
    Wh_ += (ll)bt * bsW;  Wl_ += (ll)bt * bsW;
    Cp  += (ll)bt * bsC;
    int Kc = K / ksplit;
    int kbeg = ks * Kc;
    int niter = Kc / BK;
    int m0 = blockIdx.x * BM, n0 = blockIdx.y * BN;
    int tid = threadIdx.x;
    int wid = tid >> 5, lane = tid & 31;
    int wm = wid >> 1, wn = wid & 1;
    int lq = lane >> 2, lr = lane & 3;

    unsigned sAh = (unsigned)__cvta_generic_to_shared(Ah);
    unsigned sAl = (unsigned)__cvta_generic_to_shared(Al);
    unsigned sBh = (unsigned)__cvta_generic_to_shared(Bh);
    unsigned sBl = (unsigned)__cvta_generic_to_shared(Bl);

    /* precomputed per-thread load coordinates */
    int arow0 = tid >> 2, aq0 = tid & 3;          /* slot 0: rows 0..63   */
    int arow1 = arow0 + 64;                        /* slot 1: rows 64..127 */
    int brow = tid >> 2, bq = tid & 3;
    bool am0 = (m0 + arow0) < M, am1 = (m0 + arow1) < M;
    bool bn  = (n0 + brow) < N;

    auto load_stage = [&](int k0, int st) {
        {
            ll g = (ll)(m0 + arow0) * lda + k0 + aq0 * 8;
            unsigned d = (st*ASZ + arow0 * PAD + aq0 * 8) * 2;
            cp16(sAh + d, Ah_ + g, am0);
            cp16(sAl + d, Al_ + g, am0);
        }
        {
            ll g = (ll)(m0 + arow1) * lda + k0 + aq0 * 8;
            unsigned d = (st*ASZ + arow1 * PAD + aq0 * 8) * 2;
            cp16(sAh + d, Ah_ + g, am1);
            cp16(sAl + d, Al_ + g, am1);
        }
        {
            ll g = (ll)(n0 + brow) * ldw + k0 + bq * 8;
            unsigned d = (st*BSZ + brow * PAD + bq * 8) * 2;
            cp16(sBh + d, Wh_ + g, bn);
            cp16(sBl + d, Wl_ + g, bn);
        }
        cp_commit();
    };

    float acc[2][4][4];
    #pragma unroll
    for (int im = 0; im < 2; im++)
        #pragma unroll
        for (int jn = 0; jn < 4; jn++)
            #pragma unroll
            for (int c = 0; c < 4; c++) acc[im][jn][c] = 0.f;

    load_stage(kbeg, 0);

    for (int it = 0; it < niter; it++) {
        cp_wait0();
        __syncthreads();
        if (it + 1 < niter) load_stage(kbeg + (it + 1) * BK, (it + 1) & 1);
        int st = it & 1;
        const bf16* cAh = Ah + st * ASZ;
        const bf16* cAl = Al + st * ASZ;
        const bf16* cBh = Bh + st * BSZ;
        const bf16* cBl = Bl + st * BSZ;

        #pragma unroll
        for (int kc = 0; kc < 2; kc++) {
            int cb = kc * 16 + lr * 2;
            unsigned ah[2][4], al[2][4], bh[4][2], bl[4][2];
            #pragma unroll
            for (int im = 0; im < 2; im++) {
                int r = wm * 32 + im * 16 + lq;
                ah[im][0] = *(const unsigned*)&cAh[ r      * PAD + cb    ];
                ah[im][1] = *(const unsigned*)&cAh[(r + 8) * PAD + cb    ];
                ah[im][2] = *(const unsigned*)&cAh[ r      * PAD + cb + 8];
                ah[im][3] = *(const unsigned*)&cAh[(r + 8) * PAD + cb + 8];
                al[im][0] = *(const unsigned*)&cAl[ r      * PAD + cb    ];
                al[im][1] = *(const unsigned*)&cAl[(r + 8) * PAD + cb    ];
                al[im][2] = *(const unsigned*)&cAl[ r      * PAD + cb + 8];
                al[im][3] = *(const unsigned*)&cAl[(r + 8) * PAD + cb + 8];
            }
            #pragma unroll
            for (int jn = 0; jn < 4; jn++) {
                int n = wn * 32 + jn * 8 + lq;
                bh[jn][0] = *(const unsigned*)&cBh[n * PAD + cb    ];
                bh[jn][1] = *(const unsigned*)&cBh[n * PAD + cb + 8];
                bl[jn][0] = *(const unsigned*)&cBl[n * PAD + cb    ];
                bl[jn][1] = *(const unsigned*)&cBl[n * PAD + cb + 8];
            }
            #pragma unroll
            for (int im = 0; im < 2; im++)
                #pragma unroll
                for (int jn = 0; jn < 4; jn++) {
                    float* cc = acc[im][jn];
                    asm volatile(
                        "mma.sync.aligned.m16n8k16.row.col.f32.bf16.bf16.f32 "
                        "{%0,%1,%2,%3}, {%4,%5,%6,%7}, {%8,%9}, {%0,%1,%2,%3};"
                        : "+f"(cc[0]), "+f"(cc[1]), "+f"(cc[2]), "+f"(cc[3])
                        : "r"(ah[im][0]), "r"(ah[im][1]), "r"(ah[im][2]), "r"(ah[im][3]),
                          "r"(bh[jn][0]), "r"(bh[jn][1]));
                    asm volatile(
                        "mma.sync.aligned.m16n8k16.row.col.f32.bf16.bf16.f32 "
                        "{%0,%1,%2,%3}, {%4,%5,%6,%7}, {%8,%9}, {%0,%1,%2,%3};"
                        : "+f"(cc[0]), "+f"(cc[1]), "+f"(cc[2]), "+f"(cc[3])
                        : "r"(ah[im][0]), "r"(ah[im][1]), "r"(ah[im][2]), "r"(ah[im][3]),
                          "r"(bl[jn][0]), "r"(bl[jn][1]));
                    asm volatile(
                        "mma.sync.aligned.m16n8k16.row.col.f32.bf16.bf16.f32 "
                        "{%0,%1,%2,%3}, {%4,%5,%6,%7}, {%8,%9}, {%0,%1,%2,%3};"
                        : "+f"(cc[0]), "+f"(cc[1]), "+f"(cc[2]), "+f"(cc[3])
                        : "r"(al[im][0]), "r"(al[im][1]), "r"(al[im][2]), "r"(al[im][3]),
                          "r"(bh[jn][0]), "r"(bh[jn][1]));
                }
        }
        __syncthreads();
    }

    #pragma unroll
    for (int im = 0; im < 2; im++) {
        int mb = m0 + wm * 32 + im * 16 + lq;
        #pragma unroll
        for (int jn = 0; jn < 4; jn++) {
            int nb = n0 + wn * 32 + jn * 8 + lr * 2;
            float b0 = 0.f, b1 = 0.f;
            if (bias && ks == 0) {
                if (nb     < N) b0 = bias[nb];
                if (nb + 1 < N) b1 = bias[nb + 1];
            }
            float* cc = acc[im][jn];
            #pragma unroll
            for (int half = 0; half < 2; half++) {
                int m = mb + half * 8;
                if (m >= M) continue;
                if (nb < N) {
                    float r = (cc[half*2] + b0) * alpha;
                    float* p = Cp + (ll)m * crs + (ll)nb * ccs;
                    if (ksplit == 1) *p = r; else atomicAdd(p, r);
                }
                if (nb + 1 < N) {
                    float r = (cc[half*2 + 1] + b1) * alpha;
                    float* p = Cp + (ll)m * crs + (ll)(nb + 1) * ccs;
                    if (ksplit == 1) *p = r; else atomicAdd(p, r);
                }
            }
        }
    }
}

/* ---------------- cosine scales per (b,r) --------------------------------- */
__global__ void scales_kernel(const float* __restrict__ z, const float* __restrict__ clt,
                              const float* __restrict__ p1, const float* __restrict__ p2,
                              float* __restrict__ s1o, float* __restrict__ s2o) {
    __shared__ float p1s[NC_], p2s[NC_], pn[2];
    int b = blockIdx.y;
    int r = blockIdx.x * 128 + threadIdx.x;
    int tid = threadIdx.x;
    for (int i = tid; i < NC_; i += 128) { p1s[i] = p1[i]; p2s[i] = p2[i]; }
    if (tid < 2) {
        const float* p = tid ? p2 : p1;
        float s = 0.f;
        for (int k = 0; k < NC_; k++) s += p[k]*p[k];
        pn[tid] = 1.0f / fmaxf(sqrtf(s), 1e-12f);
    }
    __syncthreads();
    const float* zb = z   + (ll)b * NC_ * R_ + r;
    const float* cb = clt + (ll)b * NC_ * R_ + r;
    float zz = 0.f, zp = 0.f, cc = 0.f, cp = 0.f;
    #pragma unroll 6
    for (int j = 0; j < NC_; j++) {
        float zv = zb[(ll)j * R_];
        float cv = cb[(ll)j * R_];
        zz += zv*zv; zp += zv*p1s[j];
        cc += cv*cv; cp += cv*p2s[j];
    }
    float s1 = zp * pn[0] / fmaxf(sqrtf(zz), 1e-12f);
    float s2 = cp * pn[1] / fmaxf(sqrtf(cc), 1e-12f);
    s1o[(ll)b*R_ + r] = fminf(fmaxf(s1, 0.f), 1.f);
    s2o[(ll)b*R_ + r] = fminf(fmaxf(s2, 0.f), 1.f);
}

/* ---------------- softmax: asn copy + soft bf16 hi/lo --------------------- */
__global__ void softmax_rows2(const float* __restrict__ cxz,
                              float* __restrict__ asn,
                              bf16* __restrict__ sfh, bf16* __restrict__ sfl) {
    int row = blockIdx.x;
    int b = row / 600; int rem = row - b * 600;
    int t = rem / NC_; int k = rem - t * NC_;
    const float* s = cxz + ((ll)(b * NC_ + k)) * R_ + (ll)t * N_;
    ll drow = ((ll)((b * T_ + t) * NC_ + k)) * N_;
    __shared__ float sh[8];
    int tid = threadIdx.x;
    float mx = -1e30f;
    for (int i = tid; i < N_; i += 256) mx = fmaxf(mx, s[i]);
    #pragma unroll
    for (int o = 16; o; o >>= 1) mx = fmaxf(mx, __shfl_xor_sync(0xffffffffu, mx, o));
    if ((tid & 31) == 0) sh[tid >> 5] = mx;
    __syncthreads();
    mx = fmaxf(fmaxf(fmaxf(sh[0],sh[1]),fmaxf(sh[2],sh[3])),
               fmaxf(fmaxf(sh[4],sh[5]),fmaxf(sh[6],sh[7])));
    __syncthreads();
    float sum = 0.f;
    for (int i = tid; i < N_; i += 256) sum += expf(s[i] - mx);
    sum = blockSum256(sum, sh);
    float inv = 1.0f / sum;
    for (int i = tid; i < N_; i += 256) {
        float v = s[i];
        asn[drow + i] = v;
        split_store(expf(v - mx) * inv, sfh, sfl, drow + i);
    }
}

/* ---------------- gate + LayerNorm --------------------------------------- */
__global__ void gate_ln_kernel(const float* __restrict__ cen,
                               const float* __restrict__ nw, const float* __restrict__ nb,
                               const float* __restrict__ salpha, const float* __restrict__ sbeta,
                               float* __restrict__ cin_out) {
    int k = blockIdx.x, b = blockIdx.y, c = threadIdx.x;
    __shared__ float sh[8];
    float pv[4];
    #pragma unroll
    for (int t = 0; t < 4; t++)
        pv[t] = cen[(((ll)b*4 + t) * NC_ + k) * C_ + c];
    float last = pv[3];
    float ll2 = blockSum256(last*last, sh);
    float cin = last;
    float alpha = salpha[0], beta = sbeta[0];
    for (int t = 0; t < 3; t++) {
        float dt = blockSum256(last * pv[t], sh);
        float pp = blockSum256(pv[t] * pv[t], sh);
        float denom = fmaxf(sqrtf(ll2) * sqrtf(pp), 1e-8f);
        float gate = 1.0f / (1.0f + expf(-(beta + alpha * (dt / denom))));
        cin += gate * pv[t];
    }
    float m  = blockSum256(cin, sh) * (1.0f / C_);
    float dv = cin - m;
    float var = blockSum256(dv*dv, sh) * (1.0f / C_);
    cin_out[((ll)b*NC_ + k) * C_ + c] = dv * rsqrtf(var + 1e-5f) * nw[c] + nb[c];
}

/* ---------------- K/V projections ---------------------------------------- */
__global__ void kv_kernel(const float* __restrict__ cin,
                          const float* __restrict__ kw, const float* __restrict__ kb,
                          const float* __restrict__ vw, const float* __restrict__ vb,
                          float* __restrict__ ko, float* __restrict__ vo) {
    int row = blockIdx.x, c = threadIdx.x;
    __shared__ float ci[C_];
    ci[c] = cin[(ll)row * C_ + c];
    __syncthreads();
    float ka = kb[c], va = vb[c];
    const float* kwr = kw + (ll)c * C_;
    const float* vwr = vw + (ll)c * C_;
    #pragma unroll 4
    for (int j = 0; j < C_; j++) {
        float cv = ci[j];
        ka += cv * kwr[j];
        va += cv * vwr[j];
    }
    ko[(ll)row * C_ + c] = ka;
    vo[(ll)row * C_ + c] = va;
}

/* ---------------- fused attention -> bf16 hi/lo output -------------------- */
__global__ void attn_kernel(const float* __restrict__ q, const float* __restrict__ ks,
                            const float* __restrict__ vs,
                            bf16* __restrict__ oh, bf16* __restrict__ ol) {
    const int b = blockIdx.y;
    const int n0 = blockIdx.x * 8;
    __shared__ float qs[8][C_];
    __shared__ float P[8][8][152];
    int tid = threadIdx.x;
    for (int i = tid; i < 8*C_; i += 256)
        qs[i >> 8][i & 255] = q[((ll)b*N_ + n0 + (i >> 8)) * C_ + (i & 255)];
    __syncthreads();
    int h = tid >> 5, lane = tid & 31;
    float lg[8][5];
    #pragma unroll
    for (int g = 0; g < 8; g++)
        #pragma unroll
        for (int s = 0; s < 5; s++) lg[g][s] = -1e30f;
    #pragma unroll
    for (int s = 0; s < 5; s++) {
        int idx = lane + s*32;
        if (idx < NC_) {
            const float4* kp = reinterpret_cast<const float4*>(ks + ((ll)b*NC_ + idx)*C_ + h*32);
            float4 kk[8];
            #pragma unroll
            for (int u = 0; u < 8; u++) kk[u] = kp[u];
            #pragma unroll
            for (int g = 0; g < 8; g++) {
                const float* qb = &qs[g][h*32];
                float d = 0.f;
                #pragma unroll
                for (int u = 0; u < 8; u++)
                    d += kk[u].x*qb[u*4] + kk[u].y*qb[u*4+1] + kk[u].z*qb[u*4+2] + kk[u].w*qb[u*4+3];
                lg[g][s] = d;
            }
        }
    }
    float invg[8];
    #pragma unroll
    for (int g = 0; g < 8; g++) {
        float mx = -1e30f;
        #pragma unroll
        for (int s = 0; s < 5; s++) mx = fmaxf(mx, lg[g][s]);
        #pragma unroll
        for (int o2 = 16; o2; o2 >>= 1) mx = fmaxf(mx, __shfl_xor_sync(0xffffffffu, mx, o2));
        float sum = 0.f;
        #pragma unroll
        for (int s = 0; s < 5; s++) {
            int idx = lane + s*32;
            if (idx < NC_) {
                float e = expf(lg[g][s] - mx);
                P[h][g][idx] = e;
                sum += e;
            }
        }
        #pragma unroll
        for (int o2 = 16; o2; o2 >>= 1) sum += __shfl_xor_sync(0xffffffffu, sum, o2);
        invg[g] = 1.0f / sum;
    }
    __syncwarp();
    float og[8] = {0.f,0.f,0.f,0.f,0.f,0.f,0.f,0.f};
    for (int j = 0; j < NC_; j++) {
        float vv = vs[((ll)b*NC_ + j) * C_ + h*32 + lane];
        #pragma unroll
        for (int g = 0; g < 8; g++) og[g] += P[h][g][j] * vv;
    }
    #pragma unroll
    for (int g = 0; g < 8; g++) {
        float v = og[g] * invg[g];
        split_store(v, oh, ol, ((ll)b*N_ + n0 + g) * C_ + h*32 + lane);
    }
}

/* ---------------- depthwise 3x3 conv + GELU -> bf16 hi/lo ----------------- */
__global__ void conv_gelu2(const float* __restrict__ h,
                           const float* __restrict__ dww, const float* __restrict__ dwb,
                           bf16* __restrict__ oh, bf16* __restrict__ ol) {
    __shared__ float patch[10][10][64];
    int ch0 = blockIdx.x * 64;
    int tileid = blockIdx.y;
    int y0 = (tileid >> 3) * 8, x0 = (tileid & 7) * 8;
    int b = blockIdx.z;
    int tid = threadIdx.x;
    for (int i = tid; i < 6400; i += 256) {
        int c = i & 63, sp = i >> 6;
        int py = sp / 10, px = sp % 10;
        int yy = y0 + py - 1, xx = x0 + px - 1;
        float v = 0.f;
        if (yy >= 0 && yy < 64 && xx >= 0 && xx < 64)
            v = h[(((ll)b*N_) + (yy*64 + xx)) * HID_ + ch0 + c];
        patch[py][px][c] = v;
    }
    __syncthreads();
    int c = tid & 63, sub = tid >> 6;
    float w[9];
    #pragma unroll
    for (int i = 0; i < 9; i++) w[i] = dww[(ch0 + c)*9 + i];
    float bv = dwb[ch0 + c];
    for (int oy = sub; oy < 8; oy += 4) {
        #pragma unroll
        for (int ox = 0; ox < 8; ox++) {
            float a = bv;
            #pragma unroll
            for (int dy = 0; dy < 3; dy++)
                #pragma unroll
                for (int dx = 0; dx < 3; dx++)
                    a += patch[oy+dy][ox+dx][c] * w[dy*3+dx];
            float g = 0.5f * a * (1.0f + erff(a * 0.7071067811865475f));
            split_store(g, oh, ol, (((ll)b*N_) + ((y0+oy)*64 + x0+ox)) * HID_ + ch0 + c);
        }
    }
}

/* ---------------- residual + LayerNorm (optional bf16 dual-write) ---------- */
__global__ void add_ln_kernel(const float* __restrict__ res, const float* __restrict__ val,
                              const float* __restrict__ nw, const float* __restrict__ nb,
                              float* __restrict__ dst,
                              bf16* __restrict__ dh, bf16* __restrict__ dl) {
    ll row = blockIdx.x;
    int c = threadIdx.x;
    __shared__ float sh[8];
    float v = val[row * C_ + c];
    float m = blockSum256(v, sh) * (1.0f / C_);
    float d = v - m;
    float var = blockSum256(d*d, sh) * (1.0f / C_);
    float r = res[row * C_ + c] + d * rsqrtf(var + 1e-5f) * nw[c] + nb[c];
    dst[row * C_ + c] = r;
    if (dh) split_store(r, dh, dl, row * C_ + c);
}

/* ---------------- host launch --------------------------------------------- */
static float* symaddr(const void* sym) {
    void* p = nullptr;
    cudaGetSymbolAddress(&p, sym);
    return (float*)p;
}
static bf16* symaddrb(const void* sym) {
    void* p = nullptr;
    cudaGetSymbolAddress(&p, sym);
    return (bf16*)p;
}

extern "C" void kernel_launch(void* const* d_in, const int* in_sizes, int n_in,
                              void* d_out, int out_size) {
    const float* x    = (const float*)d_in[0];
    const float* z    = (const float*)d_in[1];
    const float* mem  = (const float*)d_in[2];
    const float* cw   = (const float*)d_in[3];
    const float* p1   = (const float*)d_in[4];
    const float* t1   = (const float*)d_in[5];
    const float* p2   = (const float*)d_in[6];
    const float* t2   = (const float*)d_in[7];
    const float* sal  = (const float*)d_in[8];
    const float* sbe  = (const float*)d_in[9];
    const float* qw   = (const float*)d_in[10];
    const float* qb   = (const float*)d_in[11];
    const float* kw   = (const float*)d_in[12];
    const float* kb   = (const float*)d_in[13];
    const float* vw   = (const float*)d_in[14];
    const float* vb   = (const float*)d_in[15];
    const float* pw   = (const float*)d_in[16];
    const float* pb   = (const float*)d_in[17];
    const float* nw   = (const float*)d_in[18];
    const float* nb   = (const float*)d_in[19];
    const float* f1w  = (const float*)d_in[20];
    const float* f1b  = (const float*)d_in[21];
    const float* dww  = (const float*)d_in[22];
    const float* dwb  = (const float*)d_in[23];
    const float* f2w  = (const float*)d_in[24];
    const float* f2b  = (const float*)d_in[25];

    float* out_main = (float*)d_out;
    float* out_cxz  = out_main + (ll)B_*N_*C_;
    float* out_asn  = out_cxz  + (ll)B_*NC_*R_;

    float* xf   = symaddr(g_xf);
    float* clt  = symaddr(g_clt);
    float* s1   = symaddr(g_s1);
    float* s2   = symaddr(g_s2);
    float* cen  = symaddr(g_cen);
    float* cin  = symaddr(g_cin);
    float* ksc  = symaddr(g_k);
    float* vsc  = symaddr(g_v);
    float* qsc  = symaddr(g_q);
    float* tmp  = symaddr(g_tmp);
    float* out1 = symaddr(g_out1);
    float* h1   = symaddr(g_h1);

    bf16 *xf_h = symaddrb(g_xf_h), *xf_l = symaddrb(g_xf_l);
    bf16 *xT_h = symaddrb(g_xfT_h),*xT_l = symaddrb(g_xfT_l);
    bf16 *S_h  = symaddrb(g_S_h),  *S_l  = symaddrb(g_S_l);
    bf16 *tc_h = symaddrb(g_tc_h), *tc_l = symaddrb(g_tc_l);
    bf16 *sf_h = symaddrb(g_sf_h), *sf_l = symaddrb(g_sf_l);
    bf16 *x_h  = symaddrb(g_x_h),  *x_l  = symaddrb(g_x_l);
    bf16 *at_h = symaddrb(g_atn_h),*at_l = symaddrb(g_atn_l);
    bf16 *o1_h = symaddrb(g_o1_h), *o1_l = symaddrb(g_o1_l);
    bf16 *hg_h = symaddrb(g_hg_h), *hg_l = symaddrb(g_hg_l);
    bf16 *cw_h = symaddrb(g_cw_h), *cw_l = symaddrb(g_cw_l);
    bf16 *qw_h = symaddrb(g_qw_h), *qw_l = symaddrb(g_qw_l);
    bf16 *pw_h = symaddrb(g_pw_h), *pw_l = symaddrb(g_pw_l);
    bf16 *f1_h = symaddrb(g_f1_h), *f1_l = symaddrb(g_f1_l);
    bf16 *f2_h = symaddrb(g_f2_h), *f2_l = symaddrb(g_f2_l);

    /* 0. fused weight + x conversions (one launch), tcat */
    {
        CvtJob j0 = {(const float4*)cw,  cw_h, cw_l, NC_*C_/4};
        CvtJob j1 = {(const float4*)qw,  qw_h, qw_l, C_*C_/4};
        CvtJob j2 = {(const float4*)pw,  pw_h, pw_l, C_*C_/4};
        CvtJob j3 = {(const float4*)f1w, f1_h, f1_l, HID_*C_/4};
        CvtJob j4 = {(const float4*)f2w, f2_h, f2_l, HID_*C_/4};
        CvtJob j5 = {(const float4*)x,   x_h,  x_l,  B_*N_*C_/4};
        int mx = HID_*C_/4;
        if (B_*N_*C_/4 > mx) mx = B_*N_*C_/4;
        cvt_multi<<<dim3((mx + 255)/256, 6), 256>>>(j0, j1, j2, j3, j4, j5);
    }
    build_tcat<<<(NC_*KS_ + 255)/256, 256>>>(t1, t2, tc_h, tc_l);

    /* 1. xf = concat(mem, x) + bf16 split; xfT for cen */
    copy_xf_kernel<<<8192, 256>>>((const float4*)x, (const float4*)mem,
                                  (float4*)xf, xf_h, xf_l);
    build_xfT<<<dim3(N_/64, C_/32, B_*T_), 256>>>(xf, xT_h, xT_l);

    /* 2. clt (MMA, transposed store) */
    gemm_mma2<<<dim3(R_/128, 3, B_), 256>>>(
        R_, NC_, C_, xf_h, xf_l, C_, (ll)R_*C_, cw_h, cw_l, C_, 0,
        clt, 1, R_, (ll)NC_*R_, nullptr, 1.0f, 1);

    /* 3. cosine scales + scaled/split S */
    scales_kernel<<<dim3(R_/128, B_), 128>>>(z, clt, p1, p2, s1, s2);
    build_S<<<dim3(R_/64, B_), 256>>>(z, clt, s1, s2, S_h, S_l);

    /* 4. cluster_x_z (MMA: M=R, N=150, K=320, transposed store) */
    gemm_mma2<<<dim3(R_/128, 3, B_), 256>>>(
        R_, NC_, KS_, S_h, S_l, KS_, (ll)R_*KS_, tc_h, tc_l, KS_, 0,
        out_cxz, 1, R_, (ll)NC_*R_, nullptr, 0.5f, 1);

    /* 5. softmax: asn copy + soft bf16 */
    softmax_rows2<<<B_*T_*NC_, 256>>>(out_cxz, out_asn, sf_h, sf_l);

    /* 6. cen = soft @ xf (MMA, split-K=8 atomic, M=150 guarded) */
    zero_kernel<<<(B_*T_*NC_*C_ + 255)/256, 256>>>(cen, B_*T_*NC_*C_);
    gemm_mma2<<<dim3(2, 4, B_*T_*8), 256>>>(
        NC_, C_, N_, sf_h, sf_l, N_, (ll)NC_*N_, xT_h, xT_l, N_, (ll)C_*N_,
        cen, C_, 1, (ll)NC_*C_, nullptr, 1.0f, 8);

    /* 7. gate + LN */
    gate_ln_kernel<<<dim3(NC_, B_), 256>>>(cen, nw, nb, sal, sbe, cin);

    /* 8. k,v */
    kv_kernel<<<B_*NC_, 256>>>(cin, kw, kb, vw, vb, ksc, vsc);

    /* 9. q (MMA) */
    gemm_mma2<<<dim3(64, 4, 1), 256>>>(
        B_*N_, C_, C_, x_h, x_l, C_, 0, qw_h, qw_l, C_, 0,
        qsc, C_, 1, 0, qb, 0.17677669529663687f, 1);

    /* 10. attention -> bf16 */
    attn_kernel<<<dim3(N_/8, B_), 256>>>(qsc, ksc, vsc, at_h, at_l);

    /* 11. proj (MMA) */
    gemm_mma2<<<dim3(64, 4, 1), 256>>>(
        B_*N_, C_, C_, at_h, at_l, C_, 0, pw_h, pw_l, C_, 0,
        tmp, C_, 1, 0, pb, 1.0f, 1);

    /* 12. out1 = x + LN(proj), dual-write */
    add_ln_kernel<<<B_*N_, 256>>>(x, tmp, nw, nb, out1, o1_h, o1_l);

    /* 13. fc1 (MMA) */
    gemm_mma2<<<dim3(64, 16, 1), 256>>>(
        B_*N_, HID_, C_, o1_h, o1_l, C_, 0, f1_h, f1_l, C_, 0,
        h1, HID_, 1, 0, f1b, 1.0f, 1);

    /* 14. depthwise conv + GELU -> bf16 */
    conv_gelu2<<<dim3(HID_/64, 64, B_), 256>>>(h1, dww, dwb, hg_h, hg_l);

    /* 15. fc2 (MMA, K=1024) */
    gemm_mma2<<<dim3(64, 4, 1), 256>>>(
        B_*N_, C_, HID_, hg_h, hg_l, HID_, 0, f2_h, f2_l, HID_, 0,
        tmp, C_, 1, 0, f2b, 1.0f, 1);

    /* 16. out = out1 + LN(fc2) */
    add_ln_kernel<<<B_*N_, 256>>>(out1, tmp, nw, nb, out_main, nullptr, nullptr);
}

// round 12
// speedup vs baseline: 1.9903x; 1.0677x over previous
#include <cuda_runtime.h>
#include <cuda_bf16.h>
#include <math.h>

#define B_   2
#define N_   4096
#define C_   256
#define NC_  150
#define T_   4
#define HID_ 1024
#define R_   16384   /* T_*N_ */
#define KS_  320     /* padded 2*NC_ for cxz MMA */
#define PL_  160     /* padded NC_ for attention P */

typedef long long ll;
typedef __nv_bfloat16 bf16;

/* ---------------- scratch (device globals) ------------------------------- */
__device__ float g_clt [B_*NC_*R_];
__device__ float g_s1  [B_*R_];
__device__ float g_s2  [B_*R_];
__device__ float g_cen [B_*T_*NC_*C_];
__device__ float g_cin [B_*NC_*C_];
__device__ float g_P   [B_*8*N_*PL_];
__device__ float g_tmp [B_*N_*C_];
__device__ float g_out1[B_*N_*C_];
__device__ float g_h1  [B_*N_*HID_];

/* bf16 hi/lo operand buffers — 16B aligned (float4 / cp.async reads) */
__device__ __align__(16) bf16 g_xf_h [B_*T_*N_*C_];
__device__ __align__(16) bf16 g_xf_l [B_*T_*N_*C_];
__device__ __align__(16) bf16 g_xfT_h[B_*T_*C_*N_];
__device__ __align__(16) bf16 g_xfT_l[B_*T_*C_*N_];
__device__ __align__(16) bf16 g_S_h  [B_*R_*KS_];
__device__ __align__(16) bf16 g_S_l  [B_*R_*KS_];
__device__ __align__(16) bf16 g_tc_h [NC_*KS_];
__device__ __align__(16) bf16 g_tc_l [NC_*KS_];
__device__ __align__(16) bf16 g_sf_h [B_*T_*NC_*N_];
__device__ __align__(16) bf16 g_sf_l [B_*T_*NC_*N_];
__device__ __align__(16) bf16 g_x_h  [B_*N_*C_];
__device__ __align__(16) bf16 g_x_l  [B_*N_*C_];
__device__ __align__(16) bf16 g_q_h  [B_*N_*C_];
__device__ __align__(16) bf16 g_q_l  [B_*N_*C_];
__device__ __align__(16) bf16 g_k_h  [B_*NC_*C_];
__device__ __align__(16) bf16 g_k_l  [B_*NC_*C_];
__device__ __align__(16) bf16 g_vt_h [B_*8*32*PL_];
__device__ __align__(16) bf16 g_vt_l [B_*8*32*PL_];
__device__ __align__(16) bf16 g_P_h  [B_*8*N_*PL_];
__device__ __align__(16) bf16 g_P_l  [B_*8*N_*PL_];
__device__ __align__(16) bf16 g_atn_h[B_*N_*C_];
__device__ __align__(16) bf16 g_atn_l[B_*N_*C_];
__device__ __align__(16) bf16 g_o1_h [B_*N_*C_];
__device__ __align__(16) bf16 g_o1_l [B_*N_*C_];
__device__ __align__(16) bf16 g_hg_h [B_*N_*HID_];
__device__ __align__(16) bf16 g_hg_l [B_*N_*HID_];
__device__ __align__(16) bf16 g_cw_h [NC_*C_];
__device__ __align__(16) bf16 g_cw_l [NC_*C_];
__device__ __align__(16) bf16 g_qw_h [C_*C_];
__device__ __align__(16) bf16 g_qw_l [C_*C_];
__device__ __align__(16) bf16 g_pw_h [C_*C_];
__device__ __align__(16) bf16 g_pw_l [C_*C_];
__device__ __align__(16) bf16 g_f1_h [HID_*C_];
__device__ __align__(16) bf16 g_f1_l [HID_*C_];
__device__ __align__(16) bf16 g_f2_h [C_*HID_];
__device__ __align__(16) bf16 g_f2_l [C_*HID_];

__device__ __forceinline__ float blockSum256(float v, float* sh) {
    #pragma unroll
    for (int o = 16; o; o >>= 1) v += __shfl_xor_sync(0xffffffffu, v, o);
    if ((threadIdx.x & 31) == 0) sh[threadIdx.x >> 5] = v;
    __syncthreads();
    float r = sh[0]+sh[1]+sh[2]+sh[3]+sh[4]+sh[5]+sh[6]+sh[7];
    __syncthreads();
    return r;
}

__device__ __forceinline__ void split_store(float v, bf16* h, bf16* l, ll idx) {
    bf16 hh = __float2bfloat16(v);
    h[idx] = hh;
    l[idx] = __float2bfloat16(v - __bfloat162float(hh));
}
__device__ __forceinline__ void split_pair(float v, bf16& h, bf16& l) {
    h = __float2bfloat16(v);
    l = __float2bfloat16(v - __bfloat162float(h));
}

/* ---------------- cp.async helpers ---------------------------------------- */
__device__ __forceinline__ void cp16(unsigned dst, const void* src, bool pred) {
    int sz = pred ? 16 : 0;
    asm volatile("cp.async.ca.shared.global [%0], [%1], 16, %2;"
                 :: "r"(dst), "l"(src), "r"(sz));
}
__device__ __forceinline__ void cp_commit() {
    asm volatile("cp.async.commit_group;");
}
__device__ __forceinline__ void cp_wait0() {
    asm volatile("cp.async.wait_group 0;");
}

__global__ void zero_kernel(float* p, int n) {
    int i = blockIdx.x * 256 + threadIdx.x;
    if (i < n) p[i] = 0.f;
}
__global__ void zero_bf2(bf16* a, bf16* b, int n) {
    int i = blockIdx.x * 256 + threadIdx.x;
    if (i < n) { a[i] = __float2bfloat16(0.f); b[i] = __float2bfloat16(0.f); }
}

/* ---------------- fused fp32 -> bf16 hi/lo split (6 segments) -------------- */
struct CvtJob { const float4* s; bf16* h; bf16* l; int n4; };
__global__ void cvt_multi(CvtJob j0, CvtJob j1, CvtJob j2,
                          CvtJob j3, CvtJob j4, CvtJob j5) {
    CvtJob j;
    switch (blockIdx.y) {
        case 0: j = j0; break;
        case 1: j = j1; break;
        case 2: j = j2; break;
        case 3: j = j3; break;
        case 4: j = j4; break;
        default: j = j5; break;
    }
    int i = blockIdx.x * 256 + threadIdx.x;
    if (i >= j.n4) return;
    float4 v = j.s[i];
    float vv[4] = {v.x, v.y, v.z, v.w};
    #pragma unroll
    for (int u = 0; u < 4; u++) split_store(vv[u], j.h, j.l, (ll)i*4 + u);
}

/* ---------------- tcat hi/lo ----------------------------------------------- */
__global__ void build_tcat(const float* __restrict__ t1, const float* __restrict__ t2,
                           bf16* __restrict__ th, bf16* __restrict__ tl) {
    int idx = blockIdx.x * 256 + threadIdx.x;
    if (idx >= NC_ * KS_) return;
    int kp = idx / KS_, j = idx % KS_;
    float v = 0.f;
    if (j < NC_)        v = t1[j * NC_ + kp];
    else if (j < 2*NC_) v = t2[(j - NC_) * NC_ + kp];
    split_store(v, th, tl, idx);
}

/* ---------------- xf = concat(mem, x), bf16 split only --------------------- */
__global__ void copy_xf_kernel(const float4* __restrict__ x,
                               const float4* __restrict__ mem,
                               bf16* __restrict__ xh, bf16* __restrict__ xl) {
    ll i = (ll)blockIdx.x * 256 + threadIdx.x;
    int b  = (int)(i >> 20);
    int rem = (int)(i & 1048575);
    int tt = rem >> 18;
    int rc = rem & 262143;
    float4 v;
    if (tt < 3) v = mem[((ll)(b*3 + tt) << 18) + rc];
    else        v = x[((ll)b << 18) + rc];
    float vv[4] = {v.x, v.y, v.z, v.w};
    #pragma unroll
    for (int u = 0; u < 4; u++) split_store(vv[u], xh, xl, i*4 + u);
}

/* ---------------- xfT hi/lo: xfT[bt][c][n] (reads x/mem directly) ---------- */
__global__ void build_xfT(const float* __restrict__ x, const float* __restrict__ mem,
                          bf16* __restrict__ oh, bf16* __restrict__ olo) {
    __shared__ float tile[32][65];
    int bt = blockIdx.z;
    int b = bt >> 2, t = bt & 3;
    const float* src = (t < 3) ? (mem + ((ll)(b*3 + t)) * N_ * C_)
                               : (x   + ((ll)b) * N_ * C_);
    int n0 = blockIdx.x * 64, c0 = blockIdx.y * 32;
    int tid = threadIdx.x;
    for (int i = tid; i < 32 * 64; i += 256) {
        int cl = i & 31, nl = i >> 5;
        tile[cl][nl] = src[((ll)(n0 + nl)) * C_ + c0 + cl];
    }
    __syncthreads();
    int cl = tid >> 3, nseg = (tid & 7) * 8;
    __align__(16) bf16 hb[8], lb[8];
    #pragma unroll
    for (int u = 0; u < 8; u++) split_pair(tile[cl][nseg + u], hb[u], lb[u]);
    ll off = ((ll)bt * C_ + c0 + cl) * N_ + n0 + nseg;
    *(uint4*)&oh [off] = *(const uint4*)hb;
    *(uint4*)&olo[off] = *(const uint4*)lb;
}

/* ---------------- S hi/lo: S[b][r][j] = scaled z/clt (smem transpose) ------ */
__global__ void build_S(const float* __restrict__ z, const float* __restrict__ clt,
                        const float* __restrict__ s1, const float* __restrict__ s2,
                        bf16* __restrict__ sh_, bf16* __restrict__ sl_) {
    __shared__ float tile[32][65];
    __shared__ float s1s[64], s2s[64];
    int b = blockIdx.y;
    int r0 = blockIdx.x * 64;
    int tid = threadIdx.x;
    if (tid < 64) {
        s1s[tid] = s1[(ll)b * R_ + r0 + tid];
        s2s[tid] = s2[(ll)b * R_ + r0 + tid];
    }
    __syncthreads();
    for (int jc = 0; jc < KS_ / 32; jc++) {
        int j0 = jc * 32;
        for (int i = tid; i < 32 * 64; i += 256) {
            int rl = i & 63, jl = i >> 6;
            int j = j0 + jl;
            float v = 0.f;
            if (j < NC_)        v = z  [((ll)b * NC_ + j)        * R_ + r0 + rl] * s1s[rl];
            else if (j < 2*NC_) v = clt[((ll)b * NC_ + (j-NC_))  * R_ + r0 + rl] * s2s[rl];
            tile[jl][rl] = v;
        }
        __syncthreads();
        int rl = tid >> 2, jseg = (tid & 3) * 8;
        __align__(16) bf16 hb[8], lb[8];
        #pragma unroll
        for (int u = 0; u < 8; u++) split_pair(tile[jseg + u][rl], hb[u], lb[u]);
        ll off = ((ll)b * R_ + r0 + rl) * KS_ + j0 + jseg;
        *(uint4*)&sh_[off] = *(const uint4*)hb;
        *(uint4*)&sl_[off] = *(const uint4*)lb;
        __syncthreads();
    }
}

/* ---------------- pipelined pre-split bf16 tensor-core GEMM ----------------
 * out = alpha*(A·W^T + bias); fp32 out (Cp, nullable) and/or bf16 hi/lo
 * dual-write (Oh/Ol, same strides). 2-stage cp.async. (K/ksplit)%32==0.   */
__global__ void gemm_mma2(int M, int N, int K,
                          const bf16* __restrict__ Ah_, const bf16* __restrict__ Al_,
                          int lda, ll bsA,
                          const bf16* __restrict__ Wh_, const bf16* __restrict__ Wl_,
                          int ldw, ll bsW,
                          float* __restrict__ Cp, ll crs, ll ccs, ll bsC,
                          bf16* __restrict__ Oh, bf16* __restrict__ Ol,
                          const float* __restrict__ bias, float alpha, int ksplit) {
    constexpr int BM = 128, BN = 64, BK = 32, PAD = 40;
    constexpr int ASZ = BM * PAD, BSZ = BN * PAD;
    __shared__ __align__(16) bf16 Ah[2*ASZ], Al[2*ASZ];
    __shared__ __align__(16) bf16 Bh[2*BSZ], Bl[2*BSZ];
    int zz = blockIdx.z, bt = zz / ksplit, ks = zz - bt * ksplit;
    Ah_ += (ll)bt * bsA;  Al_ += (ll)bt * bsA;
    Wh_ += (ll)bt * bsW;  Wl_ += (ll)bt * bsW;
    if (Cp) Cp += (ll)bt * bsC;
    if (Oh) { Oh += (ll)bt * bsC; Ol += (ll)bt * bsC; }
    int Kc = K / ksplit;
    int kbeg = ks * Kc;
    int niter = Kc / BK;
    int m0 = blockIdx.x * BM, n0 = blockIdx.y * BN;
    int tid = threadIdx.x;
    int wid = tid >> 5, lane = tid & 31;
    int wm = wid >> 1, wn = wid & 1;
    int lq = lane >> 2, lr = lane & 3;

    unsigned sAh = (unsigned)__cvta_generic_to_shared(Ah);
    unsigned sAl = (unsigned)__cvta_generic_to_shared(Al);
    unsigned sBh = (unsigned)__cvta_generic_to_shared(Bh);
    unsigned sBl = (unsigned)__cvta_generic_to_shared(Bl);

    int arow0 = tid >> 2, aq0 = tid & 3;
    int arow1 = arow0 + 64;
    int brow = tid >> 2, bq = tid & 3;
    bool am0 = (m0 + arow0) < M, am1 = (m0 + arow1) < M;
    bool bn  = (n0 + brow) < N;

    auto load_stage = [&](int k0, int st) {
        {
            ll g = (ll)(m0 + arow0) * lda + k0 + aq0 * 8;
            unsigned d = (st*ASZ + arow0 * PAD + aq0 * 8) * 2;
            cp16(sAh + d, Ah_ + g, am0);
            cp16(sAl + d, Al_ + g, am0);
        }
        {
            ll g = (ll)(m0 + arow1) * lda + k0 + aq0 * 8;
            unsigned d = (st*ASZ + arow1 * PAD + aq0 * 8) * 2;
            cp16(sAh + d, Ah_ + g, am1);
            cp16(sAl + d, Al_ + g, am1);
        }
        {
            ll g = (ll)(n0 + brow) * ldw + k0 + bq * 8;
            unsigned d = (st*BSZ + brow * PAD + bq * 8) * 2;
            cp16(sBh + d, Wh_ + g, bn);
            cp16(sBl + d, Wl_ + g, bn);
        }
        cp_commit();
    };

    float acc[2][4][4];
    #pragma unroll
    for (int im = 0; im < 2; im++)
        #pragma unroll
        for (int jn = 0; jn < 4; jn++)
            #pragma unroll
            for (int c = 0; c < 4; c++) acc[im][jn][c] = 0.f;

    load_stage(kbeg, 0);

    for (int it = 0; it < niter; it++) {
        cp_wait0();
        __syncthreads();
        if (it + 1 < niter) load_stage(kbeg + (it + 1) * BK, (it + 1) & 1);
        int st = it & 1;
        const bf16* cAh = Ah + st * ASZ;
        const bf16* cAl = Al + st * ASZ;
        const bf16* cBh = Bh + st * BSZ;
        const bf16* cBl = Bl + st * BSZ;

        #pragma unroll
        for (int kc = 0; kc < 2; kc++) {
            int cb = kc * 16 + lr * 2;
            unsigned ah[2][4], al[2][4], bh[4][2], bl[4][2];
            #pragma unroll
            for (int im = 0; im < 2; im++) {
                int r = wm * 32 + im * 16 + lq;
                ah[im][0] = *(const unsigned*)&cAh[ r      * PAD + cb    ];
                ah[im][1] = *(const unsigned*)&cAh[(r + 8) * PAD + cb    ];
                ah[im][2] = *(const unsigned*)&cAh[ r      * PAD + cb + 8];
                ah[im][3] = *(const unsigned*)&cAh[(r + 8) * PAD + cb + 8];
                al[im][0] = *(const unsigned*)&cAl[ r      * PAD + cb    ];
                al[im][1] = *(const unsigned*)&cAl[(r + 8) * PAD + cb    ];
                al[im][2] = *(const unsigned*)&cAl[ r      * PAD + cb + 8];
                al[im][3] = *(const unsigned*)&cAl[(r + 8) * PAD + cb + 8];
            }
            #pragma unroll
            for (int jn = 0; jn < 4; jn++) {
                int n = wn * 32 + jn * 8 + lq;
                bh[jn][0] = *(const unsigned*)&cBh[n * PAD + cb    ];
                bh[jn][1] = *(const unsigned*)&cBh[n * PAD + cb + 8];
                bl[jn][0] = *(const unsigned*)&cBl[n * PAD + cb    ];
                bl[jn][1] = *(const unsigned*)&cBl[n * PAD + cb + 8];
            }
            #pragma unroll
            for (int im = 0; im < 2; im++)
                #pragma unroll
                for (int jn = 0; jn < 4; jn++) {
                    float* cc = acc[im][jn];
                    asm volatile(
                        "mma.sync.aligned.m16n8k16.row.col.f32.bf16.bf16.f32 "
                        "{%0,%1,%2,%3}, {%4,%5,%6,%7}, {%8,%9}, {%0,%1,%2,%3};"
                        : "+f"(cc[0]), "+f"(cc[1]), "+f"(cc[2]), "+f"(cc[3])
                        : "r"(ah[im][0]), "r"(ah[im][1]), "r"(ah[im][2]), "r"(ah[im][3]),
                          "r"(bh[jn][0]), "r"(bh[jn][1]));
                    asm volatile(
                        "mma.sync.aligned.m16n8k16.row.col.f32.bf16.bf16.f32 "
                        "{%0,%1,%2,%3}, {%4,%5,%6,%7}, {%8,%9}, {%0,%1,%2,%3};"
                        : "+f"(cc[0]), "+f"(cc[1]), "+f"(cc[2]), "+f"(cc[3])
                        : "r"(ah[im][0]), "r"(ah[im][1]), "r"(ah[im][2]), "r"(ah[im][3]),
                          "r"(bl[jn][0]), "r"(bl[jn][1]));
                    asm volatile(
                        "mma.sync.aligned.m16n8k16.row.col.f32.bf16.bf16.f32 "
                        "{%0,%1,%2,%3}, {%4,%5,%6,%7}, {%8,%9}, {%0,%1,%2,%3};"
                        : "+f"(cc[0]), "+f"(cc[1]), "+f"(cc[2]), "+f"(cc[3])
                        : "r"(al[im][0]), "r"(al[im][1]), "r"(al[im][2]), "r"(al[im][3]),
                          "r"(bh[jn][0]), "r"(bh[jn][1]));
                }
        }
        __syncthreads();
    }

    #pragma unroll
    for (int im = 0; im < 2; im++) {
        int mb = m0 + wm * 32 + im * 16 + lq;
        #pragma unroll
        for (int jn = 0; jn < 4; jn++) {
            int nb = n0 + wn * 32 + jn * 8 + lr * 2;
            float b0 = 0.f, b1 = 0.f;
            if (bias && ks == 0) {
                if (nb     < N) b0 = bias[nb];
                if (nb + 1 < N) b1 = bias[nb + 1];
            }
            float* cc = acc[im][jn];
            #pragma unroll
            for (int half = 0; half < 2; half++) {
                int m = mb + half * 8;
                if (m >= M) continue;
                #pragma unroll
                for (int e = 0; e < 2; e++) {
                    int n = nb + e;
                    if (n >= N) continue;
                    float r = (cc[half*2 + e] + (e ? b1 : b0)) * alpha;
                    ll off = (ll)m * crs + (ll)n * ccs;
                    if (Cp) {
                        if (ksplit == 1) Cp[off] = r;
                        else atomicAdd(&Cp[off], r);
                    }
                    if (Oh) split_store(r, Oh, Ol, off);
                }
            }
        }
    }
}

/* ---------------- cosine scales per (b,r) --------------------------------- */
__global__ void scales_kernel(const float* __restrict__ z, const float* __restrict__ clt,
                              const float* __restrict__ p1, const float* __restrict__ p2,
                              float* __restrict__ s1o, float* __restrict__ s2o) {
    __shared__ float p1s[NC_], p2s[NC_], pn[2];
    int b = blockIdx.y;
    int r = blockIdx.x * 128 + threadIdx.x;
    int tid = threadIdx.x;
    for (int i = tid; i < NC_; i += 128) { p1s[i] = p1[i]; p2s[i] = p2[i]; }
    if (tid < 2) {
        const float* p = tid ? p2 : p1;
        float s = 0.f;
        for (int k = 0; k < NC_; k++) s += p[k]*p[k];
        pn[tid] = 1.0f / fmaxf(sqrtf(s), 1e-12f);
    }
    __syncthreads();
    const float* zb = z   + (ll)b * NC_ * R_ + r;
    const float* cb = clt + (ll)b * NC_ * R_ + r;
    float zz = 0.f, zp = 0.f, cc = 0.f, cp = 0.f;
    #pragma unroll 6
    for (int j = 0; j < NC_; j++) {
        float zv = zb[(ll)j * R_];
        float cv = cb[(ll)j * R_];
        zz += zv*zv; zp += zv*p1s[j];
        cc += cv*cv; cp += cv*p2s[j];
    }
    float s1 = zp * pn[0] / fmaxf(sqrtf(zz), 1e-12f);
    float s2 = cp * pn[1] / fmaxf(sqrtf(cc), 1e-12f);
    s1o[(ll)b*R_ + r] = fminf(fmaxf(s1, 0.f), 1.f);
    s2o[(ll)b*R_ + r] = fminf(fmaxf(s2, 0.f), 1.f);
}

/* ---------------- softmax: asn copy + soft bf16 hi/lo --------------------- */
__global__ void softmax_rows2(const float* __restrict__ cxz,
                              float* __restrict__ asn,
                              bf16* __restrict__ sfh, bf16* __restrict__ sfl) {
    int row = blockIdx.x;
    int b = row / 600; int rem = row - b * 600;
    int t = rem / NC_; int k = rem - t * NC_;
    const float* s = cxz + ((ll)(b * NC_ + k)) * R_ + (ll)t * N_;
    ll drow = ((ll)((b * T_ + t) * NC_ + k)) * N_;
    __shared__ float sh[8];
    int tid = threadIdx.x;
    float mx = -1e30f;
    for (int i = tid; i < N_; i += 256) mx = fmaxf(mx, s[i]);
    #pragma unroll
    for (int o = 16; o; o >>= 1) mx = fmaxf(mx, __shfl_xor_sync(0xffffffffu, mx, o));
    if ((tid & 31) == 0) sh[tid >> 5] = mx;
    __syncthreads();
    mx = fmaxf(fmaxf(fmaxf(sh[0],sh[1]),fmaxf(sh[2],sh[3])),
               fmaxf(fmaxf(sh[4],sh[5]),fmaxf(sh[6],sh[7])));
    __syncthreads();
    float sum = 0.f;
    for (int i = tid; i < N_; i += 256) sum += expf(s[i] - mx);
    sum = blockSum256(sum, sh);
    float inv = 1.0f / sum;
    for (int i = tid; i < N_; i += 256) {
        float v = s[i];
        asn[drow + i] = v;
        split_store(expf(v - mx) * inv, sfh, sfl, drow + i);
    }
}

/* ---------------- P softmax: warp per row, write padded bf16 --------------- */
__global__ void p_softmax(const float* __restrict__ P,
                          bf16* __restrict__ ph, bf16* __restrict__ pl) {
    int row = blockIdx.x * 8 + (threadIdx.x >> 5);
    int lane = threadIdx.x & 31;
    const float* p = P + (ll)row * PL_;
    float v[5];
    float mx = -1e30f;
    #pragma unroll
    for (int u = 0; u < 5; u++) {
        int i = lane + u * 32;
        v[u] = (i < NC_) ? p[i] : -1e30f;
        mx = fmaxf(mx, v[u]);
    }
    #pragma unroll
    for (int o = 16; o; o >>= 1) mx = fmaxf(mx, __shfl_xor_sync(0xffffffffu, mx, o));
    float sum = 0.f;
    #pragma unroll
    for (int u = 0; u < 5; u++) {
        int i = lane + u * 32;
        v[u] = (i < NC_) ? expf(v[u] - mx) : 0.f;
        sum += v[u];
    }
    #pragma unroll
    for (int o = 16; o; o >>= 1) sum += __shfl_xor_sync(0xffffffffu, sum, o);
    float inv = 1.0f / sum;
    #pragma unroll
    for (int u = 0; u < 5; u++) {
        int i = lane + u * 32;
        if (i < PL_) split_store(v[u] * inv, ph, pl, (ll)row * PL_ + i);
    }
}

/* ---------------- gate + LayerNorm --------------------------------------- */
__global__ void gate_ln_kernel(const float* __restrict__ cen,
                               const float* __restrict__ nw, const float* __restrict__ nb,
                               const float* __restrict__ salpha, const float* __restrict__ sbeta,
                               float* __restrict__ cin_out) {
    int k = blockIdx.x, b = blockIdx.y, c = threadIdx.x;
    __shared__ float sh[8];
    float pv[4];
    #pragma unroll
    for (int t = 0; t < 4; t++)
        pv[t] = cen[(((ll)b*4 + t) * NC_ + k) * C_ + c];
    float last = pv[3];
    float ll2 = blockSum256(last*last, sh);
    float cin = last;
    float alpha = salpha[0], beta = sbeta[0];
    for (int t = 0; t < 3; t++) {
        float dt = blockSum256(last * pv[t], sh);
        float pp = blockSum256(pv[t] * pv[t], sh);
        float denom = fmaxf(sqrtf(ll2) * sqrtf(pp), 1e-8f);
        float gate = 1.0f / (1.0f + expf(-(beta + alpha * (dt / denom))));
        cin += gate * pv[t];
    }
    float m  = blockSum256(cin, sh) * (1.0f / C_);
    float dv = cin - m;
    float var = blockSum256(dv*dv, sh) * (1.0f / C_);
    cin_out[((ll)b*NC_ + k) * C_ + c] = dv * rsqrtf(var + 1e-5f) * nw[c] + nb[c];
}

/* ---------------- K/V projections -> bf16 (K rows, V transposed) ----------- */
__global__ void kv_kernel(const float* __restrict__ cin,
                          const float* __restrict__ kw, const float* __restrict__ kb,
                          const float* __restrict__ vw, const float* __restrict__ vb,
                          bf16* __restrict__ kh, bf16* __restrict__ kl,
                          bf16* __restrict__ vth, bf16* __restrict__ vtl) {
    int row = blockIdx.x, c = threadIdx.x;
    int b = row / NC_, kk = row - b * NC_;
    __shared__ float ci[C_];
    ci[c] = cin[(ll)row * C_ + c];
    __syncthreads();
    float ka = kb[c], va = vb[c];
    const float* kwr = kw + (ll)c * C_;
    const float* vwr = vw + (ll)c * C_;
    #pragma unroll 4
    for (int j = 0; j < C_; j++) {
        float cv = ci[j];
        ka += cv * kwr[j];
        va += cv * vwr[j];
    }
    split_store(ka, kh, kl, (ll)row * C_ + c);
    int h = c >> 5, nn = c & 31;
    ll vt = ((ll)(b * 8 + h) * 32 + nn) * PL_ + kk;
    split_store(va, vth, vtl, vt);
}

/* ---------------- depthwise 3x3 conv + GELU -> bf16 hi/lo ----------------- */
__global__ void conv_gelu2(const float* __restrict__ h,
                           const float* __restrict__ dww, const float* __restrict__ dwb,
                           bf16* __restrict__ oh, bf16* __restrict__ ol) {
    __shared__ float patch[10][10][64];
    int ch0 = blockIdx.x * 64;
    int tileid = blockIdx.y;
    int y0 = (tileid >> 3) * 8, x0 = (tileid & 7) * 8;
    int b = blockIdx.z;
    int tid = threadIdx.x;
    for (int i = tid; i < 6400; i += 256) {
        int c = i & 63, sp = i >> 6;
        int py = sp / 10, px = sp % 10;
        int yy = y0 + py - 1, xx = x0 + px - 1;
        float v = 0.f;
        if (yy >= 0 && yy < 64 && xx >= 0 && xx < 64)
            v = h[(((ll)b*N_) + (yy*64 + xx)) * HID_ + ch0 + c];
        patch[py][px][c] = v;
    }
    __syncthreads();
    int c = tid & 63, sub = tid >> 6;
    float w[9];
    #pragma unroll
    for (int i = 0; i < 9; i++) w[i] = dww[(ch0 + c)*9 + i];
    float bv = dwb[ch0 + c];
    for (int oy = sub; oy < 8; oy += 4) {
        #pragma unroll
        for (int ox = 0; ox < 8; ox++) {
            float a = bv;
            #pragma unroll
            for (int dy = 0; dy < 3; dy++)
                #pragma unroll
                for (int dx = 0; dx < 3; dx++)
                    a += patch[oy+dy][ox+dx][c] * w[dy*3+dx];
            float g = 0.5f * a * (1.0f + erff(a * 0.7071067811865475f));
            split_store(g, oh, ol, (((ll)b*N_) + ((y0+oy)*64 + x0+ox)) * HID_ + ch0 + c);
        }
    }
}

/* ---------------- residual + LayerNorm (optional bf16 dual-write) ---------- */
__global__ void add_ln_kernel(const float* __restrict__ res, const float* __restrict__ val,
                              const float* __restrict__ nw, const float* __restrict__ nb,
                              float* __restrict__ dst,
                              bf16* __restrict__ dh, bf16* __restrict__ dl) {
    ll row = blockIdx.x;
    int c = threadIdx.x;
    __shared__ float sh[8];
    float v = val[row * C_ + c];
    float m = blockSum256(v, sh) * (1.0f / C_);
    float d = v - m;
    float var = blockSum256(d*d, sh) * (1.0f / C_);
    float r = res[row * C_ + c] + d * rsqrtf(var + 1e-5f) * nw[c] + nb[c];
    dst[row * C_ + c] = r;
    if (dh) split_store(r, dh, dl, row * C_ + c);
}

/* ---------------- host launch --------------------------------------------- */
static float* symaddr(const void* sym) {
    void* p = nullptr;
    cudaGetSymbolAddress(&p, sym);
    return (float*)p;
}
static bf16* symaddrb(const void* sym) {
    void* p = nullptr;
    cudaGetSymbolAddress(&p, sym);
    return (bf16*)p;
}

extern "C" void kernel_launch(void* const* d_in, const int* in_sizes, int n_in,
                              void* d_out, int out_size) {
    const float* x    = (const float*)d_in[0];
    const float* z    = (const float*)d_in[1];
    const float* mem  = (const float*)d_in[2];
    const float* cw   = (const float*)d_in[3];
    const float* p1   = (const float*)d_in[4];
    const float* t1   = (const float*)d_in[5];
    const float* p2   = (const float*)d_in[6];
    const float* t2   = (const float*)d_in[7];
    const float* sal  = (const float*)d_in[8];
    const float* sbe  = (const float*)d_in[9];
    const float* qw   = (const float*)d_in[10];
    const float* qb   = (const float*)d_in[11];
    const float* kw   = (const float*)d_in[12];
    const float* kb   = (const float*)d_in[13];
    const float* vw   = (const float*)d_in[14];
    const float* vb   = (const float*)d_in[15];
    const float* pw   = (const float*)d_in[16];
    const float* pb   = (const float*)d_in[17];
    const float* nw   = (const float*)d_in[18];
    const float* nb   = (const float*)d_in[19];
    const float* f1w  = (const float*)d_in[20];
    const float* f1b  = (const float*)d_in[21];
    const float* dww  = (const float*)d_in[22];
    const float* dwb  = (const float*)d_in[23];
    const float* f2w  = (const float*)d_in[24];
    const float* f2b  = (const float*)d_in[25];

    float* out_main = (float*)d_out;
    float* out_cxz  = out_main + (ll)B_*N_*C_;
    float* out_asn  = out_cxz  + (ll)B_*NC_*R_;

    float* clt  = symaddr(g_clt);
    float* s1   = symaddr(g_s1);
    float* s2   = symaddr(g_s2);
    float* cen  = symaddr(g_cen);
    float* cin  = symaddr(g_cin);
    float* Pf   = symaddr(g_P);
    float* tmp  = symaddr(g_tmp);
    float* out1 = symaddr(g_out1);
    float* h1   = symaddr(g_h1);

    bf16 *xf_h = symaddrb(g_xf_h), *xf_l = symaddrb(g_xf_l);
    bf16 *xT_h = symaddrb(g_xfT_h),*xT_l = symaddrb(g_xfT_l);
    bf16 *S_h  = symaddrb(g_S_h),  *S_l  = symaddrb(g_S_l);
    bf16 *tc_h = symaddrb(g_tc_h), *tc_l = symaddrb(g_tc_l);
    bf16 *sf_h = symaddrb(g_sf_h), *sf_l = symaddrb(g_sf_l);
    bf16 *x_h  = symaddrb(g_x_h),  *x_l  = symaddrb(g_x_l);
    bf16 *q_h  = symaddrb(g_q_h),  *q_l  = symaddrb(g_q_l);
    bf16 *k_h  = symaddrb(g_k_h),  *k_l  = symaddrb(g_k_l);
    bf16 *vt_h = symaddrb(g_vt_h), *vt_l = symaddrb(g_vt_l);
    bf16 *P_h  = symaddrb(g_P_h),  *P_l  = symaddrb(g_P_l);
    bf16 *at_h = symaddrb(g_atn_h),*at_l = symaddrb(g_atn_l);
    bf16 *o1_h = symaddrb(g_o1_h), *o1_l = symaddrb(g_o1_l);
    bf16 *hg_h = symaddrb(g_hg_h), *hg_l = symaddrb(g_hg_l);
    bf16 *cw_h = symaddrb(g_cw_h), *cw_l = symaddrb(g_cw_l);
    bf16 *qw_h = symaddrb(g_qw_h), *qw_l = symaddrb(g_qw_l);
    bf16 *pw_h = symaddrb(g_pw_h), *pw_l = symaddrb(g_pw_l);
    bf16 *f1_h = symaddrb(g_f1_h), *f1_l = symaddrb(g_f1_l);
    bf16 *f2_h = symaddrb(g_f2_h), *f2_l = symaddrb(g_f2_l);

    /* 0. fused weight + x conversions (one launch), tcat */
    {
        CvtJob j0 = {(const float4*)cw,  cw_h, cw_l, NC_*C_/4};
        CvtJob j1 = {(const float4*)qw,  qw_h, qw_l, C_*C_/4};
        CvtJob j2 = {(const float4*)pw,  pw_h, pw_l, C_*C_/4};
        CvtJob j3 = {(const float4*)f1w, f1_h, f1_l, HID_*C_/4};
        CvtJob j4 = {(const float4*)f2w, f2_h, f2_l, HID_*C_/4};
        CvtJob j5 = {(const float4*)x,   x_h,  x_l,  B_*N_*C_/4};
        int mx = HID_*C_/4;
        if (B_*N_*C_/4 > mx) mx = B_*N_*C_/4;
        cvt_multi<<<dim3((mx + 255)/256, 6), 256>>>(j0, j1, j2, j3, j4, j5);
    }
    build_tcat<<<(NC_*KS_ + 255)/256, 256>>>(t1, t2, tc_h, tc_l);

    /* 1. xf bf16 + xfT */
    copy_xf_kernel<<<8192, 256>>>((const float4*)x, (const float4*)mem, xf_h, xf_l);
    build_xfT<<<dim3(N_/64, C_/32, B_*T_), 256>>>(x, mem, xT_h, xT_l);

    /* 2. clt (MMA, transposed store) */
    gemm_mma2<<<dim3(R_/128, 3, B_), 256>>>(
        R_, NC_, C_, xf_h, xf_l, C_, (ll)R_*C_, cw_h, cw_l, C_, 0,
        clt, 1, R_, (ll)NC_*R_, nullptr, nullptr, nullptr, 1.0f, 1);

    /* 3. cosine scales + scaled/split S */
    scales_kernel<<<dim3(R_/128, B_), 128>>>(z, clt, p1, p2, s1, s2);
    build_S<<<dim3(R_/64, B_), 256>>>(z, clt, s1, s2, S_h, S_l);

    /* 4. cluster_x_z (MMA: M=R, N=150, K=320, transposed store) */
    gemm_mma2<<<dim3(R_/128, 3, B_), 256>>>(
        R_, NC_, KS_, S_h, S_l, KS_, (ll)R_*KS_, tc_h, tc_l, KS_, 0,
        out_cxz, 1, R_, (ll)NC_*R_, nullptr, nullptr, nullptr, 0.5f, 1);

    /* 5. softmax: asn copy + soft bf16 */
    softmax_rows2<<<B_*T_*NC_, 256>>>(out_cxz, out_asn, sf_h, sf_l);

    /* 6. cen = soft @ xf (MMA, split-K=8 atomic, M=150 guarded) */
    zero_kernel<<<(B_*T_*NC_*C_ + 255)/256, 256>>>(cen, B_*T_*NC_*C_);
    gemm_mma2<<<dim3(2, 4, B_*T_*8), 256>>>(
        NC_, C_, N_, sf_h, sf_l, N_, (ll)NC_*N_, xT_h, xT_l, N_, (ll)C_*N_,
        cen, C_, 1, (ll)NC_*C_, nullptr, nullptr, nullptr, 1.0f, 8);

    /* 7. gate + LN */
    gate_ln_kernel<<<dim3(NC_, B_), 256>>>(cen, nw, nb, sal, sbe, cin);

    /* 8. k,v -> bf16 (Vt padded; zero pad region first) */
    zero_bf2<<<(B_*8*32*PL_ + 255)/256, 256>>>(vt_h, vt_l, B_*8*32*PL_);
    kv_kernel<<<B_*NC_, 256>>>(cin, kw, kb, vw, vb, k_h, k_l, vt_h, vt_l);

    /* 9. q (MMA, bf16 dual-write only) */
    gemm_mma2<<<dim3(64, 4, 1), 256>>>(
        B_*N_, C_, C_, x_h, x_l, C_, 0, qw_h, qw_l, C_, 0,
        nullptr, C_, 1, 0, q_h, q_l, qb, 0.17677669529663687f, 1);

    /* 10a. QK logits (MMA, batched over h; one launch per b) */
    for (int b = 0; b < B_; b++) {
        gemm_mma2<<<dim3(N_/128, 3, 8), 256>>>(
            N_, NC_, 32,
            q_h + (ll)b*N_*C_, q_l + (ll)b*N_*C_, C_, 32,
            k_h + (ll)b*NC_*C_, k_l + (ll)b*NC_*C_, C_, 32,
            Pf + (ll)b*8*N_*PL_, PL_, 1, (ll)N_*PL_,
            nullptr, nullptr, nullptr, 1.0f, 1);
    }

    /* 10b. P softmax -> padded bf16 */
    p_softmax<<<B_*8*N_/8, 256>>>(Pf, P_h, P_l);

    /* 10c. PV (MMA, batched over h; dual-write atn bf16) */
    for (int b = 0; b < B_; b++) {
        gemm_mma2<<<dim3(N_/128, 1, 8), 256>>>(
            N_, 32, PL_,
            P_h + (ll)b*8*N_*PL_, P_l + (ll)b*8*N_*PL_, PL_, (ll)N_*PL_,
            vt_h + (ll)b*8*32*PL_, vt_l + (ll)b*8*32*PL_, PL_, (ll)32*PL_,
            nullptr, C_, 1, 32,
            at_h + (ll)b*N_*C_, at_l + (ll)b*N_*C_, nullptr, 1.0f, 1);
    }

    /* 11. proj (MMA) */
    gemm_mma2<<<dim3(64, 4, 1), 256>>>(
        B_*N_, C_, C_, at_h, at_l, C_, 0, pw_h, pw_l, C_, 0,
        tmp, C_, 1, 0, nullptr, nullptr, pb, 1.0f, 1);

    /* 12. out1 = x + LN(proj), dual-write */
    add_ln_kernel<<<B_*N_, 256>>>(x, tmp, nw, nb, out1, o1_h, o1_l);

    /* 13. fc1 (MMA) */
    gemm_mma2<<<dim3(64, 16, 1), 256>>>(
        B_*N_, HID_, C_, o1_h, o1_l, C_, 0, f1_h, f1_l, C_, 0,
        h1, HID_, 1, 0, nullptr, nullptr, f1b, 1.0f, 1);

    /* 14. depthwise conv + GELU -> bf16 */
    conv_gelu2<<<dim3(HID_/64, 64, B_), 256>>>(h1, dww, dwb, hg_h, hg_l);

    /* 15. fc2 (MMA, K=1024) */
    gemm_mma2<<<dim3(64, 4, 1), 256>>>(
        B_*N_, C_, HID_, hg_h, hg_l, HID_, 0, f2_h, f2_l, HID_, 0,
        tmp, C_, 1, 0, nullptr, nullptr, f2b, 1.0f, 1);

    /* 16. out = out1 + LN(fc2) */
    add_ln_kernel<<<B_*N_, 256>>>(out1, tmp, nw, nb, out_main, nullptr, nullptr);
}

// round 13
// speedup vs baseline: 2.0940x; 1.0521x over previous
#include <cuda_runtime.h>
#include <cuda_bf16.h>
#include <math.h>

#define B_   2
#define N_   4096
#define C_   256
#define NC_  150
#define T_   4
#define HID_ 1024
#define R_   16384   /* T_*N_ */
#define KS_  320     /* padded 2*NC_ for cxz MMA */
#define PL_  160     /* padded NC_ for attention P */
#define CLTS 152     /* padded row stride of clt_rm */

typedef long long ll;
typedef __nv_bfloat16 bf16;

/* ---------------- scratch (device globals) ------------------------------- */
__device__ float g_clt [B_*R_*CLTS];     /* r-major, padded */
__device__ float g_cen [B_*T_*NC_*C_];
__device__ float g_cin [B_*NC_*C_];
__device__ float g_P   [B_*8*N_*PL_];
__device__ float g_tmp [B_*N_*C_];
__device__ float g_out1[B_*N_*C_];
__device__ float g_h1  [B_*N_*HID_];

/* bf16 hi/lo operand buffers — 16B aligned (float4 / cp.async reads) */
__device__ __align__(16) bf16 g_xf_h [B_*T_*N_*C_];
__device__ __align__(16) bf16 g_xf_l [B_*T_*N_*C_];
__device__ __align__(16) bf16 g_xfT_h[B_*T_*C_*N_];
__device__ __align__(16) bf16 g_xfT_l[B_*T_*C_*N_];
__device__ __align__(16) bf16 g_S_h  [B_*R_*KS_];
__device__ __align__(16) bf16 g_S_l  [B_*R_*KS_];
__device__ __align__(16) bf16 g_tc_h [NC_*KS_];
__device__ __align__(16) bf16 g_tc_l [NC_*KS_];
__device__ __align__(16) bf16 g_sf_h [B_*T_*NC_*N_];
__device__ __align__(16) bf16 g_sf_l [B_*T_*NC_*N_];
__device__ __align__(16) bf16 g_x_h  [B_*N_*C_];
__device__ __align__(16) bf16 g_x_l  [B_*N_*C_];
__device__ __align__(16) bf16 g_q_h  [B_*N_*C_];
__device__ __align__(16) bf16 g_q_l  [B_*N_*C_];
__device__ __align__(16) bf16 g_k_h  [B_*NC_*C_];
__device__ __align__(16) bf16 g_k_l  [B_*NC_*C_];
__device__ __align__(16) bf16 g_vt_h [B_*8*32*PL_];
__device__ __align__(16) bf16 g_vt_l [B_*8*32*PL_];
__device__ __align__(16) bf16 g_P_h  [B_*8*N_*PL_];
__device__ __align__(16) bf16 g_P_l  [B_*8*N_*PL_];
__device__ __align__(16) bf16 g_atn_h[B_*N_*C_];
__device__ __align__(16) bf16 g_atn_l[B_*N_*C_];
__device__ __align__(16) bf16 g_o1_h [B_*N_*C_];
__device__ __align__(16) bf16 g_o1_l [B_*N_*C_];
__device__ __align__(16) bf16 g_hg_h [B_*N_*HID_];
__device__ __align__(16) bf16 g_hg_l [B_*N_*HID_];
__device__ __align__(16) bf16 g_cw_h [NC_*C_];
__device__ __align__(16) bf16 g_cw_l [NC_*C_];
__device__ __align__(16) bf16 g_qw_h [C_*C_];
__device__ __align__(16) bf16 g_qw_l [C_*C_];
__device__ __align__(16) bf16 g_pw_h [C_*C_];
__device__ __align__(16) bf16 g_pw_l [C_*C_];
__device__ __align__(16) bf16 g_f1_h [HID_*C_];
__device__ __align__(16) bf16 g_f1_l [HID_*C_];
__device__ __align__(16) bf16 g_f2_h [C_*HID_];
__device__ __align__(16) bf16 g_f2_l [C_*HID_];

__device__ __forceinline__ float blockSum256(float v, float* sh) {
    #pragma unroll
    for (int o = 16; o; o >>= 1) v += __shfl_xor_sync(0xffffffffu, v, o);
    if ((threadIdx.x & 31) == 0) sh[threadIdx.x >> 5] = v;
    __syncthreads();
    float r = sh[0]+sh[1]+sh[2]+sh[3]+sh[4]+sh[5]+sh[6]+sh[7];
    __syncthreads();
    return r;
}

__device__ __forceinline__ void split_store(float v, bf16* h, bf16* l, ll idx) {
    bf16 hh = __float2bfloat16(v);
    h[idx] = hh;
    l[idx] = __float2bfloat16(v - __bfloat162float(hh));
}
__device__ __forceinline__ void split_pair(float v, bf16& h, bf16& l) {
    h = __float2bfloat16(v);
    l = __float2bfloat16(v - __bfloat162float(h));
}

/* ---------------- cp.async helpers ---------------------------------------- */
__device__ __forceinline__ void cp16(unsigned dst, const void* src, bool pred) {
    int sz = pred ? 16 : 0;
    asm volatile("cp.async.ca.shared.global [%0], [%1], 16, %2;"
                 :: "r"(dst), "l"(src), "r"(sz));
}
__device__ __forceinline__ void cp_commit() {
    asm volatile("cp.async.commit_group;");
}
__device__ __forceinline__ void cp_wait0() {
    asm volatile("cp.async.wait_group 0;");
}

__global__ void zero_kernel(float* p, int n) {
    int i = blockIdx.x * 256 + threadIdx.x;
    if (i < n) p[i] = 0.f;
}
__global__ void zero_bf2(bf16* a, bf16* b, int n) {
    int i = blockIdx.x * 256 + threadIdx.x;
    if (i < n) { a[i] = __float2bfloat16(0.f); b[i] = __float2bfloat16(0.f); }
}

/* ---------------- fused fp32 -> bf16 hi/lo split (6 segments) -------------- */
struct CvtJob { const float4* s; bf16* h; bf16* l; int n4; };
__global__ void cvt_multi(CvtJob j0, CvtJob j1, CvtJob j2,
                          CvtJob j3, CvtJob j4, CvtJob j5) {
    CvtJob j;
    switch (blockIdx.y) {
        case 0: j = j0; break;
        case 1: j = j1; break;
        case 2: j = j2; break;
        case 3: j = j3; break;
        case 4: j = j4; break;
        default: j = j5; break;
    }
    int i = blockIdx.x * 256 + threadIdx.x;
    if (i >= j.n4) return;
    float4 v = j.s[i];
    float vv[4] = {v.x, v.y, v.z, v.w};
    #pragma unroll
    for (int u = 0; u < 4; u++) split_store(vv[u], j.h, j.l, (ll)i*4 + u);
}

/* ---------------- tcat hi/lo ----------------------------------------------- */
__global__ void build_tcat(const float* __restrict__ t1, const float* __restrict__ t2,
                           bf16* __restrict__ th, bf16* __restrict__ tl) {
    int idx = blockIdx.x * 256 + threadIdx.x;
    if (idx >= NC_ * KS_) return;
    int kp = idx / KS_, j = idx % KS_;
    float v = 0.f;
    if (j < NC_)        v = t1[j * NC_ + kp];
    else if (j < 2*NC_) v = t2[(j - NC_) * NC_ + kp];
    split_store(v, th, tl, idx);
}

/* ---------------- fused xf: row-major + transposed bf16 hi/lo -------------- */
__global__ void build_xf_all(const float* __restrict__ x, const float* __restrict__ mem,
                             bf16* __restrict__ xh, bf16* __restrict__ xl,
                             bf16* __restrict__ oth, bf16* __restrict__ otl) {
    __shared__ float tile[32][65];
    int bt = blockIdx.z;
    int b = bt >> 2, t = bt & 3;
    const float* src = (t < 3) ? (mem + ((ll)(b*3 + t)) * N_ * C_)
                               : (x   + ((ll)b) * N_ * C_);
    int n0 = blockIdx.x * 64, c0 = blockIdx.y * 32;
    int tid = threadIdx.x;
    for (int i = tid; i < 32 * 64; i += 256) {
        int cl = i & 31, nl = i >> 5;
        tile[cl][nl] = src[((ll)(n0 + nl)) * C_ + c0 + cl];
    }
    __syncthreads();
    /* transposed output: [bt][c][n] */
    {
        int cl = tid >> 3, nseg = (tid & 7) * 8;
        __align__(16) bf16 hb[8], lb[8];
        #pragma unroll
        for (int u = 0; u < 8; u++) split_pair(tile[cl][nseg + u], hb[u], lb[u]);
        ll off = ((ll)bt * C_ + c0 + cl) * N_ + n0 + nseg;
        *(uint4*)&oth[off] = *(const uint4*)hb;
        *(uint4*)&otl[off] = *(const uint4*)lb;
    }
    /* row-major output: [bt][n][c] */
    {
        int nl = tid >> 2, cseg = (tid & 3) * 8;
        __align__(16) bf16 hb[8], lb[8];
        #pragma unroll
        for (int u = 0; u < 8; u++) split_pair(tile[cseg + u][nl], hb[u], lb[u]);
        ll off = ((ll)bt * N_ + n0 + nl) * C_ + c0 + cseg;
        *(uint4*)&xh[off] = *(const uint4*)hb;
        *(uint4*)&xl[off] = *(const uint4*)lb;
    }
}

/* ---------------- fused scales + S build (clt is r-major) ------------------ */
__global__ void build_S2(const float* __restrict__ z, const float* __restrict__ clt,
                         const float* __restrict__ p1, const float* __restrict__ p2,
                         bf16* __restrict__ sh_, bf16* __restrict__ sl_) {
    __shared__ float tile[32][65];
    __shared__ float s1s[64], s2s[64];
    __shared__ float p1s[NC_], p2s[NC_], pn[2];
    int b = blockIdx.y;
    int r0 = blockIdx.x * 64;
    int tid = threadIdx.x;
    if (tid < NC_) { p1s[tid] = p1[tid]; p2s[tid] = p2[tid]; }
    if (tid < 2) {
        const float* p = tid ? p2 : p1;
        float s = 0.f;
        for (int k = 0; k < NC_; k++) s += p[k]*p[k];
        pn[tid] = 1.0f / fmaxf(sqrtf(s), 1e-12f);
    }
    __syncthreads();
    /* phase A: cosine scales, 4 threads per r */
    {
        int rl = tid >> 2, sub = tid & 3;
        int r = r0 + rl;
        const float* zb = z   + (ll)b * NC_ * R_ + r;
        const float* cb = clt + ((ll)b * R_ + r) * CLTS;
        float zz = 0.f, zp = 0.f, cc = 0.f, cp = 0.f;
        for (int j = sub; j < NC_; j += 4) {
            float zv = zb[(ll)j * R_];
            float cv = cb[j];
            zz += zv*zv; zp += zv*p1s[j];
            cc += cv*cv; cp += cv*p2s[j];
        }
        #pragma unroll
        for (int o = 2; o; o >>= 1) {
            zz += __shfl_down_sync(0xffffffffu, zz, o, 4);
            zp += __shfl_down_sync(0xffffffffu, zp, o, 4);
            cc += __shfl_down_sync(0xffffffffu, cc, o, 4);
            cp += __shfl_down_sync(0xffffffffu, cp, o, 4);
        }
        if (sub == 0) {
            float s1v = zp * pn[0] / fmaxf(sqrtf(zz), 1e-12f);
            float s2v = cp * pn[1] / fmaxf(sqrtf(cc), 1e-12f);
            s1s[rl] = fminf(fmaxf(s1v, 0.f), 1.f);
            s2s[rl] = fminf(fmaxf(s2v, 0.f), 1.f);
        }
    }
    __syncthreads();
    /* phase B1: z chunks via smem transpose (j0 = 0..128; chunk 4 mixed) */
    for (int jc = 0; jc < 5; jc++) {
        int j0 = jc * 32;
        for (int i = tid; i < 32 * 64; i += 256) {
            int rl = i & 63, jl = i >> 6;
            int j = j0 + jl;
            float v;
            if (j < NC_)
                v = z[((ll)b * NC_ + j) * R_ + r0 + rl] * s1s[rl];
            else
                v = clt[((ll)b * R_ + r0 + rl) * CLTS + (j - NC_)] * s2s[rl];
            tile[jl][rl] = v;
        }
        __syncthreads();
        int rl = tid >> 2, jseg = (tid & 3) * 8;
        __align__(16) bf16 hb[8], lb[8];
        #pragma unroll
        for (int u = 0; u < 8; u++) split_pair(tile[jseg + u][rl], hb[u], lb[u]);
        ll off = ((ll)b * R_ + r0 + rl) * KS_ + j0 + jseg;
        *(uint4*)&sh_[off] = *(const uint4*)hb;
        *(uint4*)&sl_[off] = *(const uint4*)lb;
        __syncthreads();
    }
    /* phase B2: clt chunks, direct coalesced copy (j0 = 160..288) */
    {
        int rl = tid >> 2, jseg = (tid & 3) * 8;
        const float* crow = clt + ((ll)b * R_ + r0 + rl) * CLTS;
        float s2v = s2s[rl];
        for (int j0 = 160; j0 < KS_; j0 += 32) {
            __align__(16) bf16 hb[8], lb[8];
            #pragma unroll
            for (int u = 0; u < 8; u++) {
                int j = j0 + jseg + u;
                float v = (j < 2*NC_) ? crow[j - NC_] * s2v : 0.f;
                split_pair(v, hb[u], lb[u]);
            }
            ll off = ((ll)b * R_ + r0 + rl) * KS_ + j0 + jseg;
            *(uint4*)&sh_[off] = *(const uint4*)hb;
            *(uint4*)&sl_[off] = *(const uint4*)lb;
        }
    }
}

/* ---------------- pipelined pre-split bf16 tensor-core GEMM ----------------
 * out = alpha*(A·W^T + bias); fp32 out (Cp, nullable) and/or bf16 hi/lo
 * dual-write (Oh/Ol, same strides). 2-stage cp.async. (K/ksplit)%32==0.   */
__global__ void gemm_mma2(int M, int N, int K,
                          const bf16* __restrict__ Ah_, const bf16* __restrict__ Al_,
                          int lda, ll bsA,
                          const bf16* __restrict__ Wh_, const bf16* __restrict__ Wl_,
                          int ldw, ll bsW,
                          float* __restrict__ Cp, ll crs, ll ccs, ll bsC,
                          bf16* __restrict__ Oh, bf16* __restrict__ Ol,
                          const float* __restrict__ bias, float alpha, int ksplit) {
    constexpr int BM = 128, BN = 64, BK = 32, PAD = 40;
    constexpr int ASZ = BM * PAD, BSZ = BN * PAD;
    __shared__ __align__(16) bf16 Ah[2*ASZ], Al[2*ASZ];
    __shared__ __align__(16) bf16 Bh[2*BSZ], Bl[2*BSZ];
    int zz = blockIdx.z, bt = zz / ksplit, ks = zz - bt * ksplit;
    Ah_ += (ll)bt * bsA;  Al_ += (ll)bt * bsA;
    Wh_ += (ll)bt * bsW;  Wl_ += (ll)bt * bsW;
    if (Cp) Cp += (ll)bt * bsC;
    if (Oh) { Oh += (ll)bt * bsC; Ol += (ll)bt * bsC; }
    int Kc = K / ksplit;
    int kbeg = ks * Kc;
    int niter = Kc / BK;
    int m0 = blockIdx.x * BM, n0 = blockIdx.y * BN;
    int tid = threadIdx.x;
    int wid = tid >> 5, lane = tid & 31;
    int wm = wid >> 1, wn = wid & 1;
    int lq = lane >> 2, lr = lane & 3;

    unsigned sAh = (unsigned)__cvta_generic_to_shared(Ah);
    unsigned sAl = (unsigned)__cvta_generic_to_shared(Al);
    unsigned sBh = (unsigned)__cvta_generic_to_shared(Bh);
    unsigned sBl = (unsigned)__cvta_generic_to_shared(Bl);

    int arow0 = tid >> 2, aq0 = tid & 3;
    int arow1 = arow0 + 64;
    int brow = tid >> 2, bq = tid & 3;
    bool am0 = (m0 + arow0) < M, am1 = (m0 + arow1) < M;
    bool bn  = (n0 + brow) < N;

    auto load_stage = [&](int k0, int st) {
        {
            ll g = (ll)(m0 + arow0) * lda + k0 + aq0 * 8;
            unsigned d = (st*ASZ + arow0 * PAD + aq0 * 8) * 2;
            cp16(sAh + d, Ah_ + g, am0);
            cp16(sAl + d, Al_ + g, am0);
        }
        {
            ll g = (ll)(m0 + arow1) * lda + k0 + aq0 * 8;
            unsigned d = (st*ASZ + arow1 * PAD + aq0 * 8) * 2;
            cp16(sAh + d, Ah_ + g, am1);
            cp16(sAl + d, Al_ + g, am1);
        }
        {
            ll g = (ll)(n0 + brow) * ldw + k0 + bq * 8;
            unsigned d = (st*BSZ + brow * PAD + bq * 8) * 2;
            cp16(sBh + d, Wh_ + g, bn);
            cp16(sBl + d, Wl_ + g, bn);
        }
        cp_commit();
    };

    float acc[2][4][4];
    #pragma unroll
    for (int im = 0; im < 2; im++)
        #pragma unroll
        for (int jn = 0; jn < 4; jn++)
            #pragma unroll
            for (int c = 0; c < 4; c++) acc[im][jn][c] = 0.f;

    load_stage(kbeg, 0);

    for (int it = 0; it < niter; it++) {
        cp_wait0();
        __syncthreads();
        if (it + 1 < niter) load_stage(kbeg + (it + 1) * BK, (it + 1) & 1);
        int st = it & 1;
        const bf16* cAh = Ah + st * ASZ;
        const bf16* cAl = Al + st * ASZ;
        const bf16* cBh = Bh + st * BSZ;
        const bf16* cBl = Bl + st * BSZ;

        #pragma unroll
        for (int kc = 0; kc < 2; kc++) {
            int cb = kc * 16 + lr * 2;
            unsigned ah[2][4], al[2][4], bh[4][2], bl[4][2];
            #pragma unroll
            for (int im = 0; im < 2; im++) {
                int r = wm * 32 + im * 16 + lq;
                ah[im][0] = *(const unsigned*)&cAh[ r      * PAD + cb    ];
                ah[im][1] = *(const unsigned*)&cAh[(r + 8) * PAD + cb    ];
                ah[im][2] = *(const unsigned*)&cAh[ r      * PAD + cb + 8];
                ah[im][3] = *(const unsigned*)&cAh[(r + 8) * PAD + cb + 8];
                al[im][0] = *(const unsigned*)&cAl[ r      * PAD + cb    ];
                al[im][1] = *(const unsigned*)&cAl[(r + 8) * PAD + cb    ];
                al[im][2] = *(const unsigned*)&cAl[ r      * PAD + cb + 8];
                al[im][3] = *(const unsigned*)&cAl[(r + 8) * PAD + cb + 8];
            }
            #pragma unroll
            for (int jn = 0; jn < 4; jn++) {
                int n = wn * 32 + jn * 8 + lq;
                bh[jn][0] = *(const unsigned*)&cBh[n * PAD + cb    ];
                bh[jn][1] = *(const unsigned*)&cBh[n * PAD + cb + 8];
                bl[jn][0] = *(const unsigned*)&cBl[n * PAD + cb    ];
                bl[jn][1] = *(const unsigned*)&cBl[n * PAD + cb + 8];
            }
            #pragma unroll
            for (int im = 0; im < 2; im++)
                #pragma unroll
                for (int jn = 0; jn < 4; jn++) {
                    float* cc = acc[im][jn];
                    asm volatile(
                        "mma.sync.aligned.m16n8k16.row.col.f32.bf16.bf16.f32 "
                        "{%0,%1,%2,%3}, {%4,%5,%6,%7}, {%8,%9}, {%0,%1,%2,%3};"
                        : "+f"(cc[0]), "+f"(cc[1]), "+f"(cc[2]), "+f"(cc[3])
                        : "r"(ah[im][0]), "r"(ah[im][1]), "r"(ah[im][2]), "r"(ah[im][3]),
                          "r"(bh[jn][0]), "r"(bh[jn][1]));
                    asm volatile(
                        "mma.sync.aligned.m16n8k16.row.col.f32.bf16.bf16.f32 "
                        "{%0,%1,%2,%3}, {%4,%5,%6,%7}, {%8,%9}, {%0,%1,%2,%3};"
                        : "+f"(cc[0]), "+f"(cc[1]), "+f"(cc[2]), "+f"(cc[3])
                        : "r"(ah[im][0]), "r"(ah[im][1]), "r"(ah[im][2]), "r"(ah[im][3]),
                          "r"(bl[jn][0]), "r"(bl[jn][1]));
                    asm volatile(
                        "mma.sync.aligned.m16n8k16.row.col.f32.bf16.bf16.f32 "
                        "{%0,%1,%2,%3}, {%4,%5,%6,%7}, {%8,%9}, {%0,%1,%2,%3};"
                        : "+f"(cc[0]), "+f"(cc[1]), "+f"(cc[2]), "+f"(cc[3])
                        : "r"(al[im][0]), "r"(al[im][1]), "r"(al[im][2]), "r"(al[im][3]),
                          "r"(bh[jn][0]), "r"(bh[jn][1]));
                }
        }
        __syncthreads();
    }

    #pragma unroll
    for (int im = 0; im < 2; im++) {
        int mb = m0 + wm * 32 + im * 16 + lq;
        #pragma unroll
        for (int jn = 0; jn < 4; jn++) {
            int nb = n0 + wn * 32 + jn * 8 + lr * 2;
            float b0 = 0.f, b1 = 0.f;
            if (bias && ks == 0) {
                if (nb     < N) b0 = bias[nb];
                if (nb + 1 < N) b1 = bias[nb + 1];
            }
            float* cc = acc[im][jn];
            #pragma unroll
            for (int half = 0; half < 2; half++) {
                int m = mb + half * 8;
                if (m >= M) continue;
                #pragma unroll
                for (int e = 0; e < 2; e++) {
                    int n = nb + e;
                    if (n >= N) continue;
                    float r = (cc[half*2 + e] + (e ? b1 : b0)) * alpha;
                    ll off = (ll)m * crs + (ll)n * ccs;
                    if (Cp) {
                        if (ksplit == 1) Cp[off] = r;
                        else atomicAdd(&Cp[off], r);
                    }
                    if (Oh) split_store(r, Oh, Ol, off);
                }
            }
        }
    }
}

/* ---------------- softmax: asn copy + soft bf16 hi/lo --------------------- */
__global__ void softmax_rows2(const float* __restrict__ cxz,
                              float* __restrict__ asn,
                              bf16* __restrict__ sfh, bf16* __restrict__ sfl) {
    int row = blockIdx.x;
    int b = row / 600; int rem = row - b * 600;
    int t = rem / NC_; int k = rem - t * NC_;
    const float* s = cxz + ((ll)(b * NC_ + k)) * R_ + (ll)t * N_;
    ll drow = ((ll)((b * T_ + t) * NC_ + k)) * N_;
    __shared__ float sh[8];
    int tid = threadIdx.x;
    float mx = -1e30f;
    for (int i = tid; i < N_; i += 256) mx = fmaxf(mx, s[i]);
    #pragma unroll
    for (int o = 16; o; o >>= 1) mx = fmaxf(mx, __shfl_xor_sync(0xffffffffu, mx, o));
    if ((tid & 31) == 0) sh[tid >> 5] = mx;
    __syncthreads();
    mx = fmaxf(fmaxf(fmaxf(sh[0],sh[1]),fmaxf(sh[2],sh[3])),
               fmaxf(fmaxf(sh[4],sh[5]),fmaxf(sh[6],sh[7])));
    __syncthreads();
    float sum = 0.f;
    for (int i = tid; i < N_; i += 256) sum += expf(s[i] - mx);
    sum = blockSum256(sum, sh);
    float inv = 1.0f / sum;
    for (int i = tid; i < N_; i += 256) {
        float v = s[i];
        asn[drow + i] = v;
        split_store(expf(v - mx) * inv, sfh, sfl, drow + i);
    }
}

/* ---------------- P softmax: warp per row, write padded bf16 --------------- */
__global__ void p_softmax(const float* __restrict__ P,
                          bf16* __restrict__ ph, bf16* __restrict__ pl) {
    int row = blockIdx.x * 8 + (threadIdx.x >> 5);
    int lane = threadIdx.x & 31;
    const float* p = P + (ll)row * PL_;
    float v[5];
    float mx = -1e30f;
    #pragma unroll
    for (int u = 0; u < 5; u++) {
        int i = lane + u * 32;
        v[u] = (i < NC_) ? p[i] : -1e30f;
        mx = fmaxf(mx, v[u]);
    }
    #pragma unroll
    for (int o = 16; o; o >>= 1) mx = fmaxf(mx, __shfl_xor_sync(0xffffffffu, mx, o));
    float sum = 0.f;
    #pragma unroll
    for (int u = 0; u < 5; u++) {
        int i = lane + u * 32;
        v[u] = (i < NC_) ? expf(v[u] - mx) : 0.f;
        sum += v[u];
    }
    #pragma unroll
    for (int o = 16; o; o >>= 1) sum += __shfl_xor_sync(0xffffffffu, sum, o);
    float inv = 1.0f / sum;
    #pragma unroll
    for (int u = 0; u < 5; u++) {
        int i = lane + u * 32;
        if (i < PL_) split_store(v[u] * inv, ph, pl, (ll)row * PL_ + i);
    }
}

/* ---------------- gate + LayerNorm --------------------------------------- */
__global__ void gate_ln_kernel(const float* __restrict__ cen,
                               const float* __restrict__ nw, const float* __restrict__ nb,
                               const float* __restrict__ salpha, const float* __restrict__ sbeta,
                               float* __restrict__ cin_out) {
    int k = blockIdx.x, b = blockIdx.y, c = threadIdx.x;
    __shared__ float sh[8];
    float pv[4];
    #pragma unroll
    for (int t = 0; t < 4; t++)
        pv[t] = cen[(((ll)b*4 + t) * NC_ + k) * C_ + c];
    float last = pv[3];
    float ll2 = blockSum256(last*last, sh);
    float cin = last;
    float alpha = salpha[0], beta = sbeta[0];
    for (int t = 0; t < 3; t++) {
        float dt = blockSum256(last * pv[t], sh);
        float pp = blockSum256(pv[t] * pv[t], sh);
        float denom = fmaxf(sqrtf(ll2) * sqrtf(pp), 1e-8f);
        float gate = 1.0f / (1.0f + expf(-(beta + alpha * (dt / denom))));
        cin += gate * pv[t];
    }
    float m  = blockSum256(cin, sh) * (1.0f / C_);
    float dv = cin - m;
    float var = blockSum256(dv*dv, sh) * (1.0f / C_);
    cin_out[((ll)b*NC_ + k) * C_ + c] = dv * rsqrtf(var + 1e-5f) * nw[c] + nb[c];
}

/* ---------------- K/V projections -> bf16 (K rows, V transposed) ----------- */
__global__ void kv_kernel(const float* __restrict__ cin,
                          const float* __restrict__ kw, const float* __restrict__ kb,
                          const float* __restrict__ vw, const float* __restrict__ vb,
                          bf16* __restrict__ kh, bf16* __restrict__ kl,
                          bf16* __restrict__ vth, bf16* __restrict__ vtl) {
    int row = blockIdx.x, c = threadIdx.x;
    int b = row / NC_, kk = row - b * NC_;
    __shared__ float ci[C_];
    ci[c] = cin[(ll)row * C_ + c];
    __syncthreads();
    float ka = kb[c], va = vb[c];
    const float* kwr = kw + (ll)c * C_;
    const float* vwr = vw + (ll)c * C_;
    #pragma unroll 4
    for (int j = 0; j < C_; j++) {
        float cv = ci[j];
        ka += cv * kwr[j];
        va += cv * vwr[j];
    }
    split_store(ka, kh, kl, (ll)row * C_ + c);
    int h = c >> 5, nn = c & 31;
    ll vt = ((ll)(b * 8 + h) * 32 + nn) * PL_ + kk;
    split_store(va, vth, vtl, vt);
}

/* ---------------- depthwise 3x3 conv + GELU -> bf16 hi/lo ----------------- */
__global__ void conv_gelu2(const float* __restrict__ h,
                           const float* __restrict__ dww, const float* __restrict__ dwb,
                           bf16* __restrict__ oh, bf16* __restrict__ ol) {
    __shared__ float patch[10][10][64];
    int ch0 = blockIdx.x * 64;
    int tileid = blockIdx.y;
    int y0 = (tileid >> 3) * 8, x0 = (tileid & 7) * 8;
    int b = blockIdx.z;
    int tid = threadIdx.x;
    for (int i = tid; i < 6400; i += 256) {
        int c = i & 63, sp = i >> 6;
        int py = sp / 10, px = sp % 10;
        int yy = y0 + py - 1, xx = x0 + px - 1;
        float v = 0.f;
        if (yy >= 0 && yy < 64 && xx >= 0 && xx < 64)
            v = h[(((ll)b*N_) + (yy*64 + xx)) * HID_ + ch0 + c];
        patch[py][px][c] = v;
    }
    __syncthreads();
    int c = tid & 63, sub = tid >> 6;
    float w[9];
    #pragma unroll
    for (int i = 0; i < 9; i++) w[i] = dww[(ch0 + c)*9 + i];
    float bv = dwb[ch0 + c];
    for (int oy = sub; oy < 8; oy += 4) {
        #pragma unroll
        for (int ox = 0; ox < 8; ox++) {
            float a = bv;
            #pragma unroll
            for (int dy = 0; dy < 3; dy++)
                #pragma unroll
                for (int dx = 0; dx < 3; dx++)
                    a += patch[oy+dy][ox+dx][c] * w[dy*3+dx];
            float g = 0.5f * a * (1.0f + erff(a * 0.7071067811865475f));
            split_store(g, oh, ol, (((ll)b*N_) + ((y0+oy)*64 + x0+ox)) * HID_ + ch0 + c);
        }
    }
}

/* ---------------- residual + LayerNorm (optional bf16 dual-write) ---------- */
__global__ void add_ln_kernel(const float* __restrict__ res, const float* __restrict__ val,
                              const float* __restrict__ nw, const float* __restrict__ nb,
                              float* __restrict__ dst,
                              bf16* __restrict__ dh, bf16* __restrict__ dl) {
    ll row = blockIdx.x;
    int c = threadIdx.x;
    __shared__ float sh[8];
    float v = val[row * C_ + c];
    float m = blockSum256(v, sh) * (1.0f / C_);
    float d = v - m;
    float var = blockSum256(d*d, sh) * (1.0f / C_);
    float r = res[row * C_ + c] + d * rsqrtf(var + 1e-5f) * nw[c] + nb[c];
    dst[row * C_ + c] = r;
    if (dh) split_store(r, dh, dl, row * C_ + c);
}

/* ---------------- host launch --------------------------------------------- */
static float* symaddr(const void* sym) {
    void* p = nullptr;
    cudaGetSymbolAddress(&p, sym);
    return (float*)p;
}
static bf16* symaddrb(const void* sym) {
    void* p = nullptr;
    cudaGetSymbolAddress(&p, sym);
    return (bf16*)p;
}

extern "C" void kernel_launch(void* const* d_in, const int* in_sizes, int n_in,
                              void* d_out, int out_size) {
    const float* x    = (const float*)d_in[0];
    const float* z    = (const float*)d_in[1];
    const float* mem  = (const float*)d_in[2];
    const float* cw   = (const float*)d_in[3];
    const float* p1   = (const float*)d_in[4];
    const float* t1   = (const float*)d_in[5];
    const float* p2   = (const float*)d_in[6];
    const float* t2   = (const float*)d_in[7];
    const float* sal  = (const float*)d_in[8];
    const float* sbe  = (const float*)d_in[9];
    const float* qw   = (const float*)d_in[10];
    const float* qb   = (const float*)d_in[11];
    const float* kw   = (const float*)d_in[12];
    const float* kb   = (const float*)d_in[13];
    const float* vw   = (const float*)d_in[14];
    const float* vb   = (const float*)d_in[15];
    const float* pw   = (const float*)d_in[16];
    const float* pb   = (const float*)d_in[17];
    const float* nw   = (const float*)d_in[18];
    const float* nb   = (const float*)d_in[19];
    const float* f1w  = (const float*)d_in[20];
    const float* f1b  = (const float*)d_in[21];
    const float* dww  = (const float*)d_in[22];
    const float* dwb  = (const float*)d_in[23];
    const float* f2w  = (const float*)d_in[24];
    const float* f2b  = (const float*)d_in[25];

    float* out_main = (float*)d_out;
    float* out_cxz  = out_main + (ll)B_*N_*C_;
    float* out_asn  = out_cxz  + (ll)B_*NC_*R_;

    float* clt  = symaddr(g_clt);
    float* cen  = symaddr(g_cen);
    float* cin  = symaddr(g_cin);
    float* Pf   = symaddr(g_P);
    float* tmp  = symaddr(g_tmp);
    float* out1 = symaddr(g_out1);
    float* h1   = symaddr(g_h1);

    bf16 *xf_h = symaddrb(g_xf_h), *xf_l = symaddrb(g_xf_l);
    bf16 *xT_h = symaddrb(g_xfT_h),*xT_l = symaddrb(g_xfT_l);
    bf16 *S_h  = symaddrb(g_S_h),  *S_l  = symaddrb(g_S_l);
    bf16 *tc_h = symaddrb(g_tc_h), *tc_l = symaddrb(g_tc_l);
    bf16 *sf_h = symaddrb(g_sf_h), *sf_l = symaddrb(g_sf_l);
    bf16 *x_h  = symaddrb(g_x_h),  *x_l  = symaddrb(g_x_l);
    bf16 *q_h  = symaddrb(g_q_h),  *q_l  = symaddrb(g_q_l);
    bf16 *k_h  = symaddrb(g_k_h),  *k_l  = symaddrb(g_k_l);
    bf16 *vt_h = symaddrb(g_vt_h), *vt_l = symaddrb(g_vt_l);
    bf16 *P_h  = symaddrb(g_P_h),  *P_l  = symaddrb(g_P_l);
    bf16 *at_h = symaddrb(g_atn_h),*at_l = symaddrb(g_atn_l);
    bf16 *o1_h = symaddrb(g_o1_h), *o1_l = symaddrb(g_o1_l);
    bf16 *hg_h = symaddrb(g_hg_h), *hg_l = symaddrb(g_hg_l);
    bf16 *cw_h = symaddrb(g_cw_h), *cw_l = symaddrb(g_cw_l);
    bf16 *qw_h = symaddrb(g_qw_h), *qw_l = symaddrb(g_qw_l);
    bf16 *pw_h = symaddrb(g_pw_h), *pw_l = symaddrb(g_pw_l);
    bf16 *f1_h = symaddrb(g_f1_h), *f1_l = symaddrb(g_f1_l);
    bf16 *f2_h = symaddrb(g_f2_h), *f2_l = symaddrb(g_f2_l);

    /* 0. fused weight + x conversions (one launch), tcat */
    {
        CvtJob j0 = {(const float4*)cw,  cw_h, cw_l, NC_*C_/4};
        CvtJob j1 = {(const float4*)qw,  qw_h, qw_l, C_*C_/4};
        CvtJob j2 = {(const float4*)pw,  pw_h, pw_l, C_*C_/4};
        CvtJob j3 = {(const float4*)f1w, f1_h, f1_l, HID_*C_/4};
        CvtJob j4 = {(const float4*)f2w, f2_h, f2_l, HID_*C_/4};
        CvtJob j5 = {(const float4*)x,   x_h,  x_l,  B_*N_*C_/4};
        int mx = HID_*C_/4;
        if (B_*N_*C_/4 > mx) mx = B_*N_*C_/4;
        cvt_multi<<<dim3((mx + 255)/256, 6), 256>>>(j0, j1, j2, j3, j4, j5);
    }
    build_tcat<<<(NC_*KS_ + 255)/256, 256>>>(t1, t2, tc_h, tc_l);

    /* 1. xf: row-major + transposed bf16 (one fused kernel) */
    build_xf_all<<<dim3(N_/64, C_/32, B_*T_), 256>>>(x, mem, xf_h, xf_l, xT_h, xT_l);

    /* 2. clt (MMA, r-major store, coalesced epilogue) */
    gemm_mma2<<<dim3(R_/128, 3, B_), 256>>>(
        R_, NC_, C_, xf_h, xf_l, C_, (ll)R_*C_, cw_h, cw_l, C_, 0,
        clt, CLTS, 1, (ll)R_*CLTS, nullptr, nullptr, nullptr, 1.0f, 1);

    /* 3. fused cosine scales + S build */
    build_S2<<<dim3(R_/64, B_), 256>>>(z, clt, p1, p2, S_h, S_l);

    /* 4. cluster_x_z (MMA: M=R, N=150, K=320, transposed store) */
    gemm_mma2<<<dim3(R_/128, 3, B_), 256>>>(
        R_, NC_, KS_, S_h, S_l, KS_, (ll)R_*KS_, tc_h, tc_l, KS_, 0,
        out_cxz, 1, R_, (ll)NC_*R_, nullptr, nullptr, nullptr, 0.5f, 1);

    /* 5. softmax: asn copy + soft bf16 */
    softmax_rows2<<<B_*T_*NC_, 256>>>(out_cxz, out_asn, sf_h, sf_l);

    /* 6. cen = soft @ xf (MMA, split-K=8 atomic, M=150 guarded) */
    zero_kernel<<<(B_*T_*NC_*C_ + 255)/256, 256>>>(cen, B_*T_*NC_*C_);
    gemm_mma2<<<dim3(2, 4, B_*T_*8), 256>>>(
        NC_, C_, N_, sf_h, sf_l, N_, (ll)NC_*N_, xT_h, xT_l, N_, (ll)C_*N_,
        cen, C_, 1, (ll)NC_*C_, nullptr, nullptr, nullptr, 1.0f, 8);

    /* 7. gate + LN */
    gate_ln_kernel<<<dim3(NC_, B_), 256>>>(cen, nw, nb, sal, sbe, cin);

    /* 8. k,v -> bf16 (Vt padded; zero pad region first) */
    zero_bf2<<<(B_*8*32*PL_ + 255)/256, 256>>>(vt_h, vt_l, B_*8*32*PL_);
    kv_kernel<<<B_*NC_, 256>>>(cin, kw, kb, vw, vb, k_h, k_l, vt_h, vt_l);

    /* 9. q (MMA, bf16 dual-write only) */
    gemm_mma2<<<dim3(64, 4, 1), 256>>>(
        B_*N_, C_, C_, x_h, x_l, C_, 0, qw_h, qw_l, C_, 0,
        nullptr, C_, 1, 0, q_h, q_l, qb, 0.17677669529663687f, 1);

    /* 10a. QK logits (MMA, batched over h; one launch per b) */
    for (int b = 0; b < B_; b++) {
        gemm_mma2<<<dim3(N_/128, 3, 8), 256>>>(
            N_, NC_, 32,
            q_h + (ll)b*N_*C_, q_l + (ll)b*N_*C_, C_, 32,
            k_h + (ll)b*NC_*C_, k_l + (ll)b*NC_*C_, C_, 32,
            Pf + (ll)b*8*N_*PL_, PL_, 1, (ll)N_*PL_,
            nullptr, nullptr, nullptr, 1.0f, 1);
    }

    /* 10b. P softmax -> padded bf16 */
    p_softmax<<<B_*8*N_/8, 256>>>(Pf, P_h, P_l);

    /* 10c. PV (MMA, batched over h; dual-write atn bf16) */
    for (int b = 0; b < B_; b++) {
        gemm_mma2<<<dim3(N_/128, 1, 8), 256>>>(
            N_, 32, PL_,
            P_h + (ll)b*8*N_*PL_, P_l + (ll)b*8*N_*PL_, PL_, (ll)N_*PL_,
            vt_h + (ll)b*8*32*PL_, vt_l + (ll)b*8*32*PL_, PL_, (ll)32*PL_,
            nullptr, C_, 1, 32,
            at_h + (ll)b*N_*C_, at_l + (ll)b*N_*C_, nullptr, 1.0f, 1);
    }

    /* 11. proj (MMA) */
    gemm_mma2<<<dim3(64, 4, 1), 256>>>(
        B_*N_, C_, C_, at_h, at_l, C_, 0, pw_h, pw_l, C_, 0,
        tmp, C_, 1, 0, nullptr, nullptr, pb, 1.0f, 1);

    /* 12. out1 = x + LN(proj), dual-write */
    add_ln_kernel<<<B_*N_, 256>>>(x, tmp, nw, nb, out1, o1_h, o1_l);

    /* 13. fc1 (MMA) */
    gemm_mma2<<<dim3(64, 16, 1), 256>>>(
        B_*N_, HID_, C_, o1_h, o1_l, C_, 0, f1_h, f1_l, C_, 0,
        h1, HID_, 1, 0, nullptr, nullptr, f1b, 1.0f, 1);

    /* 14. depthwise conv + GELU -> bf16 */
    conv_gelu2<<<dim3(HID_/64, 64, B_), 256>>>(h1, dww, dwb, hg_h, hg_l);

    /* 15. fc2 (MMA, K=1024) */
    gemm_mma2<<<dim3(64, 4, 1), 256>>>(
        B_*N_, C_, HID_, hg_h, hg_l, HID_, 0, f2_h, f2_l, HID_, 0,
        tmp, C_, 1, 0, nullptr, nullptr, f2b, 1.0f, 1);

    /* 16. out = out1 + LN(fc2) */
    add_ln_kernel<<<B_*N_, 256>>>(out1, tmp, nw, nb, out_main, nullptr, nullptr);
}

// round 14
// speedup vs baseline: 2.2236x; 1.0619x over previous
#include <cuda_runtime.h>
#include <cuda_bf16.h>
#include <math.h>

#define B_   2
#define N_   4096
#define C_   256
#define NC_  150
#define T_   4
#define HID_ 1024
#define R_   16384   /* T_*N_ */
#define KS_  320     /* padded 2*NC_ for cxz MMA */
#define PL_  160     /* padded NC_ for attention P */
#define CLTS 152     /* padded row stride of clt_rm */

typedef long long ll;
typedef __nv_bfloat16 bf16;

/* ---------------- scratch (device globals) ------------------------------- */
__device__ float g_clt [B_*R_*CLTS];
__device__ float g_cen [B_*T_*NC_*C_];
__device__ float g_cin [B_*NC_*C_];
__device__ float g_P   [B_*8*N_*PL_];
__device__ float g_tmp [B_*N_*C_];
__device__ float g_out1[B_*N_*C_];
__device__ float g_h1  [B_*N_*HID_];

/* bf16 hi/lo operand buffers — 16B aligned */
__device__ __align__(16) bf16 g_xf_h [B_*T_*N_*C_];
__device__ __align__(16) bf16 g_xf_l [B_*T_*N_*C_];
__device__ __align__(16) bf16 g_xfT_h[B_*T_*C_*N_];
__device__ __align__(16) bf16 g_xfT_l[B_*T_*C_*N_];
__device__ __align__(16) bf16 g_S_h  [B_*R_*KS_];
__device__ __align__(16) bf16 g_S_l  [B_*R_*KS_];
__device__ __align__(16) bf16 g_tc_h [NC_*KS_];
__device__ __align__(16) bf16 g_tc_l [NC_*KS_];
__device__ __align__(16) bf16 g_sf_h [B_*T_*NC_*N_];
__device__ __align__(16) bf16 g_sf_l [B_*T_*NC_*N_];
__device__ __align__(16) bf16 g_x_h  [B_*N_*C_];
__device__ __align__(16) bf16 g_x_l  [B_*N_*C_];
__device__ __align__(16) bf16 g_q_h  [B_*N_*C_];
__device__ __align__(16) bf16 g_q_l  [B_*N_*C_];
__device__ __align__(16) bf16 g_k_h  [B_*NC_*C_];
__device__ __align__(16) bf16 g_k_l  [B_*NC_*C_];
__device__ __align__(16) bf16 g_vt_h [B_*8*32*PL_];
__device__ __align__(16) bf16 g_vt_l [B_*8*32*PL_];
__device__ __align__(16) bf16 g_P_h  [B_*8*N_*PL_];
__device__ __align__(16) bf16 g_P_l  [B_*8*N_*PL_];
__device__ __align__(16) bf16 g_atn_h[B_*N_*C_];
__device__ __align__(16) bf16 g_atn_l[B_*N_*C_];
__device__ __align__(16) bf16 g_o1_h [B_*N_*C_];
__device__ __align__(16) bf16 g_o1_l [B_*N_*C_];
__device__ __align__(16) bf16 g_hg_h [B_*N_*HID_];
__device__ __align__(16) bf16 g_hg_l [B_*N_*HID_];
__device__ __align__(16) bf16 g_cw_h [NC_*C_];
__device__ __align__(16) bf16 g_cw_l [NC_*C_];
__device__ __align__(16) bf16 g_qw_h [C_*C_];
__device__ __align__(16) bf16 g_qw_l [C_*C_];
__device__ __align__(16) bf16 g_pw_h [C_*C_];
__device__ __align__(16) bf16 g_pw_l [C_*C_];
__device__ __align__(16) bf16 g_f1_h [HID_*C_];
__device__ __align__(16) bf16 g_f1_l [HID_*C_];
__device__ __align__(16) bf16 g_f2_h [C_*HID_];
__device__ __align__(16) bf16 g_f2_l [C_*HID_];

__device__ __forceinline__ float blockSum256(float v, float* sh) {
    #pragma unroll
    for (int o = 16; o; o >>= 1) v += __shfl_xor_sync(0xffffffffu, v, o);
    if ((threadIdx.x & 31) == 0) sh[threadIdx.x >> 5] = v;
    __syncthreads();
    float r = sh[0]+sh[1]+sh[2]+sh[3]+sh[4]+sh[5]+sh[6]+sh[7];
    __syncthreads();
    return r;
}

__device__ __forceinline__ void split_store(float v, bf16* h, bf16* l, ll idx) {
    bf16 hh = __float2bfloat16(v);
    h[idx] = hh;
    l[idx] = __float2bfloat16(v - __bfloat162float(hh));
}
__device__ __forceinline__ void split_pair(float v, bf16& h, bf16& l) {
    h = __float2bfloat16(v);
    l = __float2bfloat16(v - __bfloat162float(h));
}

/* ---------------- cp.async / ldmatrix helpers ------------------------------ */
__device__ __forceinline__ void cp16(unsigned dst, const void* src, bool pred) {
    int sz = pred ? 16 : 0;
    asm volatile("cp.async.ca.shared.global [%0], [%1], 16, %2;"
                 :: "r"(dst), "l"(src), "r"(sz));
}
__device__ __forceinline__ void cp_commit() {
    asm volatile("cp.async.commit_group;");
}
__device__ __forceinline__ void cp_wait0() {
    asm volatile("cp.async.wait_group 0;");
}
__device__ __forceinline__ void ldsm4(unsigned& d0, unsigned& d1,
                                      unsigned& d2, unsigned& d3, unsigned addr) {
    asm volatile("ldmatrix.sync.aligned.m8n8.x4.shared.b16 {%0,%1,%2,%3}, [%4];"
                 : "=r"(d0), "=r"(d1), "=r"(d2), "=r"(d3) : "r"(addr));
}

__global__ void zero_kernel(float* p, int n) {
    int i = blockIdx.x * 256 + threadIdx.x;
    if (i < n) p[i] = 0.f;
}
__global__ void zero_bf2(bf16* a, bf16* b, int n) {
    int i = blockIdx.x * 256 + threadIdx.x;
    if (i < n) { a[i] = __float2bfloat16(0.f); b[i] = __float2bfloat16(0.f); }
}

/* ---------------- fused fp32 -> bf16 hi/lo split (6 segments) -------------- */
struct CvtJob { const float4* s; bf16* h; bf16* l; int n4; };
__global__ void cvt_multi(CvtJob j0, CvtJob j1, CvtJob j2,
                          CvtJob j3, CvtJob j4, CvtJob j5) {
    CvtJob j;
    switch (blockIdx.y) {
        case 0: j = j0; break;
        case 1: j = j1; break;
        case 2: j = j2; break;
        case 3: j = j3; break;
        case 4: j = j4; break;
        default: j = j5; break;
    }
    int i = blockIdx.x * 256 + threadIdx.x;
    if (i >= j.n4) return;
    float4 v = j.s[i];
    float vv[4] = {v.x, v.y, v.z, v.w};
    #pragma unroll
    for (int u = 0; u < 4; u++) split_store(vv[u], j.h, j.l, (ll)i*4 + u);
}

/* ---------------- tcat hi/lo ----------------------------------------------- */
__global__ void build_tcat(const float* __restrict__ t1, const float* __restrict__ t2,
                           bf16* __restrict__ th, bf16* __restrict__ tl) {
    int idx = blockIdx.x * 256 + threadIdx.x;
    if (idx >= NC_ * KS_) return;
    int kp = idx / KS_, j = idx % KS_;
    float v = 0.f;
    if (j < NC_)        v = t1[j * NC_ + kp];
    else if (j < 2*NC_) v = t2[(j - NC_) * NC_ + kp];
    split_store(v, th, tl, idx);
}

/* ---------------- fused xf: row-major + transposed bf16 hi/lo -------------- */
__global__ void build_xf_all(const float* __restrict__ x, const float* __restrict__ mem,
                             bf16* __restrict__ xh, bf16* __restrict__ xl,
                             bf16* __restrict__ oth, bf16* __restrict__ otl) {
    __shared__ float tile[32][65];
    int bt = blockIdx.z;
    int b = bt >> 2, t = bt & 3;
    const float* src = (t < 3) ? (mem + ((ll)(b*3 + t)) * N_ * C_)
                               : (x   + ((ll)b) * N_ * C_);
    int n0 = blockIdx.x * 64, c0 = blockIdx.y * 32;
    int tid = threadIdx.x;
    for (int i = tid; i < 32 * 64; i += 256) {
        int cl = i & 31, nl = i >> 5;
        tile[cl][nl] = src[((ll)(n0 + nl)) * C_ + c0 + cl];
    }
    __syncthreads();
    {
        int cl = tid >> 3, nseg = (tid & 7) * 8;
        __align__(16) bf16 hb[8], lb[8];
        #pragma unroll
        for (int u = 0; u < 8; u++) split_pair(tile[cl][nseg + u], hb[u], lb[u]);
        ll off = ((ll)bt * C_ + c0 + cl) * N_ + n0 + nseg;
        *(uint4*)&oth[off] = *(const uint4*)hb;
        *(uint4*)&otl[off] = *(const uint4*)lb;
    }
    {
        int nl = tid >> 2, cseg = (tid & 3) * 8;
        __align__(16) bf16 hb[8], lb[8];
        #pragma unroll
        for (int u = 0; u < 8; u++) split_pair(tile[cseg + u][nl], hb[u], lb[u]);
        ll off = ((ll)bt * N_ + n0 + nl) * C_ + c0 + cseg;
        *(uint4*)&xh[off] = *(const uint4*)hb;
        *(uint4*)&xl[off] = *(const uint4*)lb;
    }
}

/* ---------------- fused scales + S build (clt is r-major) ------------------ */
__global__ void build_S2(const float* __restrict__ z, const float* __restrict__ clt,
                         const float* __restrict__ p1, const float* __restrict__ p2,
                         bf16* __restrict__ sh_, bf16* __restrict__ sl_) {
    __shared__ float tile[32][65];
    __shared__ float s1s[64], s2s[64];
    __shared__ float p1s[NC_], p2s[NC_], pn[2];
    int b = blockIdx.y;
    int r0 = blockIdx.x * 64;
    int tid = threadIdx.x;
    if (tid < NC_) { p1s[tid] = p1[tid]; p2s[tid] = p2[tid]; }
    if (tid < 2) {
        const float* p = tid ? p2 : p1;
        float s = 0.f;
        for (int k = 0; k < NC_; k++) s += p[k]*p[k];
        pn[tid] = 1.0f / fmaxf(sqrtf(s), 1e-12f);
    }
    __syncthreads();
    {
        int rl = tid >> 2, sub = tid & 3;
        int r = r0 + rl;
        const float* zb = z   + (ll)b * NC_ * R_ + r;
        const float* cb = clt + ((ll)b * R_ + r) * CLTS;
        float zz = 0.f, zp = 0.f, cc = 0.f, cp = 0.f;
        for (int j = sub; j < NC_; j += 4) {
            float zv = zb[(ll)j * R_];
            float cv = cb[j];
            zz += zv*zv; zp += zv*p1s[j];
            cc += cv*cv; cp += cv*p2s[j];
        }
        #pragma unroll
        for (int o = 2; o; o >>= 1) {
            zz += __shfl_down_sync(0xffffffffu, zz, o, 4);
            zp += __shfl_down_sync(0xffffffffu, zp, o, 4);
            cc += __shfl_down_sync(0xffffffffu, cc, o, 4);
            cp += __shfl_down_sync(0xffffffffu, cp, o, 4);
        }
        if (sub == 0) {
            float s1v = zp * pn[0] / fmaxf(sqrtf(zz), 1e-12f);
            float s2v = cp * pn[1] / fmaxf(sqrtf(cc), 1e-12f);
            s1s[rl] = fminf(fmaxf(s1v, 0.f), 1.f);
            s2s[rl] = fminf(fmaxf(s2v, 0.f), 1.f);
        }
    }
    __syncthreads();
    for (int jc = 0; jc < 5; jc++) {
        int j0 = jc * 32;
        for (int i = tid; i < 32 * 64; i += 256) {
            int rl = i & 63, jl = i >> 6;
            int j = j0 + jl;
            float v;
            if (j < NC_)
                v = z[((ll)b * NC_ + j) * R_ + r0 + rl] * s1s[rl];
            else
                v = clt[((ll)b * R_ + r0 + rl) * CLTS + (j - NC_)] * s2s[rl];
            tile[jl][rl] = v;
        }
        __syncthreads();
        int rl = tid >> 2, jseg = (tid & 3) * 8;
        __align__(16) bf16 hb[8], lb[8];
        #pragma unroll
        for (int u = 0; u < 8; u++) split_pair(tile[jseg + u][rl], hb[u], lb[u]);
        ll off = ((ll)b * R_ + r0 + rl) * KS_ + j0 + jseg;
        *(uint4*)&sh_[off] = *(const uint4*)hb;
        *(uint4*)&sl_[off] = *(const uint4*)lb;
        __syncthreads();
    }
    {
        int rl = tid >> 2, jseg = (tid & 3) * 8;
        const float* crow = clt + ((ll)b * R_ + r0 + rl) * CLTS;
        float s2v = s2s[rl];
        for (int j0 = 160; j0 < KS_; j0 += 32) {
            __align__(16) bf16 hb[8], lb[8];
            #pragma unroll
            for (int u = 0; u < 8; u++) {
                int j = j0 + jseg + u;
                float v = (j < 2*NC_) ? crow[j - NC_] * s2v : 0.f;
                split_pair(v, hb[u], lb[u]);
            }
            ll off = ((ll)b * R_ + r0 + rl) * KS_ + j0 + jseg;
            *(uint4*)&sh_[off] = *(const uint4*)hb;
            *(uint4*)&sl_[off] = *(const uint4*)lb;
        }
    }
}

/* ---------------- pipelined pre-split bf16 tensor-core GEMM ----------------
 * ldmatrix fragment loads; single barrier per BK; 2-stage cp.async.        */
__global__ void gemm_mma2(int M, int N, int K,
                          const bf16* __restrict__ Ah_, const bf16* __restrict__ Al_,
                          int lda, ll bsA,
                          const bf16* __restrict__ Wh_, const bf16* __restrict__ Wl_,
                          int ldw, ll bsW,
                          float* __restrict__ Cp, ll crs, ll ccs, ll bsC,
                          bf16* __restrict__ Oh, bf16* __restrict__ Ol,
                          const float* __restrict__ bias, float alpha, int ksplit) {
    constexpr int BM = 128, BN = 64, BK = 32, PAD = 40;
    constexpr int ASZ = BM * PAD, BSZ = BN * PAD;
    __shared__ __align__(16) bf16 Ah[2*ASZ], Al[2*ASZ];
    __shared__ __align__(16) bf16 Bh[2*BSZ], Bl[2*BSZ];
    int zz = blockIdx.z, bt = zz / ksplit, ks = zz - bt * ksplit;
    Ah_ += (ll)bt * bsA;  Al_ += (ll)bt * bsA;
    Wh_ += (ll)bt * bsW;  Wl_ += (ll)bt * bsW;
    if (Cp) Cp += (ll)bt * bsC;
    if (Oh) { Oh += (ll)bt * bsC; Ol += (ll)bt * bsC; }
    int Kc = K / ksplit;
    int kbeg = ks * Kc;
    int niter = Kc / BK;
    int m0 = blockIdx.x * BM, n0 = blockIdx.y * BN;
    int tid = threadIdx.x;
    int wid = tid >> 5, lane = tid & 31;
    int wm = wid >> 1, wn = wid & 1;
    int lq = lane >> 2, lr = lane & 3;
    int g = lane >> 3, ri = lane & 7;       /* ldmatrix lane groups */

    unsigned sAh = (unsigned)__cvta_generic_to_shared(Ah);
    unsigned sAl = (unsigned)__cvta_generic_to_shared(Al);
    unsigned sBh = (unsigned)__cvta_generic_to_shared(Bh);
    unsigned sBl = (unsigned)__cvta_generic_to_shared(Bl);

    int arow0 = tid >> 2, aq0 = tid & 3;
    int arow1 = arow0 + 64;
    int brow = tid >> 2, bq = tid & 3;
    bool am0 = (m0 + arow0) < M, am1 = (m0 + arow1) < M;
    bool bn  = (n0 + brow) < N;

    auto load_stage = [&](int k0, int st) {
        {
            ll gg = (ll)(m0 + arow0) * lda + k0 + aq0 * 8;
            unsigned d = (st*ASZ + arow0 * PAD + aq0 * 8) * 2;
            cp16(sAh + d, Ah_ + gg, am0);
            cp16(sAl + d, Al_ + gg, am0);
        }
        {
            ll gg = (ll)(m0 + arow1) * lda + k0 + aq0 * 8;
            unsigned d = (st*ASZ + arow1 * PAD + aq0 * 8) * 2;
            cp16(sAh + d, Ah_ + gg, am1);
            cp16(sAl + d, Al_ + gg, am1);
        }
        {
            ll gg = (ll)(n0 + brow) * ldw + k0 + bq * 8;
            unsigned d = (st*BSZ + brow * PAD + bq * 8) * 2;
            cp16(sBh + d, Wh_ + gg, bn);
            cp16(sBl + d, Wl_ + gg, bn);
        }
        cp_commit();
    };

    /* ldmatrix per-lane element offsets (in bf16 units) */
    int aRow = (g & 1) * 8 + ri, aCol = (g >> 1) * 8;
    unsigned aoffA0 = ((wm*32 +  0 + aRow) * PAD + aCol) * 2;   /* im=0 */
    unsigned aoffA1 = ((wm*32 + 16 + aRow) * PAD + aCol) * 2;   /* im=1 */
    /* B x4 #p: m0=jn(2p) col+0, m1=jn(2p) col+8, m2=jn(2p+1) col+0, m3=... */
    int bRow0 = wn*32 + (0 + (g >> 1)) * 8 + ri;  /* p=0 -> jn 0/1 */
    int bRow1 = wn*32 + (2 + (g >> 1)) * 8 + ri;  /* p=1 -> jn 2/3 */
    int bCol  = (g & 1) * 8;
    unsigned boffB0 = (bRow0 * PAD + bCol) * 2;
    unsigned boffB1 = (bRow1 * PAD + bCol) * 2;

    float acc[2][4][4];
    #pragma unroll
    for (int im = 0; im < 2; im++)
        #pragma unroll
        for (int jn = 0; jn < 4; jn++)
            #pragma unroll
            for (int c = 0; c < 4; c++) acc[im][jn][c] = 0.f;

    load_stage(kbeg, 0);

    for (int it = 0; it < niter; it++) {
        cp_wait0();
        __syncthreads();
        if (it + 1 < niter) load_stage(kbeg + (it + 1) * BK, (it + 1) & 1);
        int st = it & 1;
        unsigned aso = (unsigned)(st * ASZ * 2);
        unsigned bso = (unsigned)(st * BSZ * 2);

        #pragma unroll
        for (int kc = 0; kc < 2; kc++) {
            unsigned cofs = kc * 16 * 2;   /* 16 bf16 = 32 bytes */
            unsigned ah[2][4], al[2][4], bh[4][2], bl[4][2];
            ldsm4(ah[0][0], ah[0][1], ah[0][2], ah[0][3], sAh + aso + aoffA0 + cofs);
            ldsm4(ah[1][0], ah[1][1], ah[1][2], ah[1][3], sAh + aso + aoffA1 + cofs);
            ldsm4(al[0][0], al[0][1], al[0][2], al[0][3], sAl + aso + aoffA0 + cofs);
            ldsm4(al[1][0], al[1][1], al[1][2], al[1][3], sAl + aso + aoffA1 + cofs);
            ldsm4(bh[0][0], bh[0][1], bh[1][0], bh[1][1], sBh + bso + boffB0 + cofs);
            ldsm4(bh[2][0], bh[2][1], bh[3][0], bh[3][1], sBh + bso + boffB1 + cofs);
            ldsm4(bl[0][0], bl[0][1], bl[1][0], bl[1][1], sBl + bso + boffB0 + cofs);
            ldsm4(bl[2][0], bl[2][1], bl[3][0], bl[3][1], sBl + bso + boffB1 + cofs);
            #pragma unroll
            for (int im = 0; im < 2; im++)
                #pragma unroll
                for (int jn = 0; jn < 4; jn++) {
                    float* cc = acc[im][jn];
                    asm volatile(
                        "mma.sync.aligned.m16n8k16.row.col.f32.bf16.bf16.f32 "
                        "{%0,%1,%2,%3}, {%4,%5,%6,%7}, {%8,%9}, {%0,%1,%2,%3};"
                        : "+f"(cc[0]), "+f"(cc[1]), "+f"(cc[2]), "+f"(cc[3])
                        : "r"(ah[im][0]), "r"(ah[im][1]), "r"(ah[im][2]), "r"(ah[im][3]),
                          "r"(bh[jn][0]), "r"(bh[jn][1]));
                    asm volatile(
                        "mma.sync.aligned.m16n8k16.row.col.f32.bf16.bf16.f32 "
                        "{%0,%1,%2,%3}, {%4,%5,%6,%7}, {%8,%9}, {%0,%1,%2,%3};"
                        : "+f"(cc[0]), "+f"(cc[1]), "+f"(cc[2]), "+f"(cc[3])
                        : "r"(ah[im][0]), "r"(ah[im][1]), "r"(ah[im][2]), "r"(ah[im][3]),
                          "r"(bl[jn][0]), "r"(bl[jn][1]));
                    asm volatile(
                        "mma.sync.aligned.m16n8k16.row.col.f32.bf16.bf16.f32 "
                        "{%0,%1,%2,%3}, {%4,%5,%6,%7}, {%8,%9}, {%0,%1,%2,%3};"
                        : "+f"(cc[0]), "+f"(cc[1]), "+f"(cc[2]), "+f"(cc[3])
                        : "r"(al[im][0]), "r"(al[im][1]), "r"(al[im][2]), "r"(al[im][3]),
                          "r"(bh[jn][0]), "r"(bh[jn][1]));
                }
        }
        /* no trailing barrier: next iteration's top-of-loop sync orders
           reads of stage st before any write to it (stage (it+2)&1 == st). */
    }

    #pragma unroll
    for (int im = 0; im < 2; im++) {
        int mb = m0 + wm * 32 + im * 16 + lq;
        #pragma unroll
        for (int jn = 0; jn < 4; jn++) {
            int nb = n0 + wn * 32 + jn * 8 + lr * 2;
            float b0 = 0.f, b1 = 0.f;
            if (bias && ks == 0) {
                if (nb     < N) b0 = bias[nb];
                if (nb + 1 < N) b1 = bias[nb + 1];
            }
            float* cc = acc[im][jn];
            #pragma unroll
            for (int half = 0; half < 2; half++) {
                int m = mb + half * 8;
                if (m >= M) continue;
                #pragma unroll
                for (int e = 0; e < 2; e++) {
                    int n = nb + e;
                    if (n >= N) continue;
                    float r = (cc[half*2 + e] + (e ? b1 : b0)) * alpha;
                    ll off = (ll)m * crs + (ll)n * ccs;
                    if (Cp) {
                        if (ksplit == 1) Cp[off] = r;
                        else atomicAdd(&Cp[off], r);
                    }
                    if (Oh) split_store(r, Oh, Ol, off);
                }
            }
        }
    }
}

/* ---------------- softmax: asn copy + soft bf16 hi/lo --------------------- */
__global__ void softmax_rows2(const float* __restrict__ cxz,
                              float* __restrict__ asn,
                              bf16* __restrict__ sfh, bf16* __restrict__ sfl) {
    int row = blockIdx.x;
    int b = row / 600; int rem = row - b * 600;
    int t = rem / NC_; int k = rem - t * NC_;
    const float* s = cxz + ((ll)(b * NC_ + k)) * R_ + (ll)t * N_;
    ll drow = ((ll)((b * T_ + t) * NC_ + k)) * N_;
    __shared__ float sh[8];
    int tid = threadIdx.x;
    float mx = -1e30f;
    for (int i = tid; i < N_; i += 256) mx = fmaxf(mx, s[i]);
    #pragma unroll
    for (int o = 16; o; o >>= 1) mx = fmaxf(mx, __shfl_xor_sync(0xffffffffu, mx, o));
    if ((tid & 31) == 0) sh[tid >> 5] = mx;
    __syncthreads();
    mx = fmaxf(fmaxf(fmaxf(sh[0],sh[1]),fmaxf(sh[2],sh[3])),
               fmaxf(fmaxf(sh[4],sh[5]),fmaxf(sh[6],sh[7])));
    __syncthreads();
    float sum = 0.f;
    for (int i = tid; i < N_; i += 256) sum += expf(s[i] - mx);
    sum = blockSum256(sum, sh);
    float inv = 1.0f / sum;
    for (int i = tid; i < N_; i += 256) {
        float v = s[i];
        asn[drow + i] = v;
        split_store(expf(v - mx) * inv, sfh, sfl, drow + i);
    }
}

/* ---------------- P softmax: warp per row, write padded bf16 --------------- */
__global__ void p_softmax(const float* __restrict__ P,
                          bf16* __restrict__ ph, bf16* __restrict__ pl) {
    int row = blockIdx.x * 8 + (threadIdx.x >> 5);
    int lane = threadIdx.x & 31;
    const float* p = P + (ll)row * PL_;
    float v[5];
    float mx = -1e30f;
    #pragma unroll
    for (int u = 0; u < 5; u++) {
        int i = lane + u * 32;
        v[u] = (i < NC_) ? p[i] : -1e30f;
        mx = fmaxf(mx, v[u]);
    }
    #pragma unroll
    for (int o = 16; o; o >>= 1) mx = fmaxf(mx, __shfl_xor_sync(0xffffffffu, mx, o));
    float sum = 0.f;
    #pragma unroll
    for (int u = 0; u < 5; u++) {
        int i = lane + u * 32;
        v[u] = (i < NC_) ? expf(v[u] - mx) : 0.f;
        sum += v[u];
    }
    #pragma unroll
    for (int o = 16; o; o >>= 1) sum += __shfl_xor_sync(0xffffffffu, sum, o);
    float inv = 1.0f / sum;
    #pragma unroll
    for (int u = 0; u < 5; u++) {
        int i = lane + u * 32;
        if (i < PL_) split_store(v[u] * inv, ph, pl, (ll)row * PL_ + i);
    }
}

/* ---------------- gate + LayerNorm --------------------------------------- */
__global__ void gate_ln_kernel(const float* __restrict__ cen,
                               const float* __restrict__ nw, const float* __restrict__ nb,
                               const float* __restrict__ salpha, const float* __restrict__ sbeta,
                               float* __restrict__ cin_out) {
    int k = blockIdx.x, b = blockIdx.y, c = threadIdx.x;
    __shared__ float sh[8];
    float pv[4];
    #pragma unroll
    for (int t = 0; t < 4; t++)
        pv[t] = cen[(((ll)b*4 + t) * NC_ + k) * C_ + c];
    float last = pv[3];
    float ll2 = blockSum256(last*last, sh);
    float cin = last;
    float alpha = salpha[0], beta = sbeta[0];
    for (int t = 0; t < 3; t++) {
        float dt = blockSum256(last * pv[t], sh);
        float pp = blockSum256(pv[t] * pv[t], sh);
        float denom = fmaxf(sqrtf(ll2) * sqrtf(pp), 1e-8f);
        float gate = 1.0f / (1.0f + expf(-(beta + alpha * (dt / denom))));
        cin += gate * pv[t];
    }
    float m  = blockSum256(cin, sh) * (1.0f / C_);
    float dv = cin - m;
    float var = blockSum256(dv*dv, sh) * (1.0f / C_);
    cin_out[((ll)b*NC_ + k) * C_ + c] = dv * rsqrtf(var + 1e-5f) * nw[c] + nb[c];
}

/* ---------------- K/V projections -> bf16 (K rows, V transposed) ----------- */
__global__ void kv_kernel(const float* __restrict__ cin,
                          const float* __restrict__ kw, const float* __restrict__ kb,
                          const float* __restrict__ vw, const float* __restrict__ vb,
                          bf16* __restrict__ kh, bf16* __restrict__ kl,
                          bf16* __restrict__ vth, bf16* __restrict__ vtl) {
    int row = blockIdx.x, c = threadIdx.x;
    int b = row / NC_, kk = row - b * NC_;
    __shared__ float ci[C_];
    ci[c] = cin[(ll)row * C_ + c];
    __syncthreads();
    float ka = kb[c], va = vb[c];
    const float* kwr = kw + (ll)c * C_;
    const float* vwr = vw + (ll)c * C_;
    #pragma unroll 4
    for (int j = 0; j < C_; j++) {
        float cv = ci[j];
        ka += cv * kwr[j];
        va += cv * vwr[j];
    }
    split_store(ka, kh, kl, (ll)row * C_ + c);
    int h = c >> 5, nn = c & 31;
    ll vt = ((ll)(b * 8 + h) * 32 + nn) * PL_ + kk;
    split_store(va, vth, vtl, vt);
}

/* ---------------- depthwise 3x3 conv + GELU -> bf16 hi/lo ----------------- */
__global__ void conv_gelu2(const float* __restrict__ h,
                           const float* __restrict__ dww, const float* __restrict__ dwb,
                           bf16* __restrict__ oh, bf16* __restrict__ ol) {
    __shared__ float patch[10][10][64];
    int ch0 = blockIdx.x * 64;
    int tileid = blockIdx.y;
    int y0 = (tileid >> 3) * 8, x0 = (tileid & 7) * 8;
    int b = blockIdx.z;
    int tid = threadIdx.x;
    for (int i = tid; i < 6400; i += 256) {
        int c = i & 63, sp = i >> 6;
        int py = sp / 10, px = sp % 10;
        int yy = y0 + py - 1, xx = x0 + px - 1;
        float v = 0.f;
        if (yy >= 0 && yy < 64 && xx >= 0 && xx < 64)
            v = h[(((ll)b*N_) + (yy*64 + xx)) * HID_ + ch0 + c];
        patch[py][px][c] = v;
    }
    __syncthreads();
    int c = tid & 63, sub = tid >> 6;
    float w[9];
    #pragma unroll
    for (int i = 0; i < 9; i++) w[i] = dww[(ch0 + c)*9 + i];
    float bv = dwb[ch0 + c];
    for (int oy = sub; oy < 8; oy += 4) {
        #pragma unroll
        for (int ox = 0; ox < 8; ox++) {
            float a = bv;
            #pragma unroll
            for (int dy = 0; dy < 3; dy++)
                #pragma unroll
                for (int dx = 0; dx < 3; dx++)
                    a += patch[oy+dy][ox+dx][c] * w[dy*3+dx];
            float g = 0.5f * a * (1.0f + erff(a * 0.7071067811865475f));
            split_store(g, oh, ol, (((ll)b*N_) + ((y0+oy)*64 + x0+ox)) * HID_ + ch0 + c);
        }
    }
}

/* ---------------- residual + LayerNorm (optional bf16 dual-write) ---------- */
__global__ void add_ln_kernel(const float* __restrict__ res, const float* __restrict__ val,
                              const float* __restrict__ nw, const float* __restrict__ nb,
                              float* __restrict__ dst,
                              bf16* __restrict__ dh, bf16* __restrict__ dl) {
    ll row = blockIdx.x;
    int c = threadIdx.x;
    __shared__ float sh[8];
    float v = val[row * C_ + c];
    float m = blockSum256(v, sh) * (1.0f / C_);
    float d = v - m;
    float var = blockSum256(d*d, sh) * (1.0f / C_);
    float r = res[row * C_ + c] + d * rsqrtf(var + 1e-5f) * nw[c] + nb[c];
    dst[row * C_ + c] = r;
    if (dh) split_store(r, dh, dl, row * C_ + c);
}

/* ---------------- host launch --------------------------------------------- */
static float* symaddr(const void* sym) {
    void* p = nullptr;
    cudaGetSymbolAddress(&p, sym);
    return (float*)p;
}
static bf16* symaddrb(const void* sym) {
    void* p = nullptr;
    cudaGetSymbolAddress(&p, sym);
    return (bf16*)p;
}

extern "C" void kernel_launch(void* const* d_in, const int* in_sizes, int n_in,
                              void* d_out, int out_size) {
    const float* x    = (const float*)d_in[0];
    const float* z    = (const float*)d_in[1];
    const float* mem  = (const float*)d_in[2];
    const float* cw   = (const float*)d_in[3];
    const float* p1   = (const float*)d_in[4];
    const float* t1   = (const float*)d_in[5];
    const float* p2   = (const float*)d_in[6];
    const float* t2   = (const float*)d_in[7];
    const float* sal  = (const float*)d_in[8];
    const float* sbe  = (const float*)d_in[9];
    const float* qw   = (const float*)d_in[10];
    const float* qb   = (const float*)d_in[11];
    const float* kw   = (const float*)d_in[12];
    const float* kb   = (const float*)d_in[13];
    const float* vw   = (const float*)d_in[14];
    const float* vb   = (const float*)d_in[15];
    const float* pw   = (const float*)d_in[16];
    const float* pb   = (const float*)d_in[17];
    const float* nw   = (const float*)d_in[18];
    const float* nb   = (const float*)d_in[19];
    const float* f1w  = (const float*)d_in[20];
    const float* f1b  = (const float*)d_in[21];
    const float* dww  = (const float*)d_in[22];
    const float* dwb  = (const float*)d_in[23];
    const float* f2w  = (const float*)d_in[24];
    const float* f2b  = (const float*)d_in[25];

    float* out_main = (float*)d_out;
    float* out_cxz  = out_main + (ll)B_*N_*C_;
    float* out_asn  = out_cxz  + (ll)B_*NC_*R_;

    float* clt  = symaddr(g_clt);
    float* cen  = symaddr(g_cen);
    float* cin  = symaddr(g_cin);
    float* Pf   = symaddr(g_P);
    float* tmp  = symaddr(g_tmp);
    float* out1 = symaddr(g_out1);
    float* h1   = symaddr(g_h1);

    bf16 *xf_h = symaddrb(g_xf_h), *xf_l = symaddrb(g_xf_l);
    bf16 *xT_h = symaddrb(g_xfT_h),*xT_l = symaddrb(g_xfT_l);
    bf16 *S_h  = symaddrb(g_S_h),  *S_l  = symaddrb(g_S_l);
    bf16 *tc_h = symaddrb(g_tc_h), *tc_l = symaddrb(g_tc_l);
    bf16 *sf_h = symaddrb(g_sf_h), *sf_l = symaddrb(g_sf_l);
    bf16 *x_h  = symaddrb(g_x_h),  *x_l  = symaddrb(g_x_l);
    bf16 *q_h  = symaddrb(g_q_h),  *q_l  = symaddrb(g_q_l);
    bf16 *k_h  = symaddrb(g_k_h),  *k_l  = symaddrb(g_k_l);
    bf16 *vt_h = symaddrb(g_vt_h), *vt_l = symaddrb(g_vt_l);
    bf16 *P_h  = symaddrb(g_P_h),  *P_l  = symaddrb(g_P_l);
    bf16 *at_h = symaddrb(g_atn_h),*at_l = symaddrb(g_atn_l);
    bf16 *o1_h = symaddrb(g_o1_h), *o1_l = symaddrb(g_o1_l);
    bf16 *hg_h = symaddrb(g_hg_h), *hg_l = symaddrb(g_hg_l);
    bf16 *cw_h = symaddrb(g_cw_h), *cw_l = symaddrb(g_cw_l);
    bf16 *qw_h = symaddrb(g_qw_h), *qw_l = symaddrb(g_qw_l);
    bf16 *pw_h = symaddrb(g_pw_h), *pw_l = symaddrb(g_pw_l);
    bf16 *f1_h = symaddrb(g_f1_h), *f1_l = symaddrb(g_f1_l);
    bf16 *f2_h = symaddrb(g_f2_h), *f2_l = symaddrb(g_f2_l);

    /* 0. fused weight + x conversions, tcat */
    {
        CvtJob j0 = {(const float4*)cw,  cw_h, cw_l, NC_*C_/4};
        CvtJob j1 = {(const float4*)qw,  qw_h, qw_l, C_*C_/4};
        CvtJob j2 = {(const float4*)pw,  pw_h, pw_l, C_*C_/4};
        CvtJob j3 = {(const float4*)f1w, f1_h, f1_l, HID_*C_/4};
        CvtJob j4 = {(const float4*)f2w, f2_h, f2_l, HID_*C_/4};
        CvtJob j5 = {(const float4*)x,   x_h,  x_l,  B_*N_*C_/4};
        int mx = HID_*C_/4;
        if (B_*N_*C_/4 > mx) mx = B_*N_*C_/4;
        cvt_multi<<<dim3((mx + 255)/256, 6), 256>>>(j0, j1, j2, j3, j4, j5);
    }
    build_tcat<<<(NC_*KS_ + 255)/256, 256>>>(t1, t2, tc_h, tc_l);

    /* 1. xf: row-major + transposed bf16 */
    build_xf_all<<<dim3(N_/64, C_/32, B_*T_), 256>>>(x, mem, xf_h, xf_l, xT_h, xT_l);

    /* 2. clt (MMA, r-major store) */
    gemm_mma2<<<dim3(R_/128, 3, B_), 256>>>(
        R_, NC_, C_, xf_h, xf_l, C_, (ll)R_*C_, cw_h, cw_l, C_, 0,
        clt, CLTS, 1, (ll)R_*CLTS, nullptr, nullptr, nullptr, 1.0f, 1);

    /* 3. fused cosine scales + S build */
    build_S2<<<dim3(R_/64, B_), 256>>>(z, clt, p1, p2, S_h, S_l);

    /* 4. cluster_x_z (MMA, transposed store) */
    gemm_mma2<<<dim3(R_/128, 3, B_), 256>>>(
        R_, NC_, KS_, S_h, S_l, KS_, (ll)R_*KS_, tc_h, tc_l, KS_, 0,
        out_cxz, 1, R_, (ll)NC_*R_, nullptr, nullptr, nullptr, 0.5f, 1);

    /* 5. softmax: asn copy + soft bf16 */
    softmax_rows2<<<B_*T_*NC_, 256>>>(out_cxz, out_asn, sf_h, sf_l);

    /* 6. cen = soft @ xf (MMA, split-K=8) */
    zero_kernel<<<(B_*T_*NC_*C_ + 255)/256, 256>>>(cen, B_*T_*NC_*C_);
    gemm_mma2<<<dim3(2, 4, B_*T_*8), 256>>>(
        NC_, C_, N_, sf_h, sf_l, N_, (ll)NC_*N_, xT_h, xT_l, N_, (ll)C_*N_,
        cen, C_, 1, (ll)NC_*C_, nullptr, nullptr, nullptr, 1.0f, 8);

    /* 7. gate + LN */
    gate_ln_kernel<<<dim3(NC_, B_), 256>>>(cen, nw, nb, sal, sbe, cin);

    /* 8. k,v -> bf16 */
    zero_bf2<<<(B_*8*32*PL_ + 255)/256, 256>>>(vt_h, vt_l, B_*8*32*PL_);
    kv_kernel<<<B_*NC_, 256>>>(cin, kw, kb, vw, vb, k_h, k_l, vt_h, vt_l);

    /* 9. q (MMA, bf16 dual-write only) */
    gemm_mma2<<<dim3(64, 4, 1), 256>>>(
        B_*N_, C_, C_, x_h, x_l, C_, 0, qw_h, qw_l, C_, 0,
        nullptr, C_, 1, 0, q_h, q_l, qb, 0.17677669529663687f, 1);

    /* 10a. QK logits (batched over h) */
    for (int b = 0; b < B_; b++) {
        gemm_mma2<<<dim3(N_/128, 3, 8), 256>>>(
            N_, NC_, 32,
            q_h + (ll)b*N_*C_, q_l + (ll)b*N_*C_, C_, 32,
            k_h + (ll)b*NC_*C_, k_l + (ll)b*NC_*C_, C_, 32,
            Pf + (ll)b*8*N_*PL_, PL_, 1, (ll)N_*PL_,
            nullptr, nullptr, nullptr, 1.0f, 1);
    }

    /* 10b. P softmax */
    p_softmax<<<B_*8*N_/8, 256>>>(Pf, P_h, P_l);

    /* 10c. PV (batched over h) */
    for (int b = 0; b < B_; b++) {
        gemm_mma2<<<dim3(N_/128, 1, 8), 256>>>(
            N_, 32, PL_,
            P_h + (ll)b*8*N_*PL_, P_l + (ll)b*8*N_*PL_, PL_, (ll)N_*PL_,
            vt_h + (ll)b*8*32*PL_, vt_l + (ll)b*8*32*PL_, PL_, (ll)32*PL_,
            nullptr, C_, 1, 32,
            at_h + (ll)b*N_*C_, at_l + (ll)b*N_*C_, nullptr, 1.0f, 1);
    }

    /* 11. proj (MMA) */
    gemm_mma2<<<dim3(64, 4, 1), 256>>>(
        B_*N_, C_, C_, at_h, at_l, C_, 0, pw_h, pw_l, C_, 0,
        tmp, C_, 1, 0, nullptr, nullptr, pb, 1.0f, 1);

    /* 12. out1 = x + LN(proj), dual-write */
    add_ln_kernel<<<B_*N_, 256>>>(x, tmp, nw, nb, out1, o1_h, o1_l);

    /* 13. fc1 (MMA) */
    gemm_mma2<<<dim3(64, 16, 1), 256>>>(
        B_*N_, HID_, C_, o1_h, o1_l, C_, 0, f1_h, f1_l, C_, 0,
        h1, HID_, 1, 0, nullptr, nullptr, f1b, 1.0f, 1);

    /* 14. depthwise conv + GELU -> bf16 */
    conv_gelu2<<<dim3(HID_/64, 64, B_), 256>>>(h1, dww, dwb, hg_h, hg_l);

    /* 15. fc2 (MMA, K=1024) */
    gemm_mma2<<<dim3(64, 4, 1), 256>>>(
        B_*N_, C_, HID_, hg_h, hg_l, HID_, 0, f2_h, f2_l, HID_, 0,
        tmp, C_, 1, 0, nullptr, nullptr, f2b, 1.0f, 1);

    /* 16. out = out1 + LN(fc2) */
    add_ln_kernel<<<B_*N_, 256>>>(out1, tmp, nw, nb, out_main, nullptr, nullptr);
}

// round 15
// speedup vs baseline: 2.2322x; 1.0039x over previous
#include <cuda_runtime.h>
#include <cuda_bf16.h>
#include <math.h>

#define B_   2
#define N_   4096
#define C_   256
#define NC_  150
#define T_   4
#define HID_ 1024
#define R_   16384   /* T_*N_ */
#define KS_  320     /* padded 2*NC_ for cxz MMA */
#define PL_  160     /* padded NC_ for attention P */
#define CLTS 152     /* padded row stride of clt_rm */

typedef long long ll;
typedef __nv_bfloat16 bf16;

/* ---------------- scratch (device globals) ------------------------------- */
__device__ float g_clt [B_*R_*CLTS];
__device__ float g_cen [B_*T_*NC_*C_];
__device__ float g_cin [B_*NC_*C_];
__device__ float g_P   [B_*8*N_*PL_];
__device__ float g_tmp [B_*N_*C_];
__device__ float g_out1[B_*N_*C_];
__device__ float g_h1  [B_*N_*HID_];

/* bf16 hi/lo operand buffers — 16B aligned */
__device__ __align__(16) bf16 g_xf_h [B_*T_*N_*C_];
__device__ __align__(16) bf16 g_xf_l [B_*T_*N_*C_];
__device__ __align__(16) bf16 g_xfT_h[B_*T_*C_*N_];
__device__ __align__(16) bf16 g_xfT_l[B_*T_*C_*N_];
__device__ __align__(16) bf16 g_S_h  [B_*R_*KS_];
__device__ __align__(16) bf16 g_S_l  [B_*R_*KS_];
__device__ __align__(16) bf16 g_tc_h [NC_*KS_];
__device__ __align__(16) bf16 g_tc_l [NC_*KS_];
__device__ __align__(16) bf16 g_sf_h [B_*T_*NC_*N_];
__device__ __align__(16) bf16 g_sf_l [B_*T_*NC_*N_];
__device__ __align__(16) bf16 g_x_h  [B_*N_*C_];
__device__ __align__(16) bf16 g_x_l  [B_*N_*C_];
__device__ __align__(16) bf16 g_q_h  [B_*N_*C_];
__device__ __align__(16) bf16 g_q_l  [B_*N_*C_];
__device__ __align__(16) bf16 g_k_h  [B_*NC_*C_];
__device__ __align__(16) bf16 g_k_l  [B_*NC_*C_];
__device__ __align__(16) bf16 g_vt_h [B_*8*32*PL_];
__device__ __align__(16) bf16 g_vt_l [B_*8*32*PL_];
__device__ __align__(16) bf16 g_P_h  [B_*8*N_*PL_];
__device__ __align__(16) bf16 g_P_l  [B_*8*N_*PL_];
__device__ __align__(16) bf16 g_atn_h[B_*N_*C_];
__device__ __align__(16) bf16 g_atn_l[B_*N_*C_];
__device__ __align__(16) bf16 g_o1_h [B_*N_*C_];
__device__ __align__(16) bf16 g_o1_l [B_*N_*C_];
__device__ __align__(16) bf16 g_hg_h [B_*N_*HID_];
__device__ __align__(16) bf16 g_hg_l [B_*N_*HID_];
__device__ __align__(16) bf16 g_cw_h [NC_*C_];
__device__ __align__(16) bf16 g_cw_l [NC_*C_];
__device__ __align__(16) bf16 g_qw_h [C_*C_];
__device__ __align__(16) bf16 g_qw_l [C_*C_];
__device__ __align__(16) bf16 g_pw_h [C_*C_];
__device__ __align__(16) bf16 g_pw_l [C_*C_];
__device__ __align__(16) bf16 g_f1_h [HID_*C_];
__device__ __align__(16) bf16 g_f1_l [HID_*C_];
__device__ __align__(16) bf16 g_f2_h [C_*HID_];
__device__ __align__(16) bf16 g_f2_l [C_*HID_];

__device__ __forceinline__ float blockSum256(float v, float* sh) {
    #pragma unroll
    for (int o = 16; o; o >>= 1) v += __shfl_xor_sync(0xffffffffu, v, o);
    if ((threadIdx.x & 31) == 0) sh[threadIdx.x >> 5] = v;
    __syncthreads();
    float r = sh[0]+sh[1]+sh[2]+sh[3]+sh[4]+sh[5]+sh[6]+sh[7];
    __syncthreads();
    return r;
}

__device__ __forceinline__ void split_store(float v, bf16* h, bf16* l, ll idx) {
    bf16 hh = __float2bfloat16(v);
    h[idx] = hh;
    l[idx] = __float2bfloat16(v - __bfloat162float(hh));
}
__device__ __forceinline__ void split_pair(float v, bf16& h, bf16& l) {
    h = __float2bfloat16(v);
    l = __float2bfloat16(v - __bfloat162float(h));
}

/* ---------------- cp.async / ldmatrix helpers ------------------------------ */
__device__ __forceinline__ void cp16(unsigned dst, const void* src, bool pred) {
    int sz = pred ? 16 : 0;
    asm volatile("cp.async.ca.shared.global [%0], [%1], 16, %2;"
                 :: "r"(dst), "l"(src), "r"(sz));
}
__device__ __forceinline__ void cp_commit() {
    asm volatile("cp.async.commit_group;");
}
__device__ __forceinline__ void cp_wait0() {
    asm volatile("cp.async.wait_group 0;");
}
__device__ __forceinline__ void ldsm4(unsigned& d0, unsigned& d1,
                                      unsigned& d2, unsigned& d3, unsigned addr) {
    asm volatile("ldmatrix.sync.aligned.m8n8.x4.shared.b16 {%0,%1,%2,%3}, [%4];"
                 : "=r"(d0), "=r"(d1), "=r"(d2), "=r"(d3) : "r"(addr));
}

__global__ void zero_kernel(float* p, int n) {
    int i = blockIdx.x * 256 + threadIdx.x;
    if (i < n) p[i] = 0.f;
}
__global__ void zero_bf2(bf16* a, bf16* b, int n) {
    int i = blockIdx.x * 256 + threadIdx.x;
    if (i < n) { a[i] = __float2bfloat16(0.f); b[i] = __float2bfloat16(0.f); }
}

/* ---------------- fused fp32 -> bf16 hi/lo split (6 segments) -------------- */
struct CvtJob { const float4* s; bf16* h; bf16* l; int n4; };
__global__ void cvt_multi(CvtJob j0, CvtJob j1, CvtJob j2,
                          CvtJob j3, CvtJob j4, CvtJob j5) {
    CvtJob j;
    switch (blockIdx.y) {
        case 0: j = j0; break;
        case 1: j = j1; break;
        case 2: j = j2; break;
        case 3: j = j3; break;
        case 4: j = j4; break;
        default: j = j5; break;
    }
    int i = blockIdx.x * 256 + threadIdx.x;
    if (i >= j.n4) return;
    float4 v = j.s[i];
    float vv[4] = {v.x, v.y, v.z, v.w};
    #pragma unroll
    for (int u = 0; u < 4; u++) split_store(vv[u], j.h, j.l, (ll)i*4 + u);
}

/* ---------------- tcat hi/lo ----------------------------------------------- */
__global__ void build_tcat(const float* __restrict__ t1, const float* __restrict__ t2,
                           bf16* __restrict__ th, bf16* __restrict__ tl) {
    int idx = blockIdx.x * 256 + threadIdx.x;
    if (idx >= NC_ * KS_) return;
    int kp = idx / KS_, j = idx % KS_;
    float v = 0.f;
    if (j < NC_)        v = t1[j * NC_ + kp];
    else if (j < 2*NC_) v = t2[(j - NC_) * NC_ + kp];
    split_store(v, th, tl, idx);
}

/* ---------------- fused xf: row-major + transposed bf16 hi/lo -------------- */
__global__ void build_xf_all(const float* __restrict__ x, const float* __restrict__ mem,
                             bf16* __restrict__ xh, bf16* __restrict__ xl,
                             bf16* __restrict__ oth, bf16* __restrict__ otl) {
    __shared__ float tile[32][65];
    int bt = blockIdx.z;
    int b = bt >> 2, t = bt & 3;
    const float* src = (t < 3) ? (mem + ((ll)(b*3 + t)) * N_ * C_)
                               : (x   + ((ll)b) * N_ * C_);
    int n0 = blockIdx.x * 64, c0 = blockIdx.y * 32;
    int tid = threadIdx.x;
    for (int i = tid; i < 32 * 64; i += 256) {
        int cl = i & 31, nl = i >> 5;
        tile[cl][nl] = src[((ll)(n0 + nl)) * C_ + c0 + cl];
    }
    __syncthreads();
    {
        int cl = tid >> 3, nseg = (tid & 7) * 8;
        __align__(16) bf16 hb[8], lb[8];
        #pragma unroll
        for (int u = 0; u < 8; u++) split_pair(tile[cl][nseg + u], hb[u], lb[u]);
        ll off = ((ll)bt * C_ + c0 + cl) * N_ + n0 + nseg;
        *(uint4*)&oth[off] = *(const uint4*)hb;
        *(uint4*)&otl[off] = *(const uint4*)lb;
    }
    {
        int nl = tid >> 2, cseg = (tid & 3) * 8;
        __align__(16) bf16 hb[8], lb[8];
        #pragma unroll
        for (int u = 0; u < 8; u++) split_pair(tile[cseg + u][nl], hb[u], lb[u]);
        ll off = ((ll)bt * N_ + n0 + nl) * C_ + c0 + cseg;
        *(uint4*)&xh[off] = *(const uint4*)hb;
        *(uint4*)&xl[off] = *(const uint4*)lb;
    }
}

/* ---------------- fused scales + S build (clt is r-major) ------------------ */
__global__ void build_S2(const float* __restrict__ z, const float* __restrict__ clt,
                         const float* __restrict__ p1, const float* __restrict__ p2,
                         bf16* __restrict__ sh_, bf16* __restrict__ sl_) {
    __shared__ float tile[32][65];
    __shared__ float s1s[64], s2s[64];
    __shared__ float p1s[NC_], p2s[NC_], pn[2];
    int b = blockIdx.y;
    int r0 = blockIdx.x * 64;
    int tid = threadIdx.x;
    if (tid < NC_) { p1s[tid] = p1[tid]; p2s[tid] = p2[tid]; }
    if (tid < 2) {
        const float* p = tid ? p2 : p1;
        float s = 0.f;
        for (int k = 0; k < NC_; k++) s += p[k]*p[k];
        pn[tid] = 1.0f / fmaxf(sqrtf(s), 1e-12f);
    }
    __syncthreads();
    {
        int rl = tid >> 2, sub = tid & 3;
        int r = r0 + rl;
        const float* zb = z   + (ll)b * NC_ * R_ + r;
        const float* cb = clt + ((ll)b * R_ + r) * CLTS;
        float zz = 0.f, zp = 0.f, cc = 0.f, cp = 0.f;
        for (int j = sub; j < NC_; j += 4) {
            float zv = zb[(ll)j * R_];
            float cv = cb[j];
            zz += zv*zv; zp += zv*p1s[j];
            cc += cv*cv; cp += cv*p2s[j];
        }
        #pragma unroll
        for (int o = 2; o; o >>= 1) {
            zz += __shfl_down_sync(0xffffffffu, zz, o, 4);
            zp += __shfl_down_sync(0xffffffffu, zp, o, 4);
            cc += __shfl_down_sync(0xffffffffu, cc, o, 4);
            cp += __shfl_down_sync(0xffffffffu, cp, o, 4);
        }
        if (sub == 0) {
            float s1v = zp * pn[0] / fmaxf(sqrtf(zz), 1e-12f);
            float s2v = cp * pn[1] / fmaxf(sqrtf(cc), 1e-12f);
            s1s[rl] = fminf(fmaxf(s1v, 0.f), 1.f);
            s2s[rl] = fminf(fmaxf(s2v, 0.f), 1.f);
        }
    }
    __syncthreads();
    for (int jc = 0; jc < 5; jc++) {
        int j0 = jc * 32;
        for (int i = tid; i < 32 * 64; i += 256) {
            int rl = i & 63, jl = i >> 6;
            int j = j0 + jl;
            float v;
            if (j < NC_)
                v = z[((ll)b * NC_ + j) * R_ + r0 + rl] * s1s[rl];
            else
                v = clt[((ll)b * R_ + r0 + rl) * CLTS + (j - NC_)] * s2s[rl];
            tile[jl][rl] = v;
        }
        __syncthreads();
        int rl = tid >> 2, jseg = (tid & 3) * 8;
        __align__(16) bf16 hb[8], lb[8];
        #pragma unroll
        for (int u = 0; u < 8; u++) split_pair(tile[jseg + u][rl], hb[u], lb[u]);
        ll off = ((ll)b * R_ + r0 + rl) * KS_ + j0 + jseg;
        *(uint4*)&sh_[off] = *(const uint4*)hb;
        *(uint4*)&sl_[off] = *(const uint4*)lb;
        __syncthreads();
    }
    {
        int rl = tid >> 2, jseg = (tid & 3) * 8;
        const float* crow = clt + ((ll)b * R_ + r0 + rl) * CLTS;
        float s2v = s2s[rl];
        for (int j0 = 160; j0 < KS_; j0 += 32) {
            __align__(16) bf16 hb[8], lb[8];
            #pragma unroll
            for (int u = 0; u < 8; u++) {
                int j = j0 + jseg + u;
                float v = (j < 2*NC_) ? crow[j - NC_] * s2v : 0.f;
                split_pair(v, hb[u], lb[u]);
            }
            ll off = ((ll)b * R_ + r0 + rl) * KS_ + j0 + jseg;
            *(uint4*)&sh_[off] = *(const uint4*)hb;
            *(uint4*)&sl_[off] = *(const uint4*)lb;
        }
    }
}

/* ---------------- pipelined pre-split bf16 tensor-core GEMM ----------------
 * ldmatrix fragment loads, BOTH kc sets prefetched up front (ILP);
 * single barrier per BK; 2-stage cp.async; regs budget 128 (2 blocks/SM). */
__global__ void __launch_bounds__(256, 2)
gemm_mma2(int M, int N, int K,
          const bf16* __restrict__ Ah_, const bf16* __restrict__ Al_,
          int lda, ll bsA,
          const bf16* __restrict__ Wh_, const bf16* __restrict__ Wl_,
          int ldw, ll bsW,
          float* __restrict__ Cp, ll crs, ll ccs, ll bsC,
          bf16* __restrict__ Oh, bf16* __restrict__ Ol,
          const float* __restrict__ bias, float alpha, int ksplit) {
    constexpr int BM = 128, BN = 64, BK = 32, PAD = 40;
    constexpr int ASZ = BM * PAD, BSZ = BN * PAD;
    __shared__ __align__(16) bf16 Ah[2*ASZ], Al[2*ASZ];
    __shared__ __align__(16) bf16 Bh[2*BSZ], Bl[2*BSZ];
    int zz = blockIdx.z, bt = zz / ksplit, ks = zz - bt * ksplit;
    Ah_ += (ll)bt * bsA;  Al_ += (ll)bt * bsA;
    Wh_ += (ll)bt * bsW;  Wl_ += (ll)bt * bsW;
    if (Cp) Cp += (ll)bt * bsC;
    if (Oh) { Oh += (ll)bt * bsC; Ol += (ll)bt * bsC; }
    int Kc = K / ksplit;
    int kbeg = ks * Kc;
    int niter = Kc / BK;
    int m0 = blockIdx.x * BM, n0 = blockIdx.y * BN;
    int tid = threadIdx.x;
    int wid = tid >> 5, lane = tid & 31;
    int wm = wid >> 1, wn = wid & 1;
    int lq = lane >> 2, lr = lane & 3;
    int g = lane >> 3, ri = lane & 7;

    unsigned sAh = (unsigned)__cvta_generic_to_shared(Ah);
    unsigned sAl = (unsigned)__cvta_generic_to_shared(Al);
    unsigned sBh = (unsigned)__cvta_generic_to_shared(Bh);
    unsigned sBl = (unsigned)__cvta_generic_to_shared(Bl);

    int arow0 = tid >> 2, aq0 = tid & 3;
    int arow1 = arow0 + 64;
    int brow = tid >> 2, bq = tid & 3;
    bool am0 = (m0 + arow0) < M, am1 = (m0 + arow1) < M;
    bool bn  = (n0 + brow) < N;

    auto load_stage = [&](int k0, int st) {
        {
            ll gg = (ll)(m0 + arow0) * lda + k0 + aq0 * 8;
            unsigned d = (st*ASZ + arow0 * PAD + aq0 * 8) * 2;
            cp16(sAh + d, Ah_ + gg, am0);
            cp16(sAl + d, Al_ + gg, am0);
        }
        {
            ll gg = (ll)(m0 + arow1) * lda + k0 + aq0 * 8;
            unsigned d = (st*ASZ + arow1 * PAD + aq0 * 8) * 2;
            cp16(sAh + d, Ah_ + gg, am1);
            cp16(sAl + d, Al_ + gg, am1);
        }
        {
            ll gg = (ll)(n0 + brow) * ldw + k0 + bq * 8;
            unsigned d = (st*BSZ + brow * PAD + bq * 8) * 2;
            cp16(sBh + d, Wh_ + gg, bn);
            cp16(sBl + d, Wl_ + gg, bn);
        }
        cp_commit();
    };

    int aRow = (g & 1) * 8 + ri, aCol = (g >> 1) * 8;
    unsigned aoffA0 = ((wm*32 +  0 + aRow) * PAD + aCol) * 2;
    unsigned aoffA1 = ((wm*32 + 16 + aRow) * PAD + aCol) * 2;
    int bRow0 = wn*32 + (0 + (g >> 1)) * 8 + ri;
    int bRow1 = wn*32 + (2 + (g >> 1)) * 8 + ri;
    int bCol  = (g & 1) * 8;
    unsigned boffB0 = (bRow0 * PAD + bCol) * 2;
    unsigned boffB1 = (bRow1 * PAD + bCol) * 2;

    float acc[2][4][4];
    #pragma unroll
    for (int im = 0; im < 2; im++)
        #pragma unroll
        for (int jn = 0; jn < 4; jn++)
            #pragma unroll
            for (int c = 0; c < 4; c++) acc[im][jn][c] = 0.f;

    load_stage(kbeg, 0);

    for (int it = 0; it < niter; it++) {
        cp_wait0();
        __syncthreads();
        if (it + 1 < niter) load_stage(kbeg + (it + 1) * BK, (it + 1) & 1);
        int st = it & 1;
        unsigned aso = (unsigned)(st * ASZ * 2);
        unsigned bso = (unsigned)(st * BSZ * 2);

        /* prefetch BOTH kc fragment sets up front — 16 LDSM then 48 MMA */
        unsigned ah[2][2][4], al[2][2][4], bh[2][4][2], bl[2][4][2];
        #pragma unroll
        for (int kc = 0; kc < 2; kc++) {
            unsigned cofs = kc * 16 * 2;
            ldsm4(ah[kc][0][0], ah[kc][0][1], ah[kc][0][2], ah[kc][0][3],
                  sAh + aso + aoffA0 + cofs);
            ldsm4(ah[kc][1][0], ah[kc][1][1], ah[kc][1][2], ah[kc][1][3],
                  sAh + aso + aoffA1 + cofs);
            ldsm4(al[kc][0][0], al[kc][0][1], al[kc][0][2], al[kc][0][3],
                  sAl + aso + aoffA0 + cofs);
            ldsm4(al[kc][1][0], al[kc][1][1], al[kc][1][2], al[kc][1][3],
                  sAl + aso + aoffA1 + cofs);
            ldsm4(bh[kc][0][0], bh[kc][0][1], bh[kc][1][0], bh[kc][1][1],
                  sBh + bso + boffB0 + cofs);
            ldsm4(bh[kc][2][0], bh[kc][2][1], bh[kc][3][0], bh[kc][3][1],
                  sBh + bso + boffB1 + cofs);
            ldsm4(bl[kc][0][0], bl[kc][0][1], bl[kc][1][0], bl[kc][1][1],
                  sBl + bso + boffB0 + cofs);
            ldsm4(bl[kc][2][0], bl[kc][2][1], bl[kc][3][0], bl[kc][3][1],
                  sBl + bso + boffB1 + cofs);
        }
        #pragma unroll
        for (int kc = 0; kc < 2; kc++)
            #pragma unroll
            for (int im = 0; im < 2; im++)
                #pragma unroll
                for (int jn = 0; jn < 4; jn++) {
                    float* cc = acc[im][jn];
                    asm volatile(
                        "mma.sync.aligned.m16n8k16.row.col.f32.bf16.bf16.f32 "
                        "{%0,%1,%2,%3}, {%4,%5,%6,%7}, {%8,%9}, {%0,%1,%2,%3};"
                        : "+f"(cc[0]), "+f"(cc[1]), "+f"(cc[2]), "+f"(cc[3])
                        : "r"(ah[kc][im][0]), "r"(ah[kc][im][1]),
                          "r"(ah[kc][im][2]), "r"(ah[kc][im][3]),
                          "r"(bh[kc][jn][0]), "r"(bh[kc][jn][1]));
                    asm volatile(
                        "mma.sync.aligned.m16n8k16.row.col.f32.bf16.bf16.f32 "
                        "{%0,%1,%2,%3}, {%4,%5,%6,%7}, {%8,%9}, {%0,%1,%2,%3};"
                        : "+f"(cc[0]), "+f"(cc[1]), "+f"(cc[2]), "+f"(cc[3])
                        : "r"(ah[kc][im][0]), "r"(ah[kc][im][1]),
                          "r"(ah[kc][im][2]), "r"(ah[kc][im][3]),
                          "r"(bl[kc][jn][0]), "r"(bl[kc][jn][1]));
                    asm volatile(
                        "mma.sync.aligned.m16n8k16.row.col.f32.bf16.bf16.f32 "
                        "{%0,%1,%2,%3}, {%4,%5,%6,%7}, {%8,%9}, {%0,%1,%2,%3};"
                        : "+f"(cc[0]), "+f"(cc[1]), "+f"(cc[2]), "+f"(cc[3])
                        : "r"(al[kc][im][0]), "r"(al[kc][im][1]),
                          "r"(al[kc][im][2]), "r"(al[kc][im][3]),
                          "r"(bh[kc][jn][0]), "r"(bh[kc][jn][1]));
                }
    }

    #pragma unroll
    for (int im = 0; im < 2; im++) {
        int mb = m0 + wm * 32 + im * 16 + lq;
        #pragma unroll
        for (int jn = 0; jn < 4; jn++) {
            int nb = n0 + wn * 32 + jn * 8 + lr * 2;
            float b0 = 0.f, b1 = 0.f;
            if (bias && ks == 0) {
                if (nb     < N) b0 = bias[nb];
                if (nb + 1 < N) b1 = bias[nb + 1];
            }
            float* cc = acc[im][jn];
            #pragma unroll
            for (int half = 0; half < 2; half++) {
                int m = mb + half * 8;
                if (m >= M) continue;
                #pragma unroll
                for (int e = 0; e < 2; e++) {
                    int n = nb + e;
                    if (n >= N) continue;
                    float r = (cc[half*2 + e] + (e ? b1 : b0)) * alpha;
                    ll off = (ll)m * crs + (ll)n * ccs;
                    if (Cp) {
                        if (ksplit == 1) Cp[off] = r;
                        else atomicAdd(&Cp[off], r);
                    }
                    if (Oh) split_store(r, Oh, Ol, off);
                }
            }
        }
    }
}

/* ---------------- softmax: asn copy + soft bf16 hi/lo --------------------- */
__global__ void softmax_rows2(const float* __restrict__ cxz,
                              float* __restrict__ asn,
                              bf16* __restrict__ sfh, bf16* __restrict__ sfl) {
    int row = blockIdx.x;
    int b = row / 600; int rem = row - b * 600;
    int t = rem / NC_; int k = rem - t * NC_;
    const float* s = cxz + ((ll)(b * NC_ + k)) * R_ + (ll)t * N_;
    ll drow = ((ll)((b * T_ + t) * NC_ + k)) * N_;
    __shared__ float sh[8];
    int tid = threadIdx.x;
    float mx = -1e30f;
    for (int i = tid; i < N_; i += 256) mx = fmaxf(mx, s[i]);
    #pragma unroll
    for (int o = 16; o; o >>= 1) mx = fmaxf(mx, __shfl_xor_sync(0xffffffffu, mx, o));
    if ((tid & 31) == 0) sh[tid >> 5] = mx;
    __syncthreads();
    mx = fmaxf(fmaxf(fmaxf(sh[0],sh[1]),fmaxf(sh[2],sh[3])),
               fmaxf(fmaxf(sh[4],sh[5]),fmaxf(sh[6],sh[7])));
    __syncthreads();
    float sum = 0.f;
    for (int i = tid; i < N_; i += 256) sum += expf(s[i] - mx);
    sum = blockSum256(sum, sh);
    float inv = 1.0f / sum;
    for (int i = tid; i < N_; i += 256) {
        float v = s[i];
        asn[drow + i] = v;
        split_store(expf(v - mx) * inv, sfh, sfl, drow + i);
    }
}

/* ---------------- P softmax: warp per row, write padded bf16 --------------- */
__global__ void p_softmax(const float* __restrict__ P,
                          bf16* __restrict__ ph, bf16* __restrict__ pl) {
    int row = blockIdx.x * 8 + (threadIdx.x >> 5);
    int lane = threadIdx.x & 31;
    const float* p = P + (ll)row * PL_;
    float v[5];
    float mx = -1e30f;
    #pragma unroll
    for (int u = 0; u < 5; u++) {
        int i = lane + u * 32;
        v[u] = (i < NC_) ? p[i] : -1e30f;
        mx = fmaxf(mx, v[u]);
    }
    #pragma unroll
    for (int o = 16; o; o >>= 1) mx = fmaxf(mx, __shfl_xor_sync(0xffffffffu, mx, o));
    float sum = 0.f;
    #pragma unroll
    for (int u = 0; u < 5; u++) {
        int i = lane + u * 32;
        v[u] = (i < NC_) ? expf(v[u] - mx) : 0.f;
        sum += v[u];
    }
    #pragma unroll
    for (int o = 16; o; o >>= 1) sum += __shfl_xor_sync(0xffffffffu, sum, o);
    float inv = 1.0f / sum;
    #pragma unroll
    for (int u = 0; u < 5; u++) {
        int i = lane + u * 32;
        if (i < PL_) split_store(v[u] * inv, ph, pl, (ll)row * PL_ + i);
    }
}

/* ---------------- gate + LayerNorm --------------------------------------- */
__global__ void gate_ln_kernel(const float* __restrict__ cen,
                               const float* __restrict__ nw, const float* __restrict__ nb,
                               const float* __restrict__ salpha, const float* __restrict__ sbeta,
                               float* __restrict__ cin_out) {
    int k = blockIdx.x, b = blockIdx.y, c = threadIdx.x;
    __shared__ float sh[8];
    float pv[4];
    #pragma unroll
    for (int t = 0; t < 4; t++)
        pv[t] = cen[(((ll)b*4 + t) * NC_ + k) * C_ + c];
    float last = pv[3];
    float ll2 = blockSum256(last*last, sh);
    float cin = last;
    float alpha = salpha[0], beta = sbeta[0];
    for (int t = 0; t < 3; t++) {
        float dt = blockSum256(last * pv[t], sh);
        float pp = blockSum256(pv[t] * pv[t], sh);
        float denom = fmaxf(sqrtf(ll2) * sqrtf(pp), 1e-8f);
        float gate = 1.0f / (1.0f + expf(-(beta + alpha * (dt / denom))));
        cin += gate * pv[t];
    }
    float m  = blockSum256(cin, sh) * (1.0f / C_);
    float dv = cin - m;
    float var = blockSum256(dv*dv, sh) * (1.0f / C_);
    cin_out[((ll)b*NC_ + k) * C_ + c] = dv * rsqrtf(var + 1e-5f) * nw[c] + nb[c];
}

/* ---------------- K/V projections -> bf16 (K rows, V transposed) ----------- */
__global__ void kv_kernel(const float* __restrict__ cin,
                          const float* __restrict__ kw, const float* __restrict__ kb,
                          const float* __restrict__ vw, const float* __restrict__ vb,
                          bf16* __restrict__ kh, bf16* __restrict__ kl,
                          bf16* __restrict__ vth, bf16* __restrict__ vtl) {
    int row = blockIdx.x, c = threadIdx.x;
    int b = row / NC_, kk = row - b * NC_;
    __shared__ float ci[C_];
    ci[c] = cin[(ll)row * C_ + c];
    __syncthreads();
    float ka = kb[c], va = vb[c];
    const float* kwr = kw + (ll)c * C_;
    const float* vwr = vw + (ll)c * C_;
    #pragma unroll 4
    for (int j = 0; j < C_; j++) {
        float cv = ci[j];
        ka += cv * kwr[j];
        va += cv * vwr[j];
    }
    split_store(ka, kh, kl, (ll)row * C_ + c);
    int h = c >> 5, nn = c & 31;
    ll vt = ((ll)(b * 8 + h) * 32 + nn) * PL_ + kk;
    split_store(va, vth, vtl, vt);
}

/* ---------------- depthwise 3x3 conv + GELU -> bf16 hi/lo ----------------- */
__global__ void conv_gelu2(const float* __restrict__ h,
                           const float* __restrict__ dww, const float* __restrict__ dwb,
                           bf16* __restrict__ oh, bf16* __restrict__ ol) {
    __shared__ float patch[10][10][64];
    int ch0 = blockIdx.x * 64;
    int tileid = blockIdx.y;
    int y0 = (tileid >> 3) * 8, x0 = (tileid & 7) * 8;
    int b = blockIdx.z;
    int tid = threadIdx.x;
    for (int i = tid; i < 6400; i += 256) {
        int c = i & 63, sp = i >> 6;
        int py = sp / 10, px = sp % 10;
        int yy = y0 + py - 1, xx = x0 + px - 1;
        float v = 0.f;
        if (yy >= 0 && yy < 64 && xx >= 0 && xx < 64)
            v = h[(((ll)b*N_) + (yy*64 + xx)) * HID_ + ch0 + c];
        patch[py][px][c] = v;
    }
    __syncthreads();
    int c = tid & 63, sub = tid >> 6;
    float w[9];
    #pragma unroll
    for (int i = 0; i < 9; i++) w[i] = dww[(ch0 + c)*9 + i];
    float bv = dwb[ch0 + c];
    for (int oy = sub; oy < 8; oy += 4) {
        #pragma unroll
        for (int ox = 0; ox < 8; ox++) {
            float a = bv;
            #pragma unroll
            for (int dy = 0; dy < 3; dy++)
                #pragma unroll
                for (int dx = 0; dx < 3; dx++)
                    a += patch[oy+dy][ox+dx][c] * w[dy*3+dx];
            float g = 0.5f * a * (1.0f + erff(a * 0.7071067811865475f));
            split_store(g, oh, ol, (((ll)b*N_) + ((y0+oy)*64 + x0+ox)) * HID_ + ch0 + c);
        }
    }
}

/* ---------------- residual + LayerNorm (optional bf16 dual-write) ---------- */
__global__ void add_ln_kernel(const float* __restrict__ res, const float* __restrict__ val,
                              const float* __restrict__ nw, const float* __restrict__ nb,
                              float* __restrict__ dst,
                              bf16* __restrict__ dh, bf16* __restrict__ dl) {
    ll row = blockIdx.x;
    int c = threadIdx.x;
    __shared__ float sh[8];
    float v = val[row * C_ + c];
    float m = blockSum256(v, sh) * (1.0f / C_);
    float d = v - m;
    float var = blockSum256(d*d, sh) * (1.0f / C_);
    float r = res[row * C_ + c] + d * rsqrtf(var + 1e-5f) * nw[c] + nb[c];
    dst[row * C_ + c] = r;
    if (dh) split_store(r, dh, dl, row * C_ + c);
}

/* ---------------- host launch --------------------------------------------- */
static float* symaddr(const void* sym) {
    void* p = nullptr;
    cudaGetSymbolAddress(&p, sym);
    return (float*)p;
}
static bf16* symaddrb(const void* sym) {
    void* p = nullptr;
    cudaGetSymbolAddress(&p, sym);
    return (bf16*)p;
}

extern "C" void kernel_launch(void* const* d_in, const int* in_sizes, int n_in,
                              void* d_out, int out_size) {
    const float* x    = (const float*)d_in[0];
    const float* z    = (const float*)d_in[1];
    const float* mem  = (const float*)d_in[2];
    const float* cw   = (const float*)d_in[3];
    const float* p1   = (const float*)d_in[4];
    const float* t1   = (const float*)d_in[5];
    const float* p2   = (const float*)d_in[6];
    const float* t2   = (const float*)d_in[7];
    const float* sal  = (const float*)d_in[8];
    const float* sbe  = (const float*)d_in[9];
    const float* qw   = (const float*)d_in[10];
    const float* qb   = (const float*)d_in[11];
    const float* kw   = (const float*)d_in[12];
    const float* kb   = (const float*)d_in[13];
    const float* vw   = (const float*)d_in[14];
    const float* vb   = (const float*)d_in[15];
    const float* pw   = (const float*)d_in[16];
    const float* pb   = (const float*)d_in[17];
    const float* nw   = (const float*)d_in[18];
    const float* nb   = (const float*)d_in[19];
    const float* f1w  = (const float*)d_in[20];
    const float* f1b  = (const float*)d_in[21];
    const float* dww  = (const float*)d_in[22];
    const float* dwb  = (const float*)d_in[23];
    const float* f2w  = (const float*)d_in[24];
    const float* f2b  = (const float*)d_in[25];

    float* out_main = (float*)d_out;
    float* out_cxz  = out_main + (ll)B_*N_*C_;
    float* out_asn  = out_cxz  + (ll)B_*NC_*R_;

    float* clt  = symaddr(g_clt);
    float* cen  = symaddr(g_cen);
    float* cin  = symaddr(g_cin);
    float* Pf   = symaddr(g_P);
    float* tmp  = symaddr(g_tmp);
    float* out1 = symaddr(g_out1);
    float* h1   = symaddr(g_h1);

    bf16 *xf_h = symaddrb(g_xf_h), *xf_l = symaddrb(g_xf_l);
    bf16 *xT_h = symaddrb(g_xfT_h),*xT_l = symaddrb(g_xfT_l);
    bf16 *S_h  = symaddrb(g_S_h),  *S_l  = symaddrb(g_S_l);
    bf16 *tc_h = symaddrb(g_tc_h), *tc_l = symaddrb(g_tc_l);
    bf16 *sf_h = symaddrb(g_sf_h), *sf_l = symaddrb(g_sf_l);
    bf16 *x_h  = symaddrb(g_x_h),  *x_l  = symaddrb(g_x_l);
    bf16 *q_h  = symaddrb(g_q_h),  *q_l  = symaddrb(g_q_l);
    bf16 *k_h  = symaddrb(g_k_h),  *k_l  = symaddrb(g_k_l);
    bf16 *vt_h = symaddrb(g_vt_h), *vt_l = symaddrb(g_vt_l);
    bf16 *P_h  = symaddrb(g_P_h),  *P_l  = symaddrb(g_P_l);
    bf16 *at_h = symaddrb(g_atn_h),*at_l = symaddrb(g_atn_l);
    bf16 *o1_h = symaddrb(g_o1_h), *o1_l = symaddrb(g_o1_l);
    bf16 *hg_h = symaddrb(g_hg_h), *hg_l = symaddrb(g_hg_l);
    bf16 *cw_h = symaddrb(g_cw_h), *cw_l = symaddrb(g_cw_l);
    bf16 *qw_h = symaddrb(g_qw_h), *qw_l = symaddrb(g_qw_l);
    bf16 *pw_h = symaddrb(g_pw_h), *pw_l = symaddrb(g_pw_l);
    bf16 *f1_h = symaddrb(g_f1_h), *f1_l = symaddrb(g_f1_l);
    bf16 *f2_h = symaddrb(g_f2_h), *f2_l = symaddrb(g_f2_l);

    /* 0. fused weight + x conversions, tcat */
    {
        CvtJob j0 = {(const float4*)cw,  cw_h, cw_l, NC_*C_/4};
        CvtJob j1 = {(const float4*)qw,  qw_h, qw_l, C_*C_/4};
        CvtJob j2 = {(const float4*)pw,  pw_h, pw_l, C_*C_/4};
        CvtJob j3 = {(const float4*)f1w, f1_h, f1_l, HID_*C_/4};
        CvtJob j4 = {(const float4*)f2w, f2_h, f2_l, HID_*C_/4};
        CvtJob j5 = {(const float4*)x,   x_h,  x_l,  B_*N_*C_/4};
        int mx = HID_*C_/4;
        if (B_*N_*C_/4 > mx) mx = B_*N_*C_/4;
        cvt_multi<<<dim3((mx + 255)/256, 6), 256>>>(j0, j1, j2, j3, j4, j5);
    }
    build_tcat<<<(NC_*KS_ + 255)/256, 256>>>(t1, t2, tc_h, tc_l);

    /* 1. xf: row-major + transposed bf16 */
    build_xf_all<<<dim3(N_/64, C_/32, B_*T_), 256>>>(x, mem, xf_h, xf_l, xT_h, xT_l);

    /* 2. clt (MMA, r-major store) */
    gemm_mma2<<<dim3(R_/128, 3, B_), 256>>>(
        R_, NC_, C_, xf_h, xf_l, C_, (ll)R_*C_, cw_h, cw_l, C_, 0,
        clt, CLTS, 1, (ll)R_*CLTS, nullptr, nullptr, nullptr, 1.0f, 1);

    /* 3. fused cosine scales + S build */
    build_S2<<<dim3(R_/64, B_), 256>>>(z, clt, p1, p2, S_h, S_l);

    /* 4. cluster_x_z (MMA, transposed store) */
    gemm_mma2<<<dim3(R_/128, 3, B_), 256>>>(
        R_, NC_, KS_, S_h, S_l, KS_, (ll)R_*KS_, tc_h, tc_l, KS_, 0,
        out_cxz, 1, R_, (ll)NC_*R_, nullptr, nullptr, nullptr, 0.5f, 1);

    /* 5. softmax: asn copy + soft bf16 */
    softmax_rows2<<<B_*T_*NC_, 256>>>(out_cxz, out_asn, sf_h, sf_l);

    /* 6. cen = soft @ xf (MMA, split-K=8) */
    zero_kernel<<<(B_*T_*NC_*C_ + 255)/256, 256>>>(cen, B_*T_*NC_*C_);
    gemm_mma2<<<dim3(2, 4, B_*T_*8), 256>>>(
        NC_, C_, N_, sf_h, sf_l, N_, (ll)NC_*N_, xT_h, xT_l, N_, (ll)C_*N_,
        cen, C_, 1, (ll)NC_*C_, nullptr, nullptr, nullptr, 1.0f, 8);

    /* 7. gate + LN */
    gate_ln_kernel<<<dim3(NC_, B_), 256>>>(cen, nw, nb, sal, sbe, cin);

    /* 8. k,v -> bf16 */
    zero_bf2<<<(B_*8*32*PL_ + 255)/256, 256>>>(vt_h, vt_l, B_*8*32*PL_);
    kv_kernel<<<B_*NC_, 256>>>(cin, kw, kb, vw, vb, k_h, k_l, vt_h, vt_l);

    /* 9. q (MMA, bf16 dual-write only) */
    gemm_mma2<<<dim3(64, 4, 1), 256>>>(
        B_*N_, C_, C_, x_h, x_l, C_, 0, qw_h, qw_l, C_, 0,
        nullptr, C_, 1, 0, q_h, q_l, qb, 0.17677669529663687f, 1);

    /* 10a. QK logits (batched over h) */
    for (int b = 0; b < B_; b++) {
        gemm_mma2<<<dim3(N_/128, 3, 8), 256>>>(
            N_, NC_, 32,
            q_h + (ll)b*N_*C_, q_l + (ll)b*N_*C_, C_, 32,
            k_h + (ll)b*NC_*C_, k_l + (ll)b*NC_*C_, C_, 32,
            Pf + (ll)b*8*N_*PL_, PL_, 1, (ll)N_*PL_,
            nullptr, nullptr, nullptr, 1.0f, 1);
    }

    /* 10b. P softmax */
    p_softmax<<<B_*8*N_/8, 256>>>(Pf, P_h, P_l);

    /* 10c. PV (batched over h) */
    for (int b = 0; b < B_; b++) {
        gemm_mma2<<<dim3(N_/128, 1, 8), 256>>>(
            N_, 32, PL_,
            P_h + (ll)b*8*N_*PL_, P_l + (ll)b*8*N_*PL_, PL_, (ll)N_*PL_,
            vt_h + (ll)b*8*32*PL_, vt_l + (ll)b*8*32*PL_, PL_, (ll)32*PL_,
            nullptr, C_, 1, 32,
            at_h + (ll)b*N_*C_, at_l + (ll)b*N_*C_, nullptr, 1.0f, 1);
    }

    /* 11. proj (MMA) */
    gemm_mma2<<<dim3(64, 4, 1), 256>>>(
        B_*N_, C_, C_, at_h, at_l, C_, 0, pw_h, pw_l, C_, 0,
        tmp, C_, 1, 0, nullptr, nullptr, pb, 1.0f, 1);

    /* 12. out1 = x + LN(proj), dual-write */
    add_ln_kernel<<<B_*N_, 256>>>(x, tmp, nw, nb, out1, o1_h, o1_l);

    /* 13. fc1 (MMA) */
    gemm_mma2<<<dim3(64, 16, 1), 256>>>(
        B_*N_, HID_, C_, o1_h, o1_l, C_, 0, f1_h, f1_l, C_, 0,
        h1, HID_, 1, 0, nullptr, nullptr, f1b, 1.0f, 1);

    /* 14. depthwise conv + GELU -> bf16 */
    conv_gelu2<<<dim3(HID_/64, 64, B_), 256>>>(h1, dww, dwb, hg_h, hg_l);

    /* 15. fc2 (MMA, K=1024) */
    gemm_mma2<<<dim3(64, 4, 1), 256>>>(
        B_*N_, C_, HID_, hg_h, hg_l, HID_, 0, f2_h, f2_l, HID_, 0,
        tmp, C_, 1, 0, nullptr, nullptr, f2b, 1.0f, 1);

    /* 16. out = out1 + LN(fc2) */
    add_ln_kernel<<<B_*N_, 256>>>(out1, tmp, nw, nb, out_main, nullptr, nullptr);
}